// round 1
// baseline (speedup 1.0000x reference)
#include <cuda_runtime.h>

// ---------------------------------------------------------------------------
// Problem constants (from reference)
// ---------------------------------------------------------------------------
#define KNB 10          // neighbors per node
#define BB  2048        // batch
#define N1  20480       // B*K  (hop-1 query rows)
#define NP1 204800      // B*K*K (hop-1 neighbor pairs)
#define NP2 20480       // B*K  (hop-2 neighbor pairs)
// D = T = 128, QD = 256, KD = 384, H = 2, hd = 128, L = 2

// ---------------------------------------------------------------------------
// Scratch (device globals — no allocation allowed in kernel_launch)
// ---------------------------------------------------------------------------
__device__ float g_st[128];                          // cos(time_b) (zero-dt encoding)
__device__ float g_et1[(size_t)NP1 * 128];           // hop-1 edge time encodings
__device__ float g_et2[(size_t)NP2 * 128];           // hop-2 edge time encodings
__device__ float g_kv1[(size_t)NP1 * 512];           // hop-1 K||V
__device__ float g_q1 [(size_t)N1  * 256];
__device__ float g_attn1[(size_t)N1 * 256];
__device__ float g_o1 [(size_t)N1  * 256];
__device__ float g_h1 [(size_t)N1  * 128];
__device__ float g_emb1[(size_t)N1 * 128];
__device__ unsigned char g_inv1[N1];
__device__ float g_kv2[(size_t)NP2 * 512];
__device__ float g_q2 [(size_t)BB  * 256];
__device__ float g_attn2[(size_t)BB * 256];
__device__ float g_o2 [(size_t)BB  * 256];
__device__ float g_h2 [(size_t)BB  * 128];
__device__ unsigned char g_inv2[BB];

// ---------------------------------------------------------------------------
// Generic GEMM with fused virtual-A loaders.  C[m,n] = sum_j A[m,j]*W[n,j] + b[n]
// W is row-major [N, K] (i.e. computes A @ W^T, matching jax `x @ W.T`).
// Columns n >= Nsplit come from (W2, b2) — used to fuse K and V projections.
// ---------------------------------------------------------------------------
struct GemmParams {
    int M, N, K, Nsplit;
    const float *W1, *b1, *W2, *b2;
    float* C;
    int relu;
    const unsigned char* invalid;   // if set: zero whole row m where invalid[m]
    const float *Adense, *nf, *memv, *ef, *et, *st;
    const int *idx, *eidx;
};

#define MODE_PLAIN      0
#define MODE_QGATHER    1
#define MODE_KIN_GATHER 2
#define MODE_KIN_DENSE  3
#define MODE_CONCAT     4

template <int MODE>
__device__ __forceinline__ float loadA(const GemmParams& p, int m, int j) {
    if constexpr (MODE == MODE_PLAIN) {
        return p.Adense[(size_t)m * p.K + j];
    } else if constexpr (MODE == MODE_QGATHER) {
        // [ base(idx[m]) || cos(time_b) ]
        if (j < 128) {
            int nd = __ldg(&p.idx[m]);
            return p.nf[(size_t)nd * 128 + j] + p.memv[(size_t)nd * 128 + j];
        }
        return p.st[j - 128];
    } else if constexpr (MODE == MODE_KIN_GATHER) {
        // [ base(nbr) || edge_feat || edge_time_enc ]
        if (j < 128) {
            int nd = __ldg(&p.idx[m]);
            return p.nf[(size_t)nd * 128 + j] + p.memv[(size_t)nd * 128 + j];
        }
        if (j < 256) {
            int e = __ldg(&p.eidx[m]);
            return p.ef[(size_t)e * 128 + (j - 128)];
        }
        return p.et[(size_t)m * 128 + (j - 256)];
    } else if constexpr (MODE == MODE_KIN_DENSE) {
        // [ emb1 (dense) || edge_feat || edge_time_enc ]
        if (j < 128) return p.Adense[(size_t)m * 128 + j];
        if (j < 256) {
            int e = __ldg(&p.eidx[m]);
            return p.ef[(size_t)e * 128 + (j - 128)];
        }
        return p.et[(size_t)m * 128 + (j - 256)];
    } else {
        // MODE_CONCAT: [ attn_out (dense, 256) || base(idx[m]) ]
        if (j < 256) return p.Adense[(size_t)m * 256 + j];
        int nd = __ldg(&p.idx[m]);
        return p.nf[(size_t)nd * 128 + (j - 256)] + p.memv[(size_t)nd * 128 + (j - 256)];
    }
}

// 128x128 block, 8x8 per-thread micro-tile, BK=8. All M,N multiples of 128; K of 8.
template <int MODE>
__global__ void __launch_bounds__(256) gemm_kernel(GemmParams p) {
    __shared__ __align__(16) float As[8][132];
    __shared__ __align__(16) float Bs[8][132];
    const int bm = blockIdx.y * 128;
    const int bn = blockIdx.x * 128;
    const int tid = threadIdx.x;
    const int tx = tid & 15;
    const int ty = tid >> 4;

    float acc[8][8];
#pragma unroll
    for (int i = 0; i < 8; i++)
#pragma unroll
        for (int j = 0; j < 8; j++) acc[i][j] = 0.f;

    for (int k0 = 0; k0 < p.K; k0 += 8) {
#pragma unroll
        for (int i = 0; i < 4; i++) {
            int l = tid * 4 + i;            // 1024 elements, 4 consecutive per thread
            int row = l >> 3;
            int kk = l & 7;
            As[kk][row] = loadA<MODE>(p, bm + row, k0 + kk);
            int c = bn + row;
            const float* W = (c < p.Nsplit) ? p.W1 : p.W2;
            int cr = (c < p.Nsplit) ? c : (c - p.Nsplit);
            Bs[kk][row] = W[(size_t)cr * p.K + k0 + kk];
        }
        __syncthreads();
#pragma unroll
        for (int kk = 0; kk < 8; kk++) {
            float a[8], b[8];
            *(float4*)&a[0] = *(const float4*)&As[kk][ty * 4];
            *(float4*)&a[4] = *(const float4*)&As[kk][64 + ty * 4];
            *(float4*)&b[0] = *(const float4*)&Bs[kk][tx * 4];
            *(float4*)&b[4] = *(const float4*)&Bs[kk][64 + tx * 4];
#pragma unroll
            for (int i = 0; i < 8; i++)
#pragma unroll
                for (int j = 0; j < 8; j++)
                    acc[i][j] = fmaf(a[i], b[j], acc[i][j]);
        }
        __syncthreads();
    }

#pragma unroll
    for (int i = 0; i < 8; i++) {
        int m = bm + ((i < 4) ? (ty * 4 + i) : (64 + ty * 4 + i - 4));
        bool zero = (p.invalid != nullptr) && p.invalid[m];
#pragma unroll
        for (int j = 0; j < 8; j++) {
            int n = bn + ((j < 4) ? (tx * 4 + j) : (64 + tx * 4 + j - 4));
            float bias = (n < p.Nsplit) ? p.b1[n] : p.b2[n - p.Nsplit];
            float v = acc[i][j] + bias;
            if (p.relu) v = fmaxf(v, 0.f);
            if (zero) v = 0.f;
            p.C[(size_t)m * p.N + n] = v;
        }
    }
}

// ---------------------------------------------------------------------------
// Time encoding: out[m, j] = cos((ts[m/DIV] - etm[m]) * w[j] + b[j])
// ---------------------------------------------------------------------------
template <int DIV>
__global__ void et_kernel(const float* __restrict__ ts, const float* __restrict__ etm,
                          const float* __restrict__ w, const float* __restrict__ b,
                          float* __restrict__ outp, int npairs) {
    int idx = blockIdx.x * blockDim.x + threadIdx.x;
    if (idx >= npairs * 128) return;
    int m = idx >> 7;
    int j = idx & 127;
    float dt = ts[m / DIV] - etm[m];
    outp[idx] = __cosf(fmaf(dt, w[j], b[j]));
}

__global__ void st_kernel(const float* __restrict__ b) {
    g_st[threadIdx.x] = __cosf(b[threadIdx.x]);
}

// ---------------------------------------------------------------------------
// Per-row temporal attention.  q: [R,256], kv: [R*10, 512] (K||V per pair).
// H=2 heads of dim 128.  mask: nbrs==0; all-masked rows un-mask slot K-1 and
// get flagged invalid (output zeroed later in the Wo GEMM epilogue).
// 320 threads: warps 0..9 compute both head scores for neighbor k=warp.
// ---------------------------------------------------------------------------
__global__ void attn_kernel(const float* __restrict__ q, const float* __restrict__ kv,
                            const int* __restrict__ nbrs, float* __restrict__ outp,
                            unsigned char* __restrict__ invalid) {
    const int r = blockIdx.x;
    const int tid = threadIdx.x;
    const int warp = tid >> 5;
    const int lane = tid & 31;
    __shared__ float sq[256];
    __shared__ float sc[2][KNB];
    __shared__ float swt[2][KNB];
    __shared__ int smask[KNB];

    if (tid < 256) sq[tid] = q[(size_t)r * 256 + tid];
    if (tid < KNB) smask[tid] = (nbrs[r * KNB + tid] != 0) ? 1 : 0;
    __syncthreads();
    if (tid == 0) {
        int any = 0;
#pragma unroll
        for (int k = 0; k < KNB; k++) any |= smask[k];
        if (!any) smask[KNB - 1] = 1;
        invalid[r] = (unsigned char)(!any);
    }
    __syncthreads();

    if (warp < KNB) {
        const float* kp = kv + ((size_t)r * KNB + warp) * 512;
        float s0 = 0.f, s1 = 0.f;
#pragma unroll
        for (int i = 0; i < 4; i++) {
            int d = lane + 32 * i;
            s0 = fmaf(sq[d], kp[d], s0);
            s1 = fmaf(sq[128 + d], kp[128 + d], s1);
        }
#pragma unroll
        for (int o = 16; o > 0; o >>= 1) {
            s0 += __shfl_down_sync(0xffffffffu, s0, o);
            s1 += __shfl_down_sync(0xffffffffu, s1, o);
        }
        if (lane == 0) {
            const float scale = 0.08838834764831845f;  // 1/sqrt(128)
            sc[0][warp] = smask[warp] ? s0 * scale : -1e9f;
            sc[1][warp] = smask[warp] ? s1 * scale : -1e9f;
        }
    }
    __syncthreads();

    if (tid < 2) {
        float mx = -3.0e38f;
#pragma unroll
        for (int k = 0; k < KNB; k++) mx = fmaxf(mx, sc[tid][k]);
        float sum = 0.f;
#pragma unroll
        for (int k = 0; k < KNB; k++) {
            float e = __expf(sc[tid][k] - mx);
            swt[tid][k] = e;
            sum += e;
        }
        float inv = 1.0f / sum;
#pragma unroll
        for (int k = 0; k < KNB; k++) swt[tid][k] *= inv;
    }
    __syncthreads();

    if (tid < 256) {
        int h = tid >> 7;
        float o = 0.f;
#pragma unroll
        for (int k = 0; k < KNB; k++)
            o = fmaf(swt[h][k], kv[((size_t)r * KNB + k) * 512 + 256 + tid], o);
        outp[(size_t)r * 256 + tid] = o;
    }
}

// ---------------------------------------------------------------------------
// Host side
// ---------------------------------------------------------------------------
static void launch_gemm(int mode, const GemmParams& p) {
    dim3 grid(p.N / 128, p.M / 128);
    switch (mode) {
        case MODE_PLAIN:      gemm_kernel<MODE_PLAIN><<<grid, 256>>>(p); break;
        case MODE_QGATHER:    gemm_kernel<MODE_QGATHER><<<grid, 256>>>(p); break;
        case MODE_KIN_GATHER: gemm_kernel<MODE_KIN_GATHER><<<grid, 256>>>(p); break;
        case MODE_KIN_DENSE:  gemm_kernel<MODE_KIN_DENSE><<<grid, 256>>>(p); break;
        case MODE_CONCAT:     gemm_kernel<MODE_CONCAT><<<grid, 256>>>(p); break;
    }
}

extern "C" void kernel_launch(void* const* d_in, const int* in_sizes, int n_in,
                              void* d_out, int out_size) {
    const float* nf   = (const float*)d_in[0];   // node_features [200000,128]
    const float* mem  = (const float*)d_in[1];   // memory        [200000,128]
    const float* ef   = (const float*)d_in[2];   // edge_features [500000,128]
    const float* tw   = (const float*)d_in[3];   // time_w [128]
    const float* tb   = (const float*)d_in[4];   // time_b [128]
    const float* Wq   = (const float*)d_in[5];   // [2,256,256]
    const float* bq   = (const float*)d_in[6];   // [2,256]
    const float* Wk   = (const float*)d_in[7];   // [2,256,384]
    const float* bk   = (const float*)d_in[8];   // [2,256]
    const float* Wv   = (const float*)d_in[9];   // [2,256,384]
    const float* bv   = (const float*)d_in[10];  // [2,256]
    const float* Wo   = (const float*)d_in[11];  // [2,256,256]
    const float* bo   = (const float*)d_in[12];  // [2,256]
    const float* f1w  = (const float*)d_in[13];  // [2,128,384]
    const float* f1b  = (const float*)d_in[14];  // [2,128]
    const float* f2w  = (const float*)d_in[15];  // [2,128,128]
    const float* f2b  = (const float*)d_in[16];  // [2,128]
    const int*   src  = (const int*)d_in[17];    // source_nodes [2048]
    const float* ts   = (const float*)d_in[18];  // timestamps [2048]
    const int*   nb2  = (const int*)d_in[19];    // neighbors_l2 [2048,10]
    const int*   ei2  = (const int*)d_in[20];    // edge_idxs_l2 [2048,10]
    const float* tm2  = (const float*)d_in[21];  // edge_times_l2 [2048,10]
    const int*   nb1  = (const int*)d_in[22];    // neighbors_l1 [20480,10]
    const int*   ei1  = (const int*)d_in[23];    // edge_idxs_l1 [20480,10]
    const float* tm1  = (const float*)d_in[24];  // edge_times_l1 [20480,10]
    float* out = (float*)d_out;

    float *pst, *pet1, *pet2, *pkv1, *pq1, *pattn1, *po1, *ph1, *pemb1;
    float *pkv2, *pq2, *pattn2, *po2, *ph2;
    unsigned char *pinv1, *pinv2;
    cudaGetSymbolAddress((void**)&pst, g_st);
    cudaGetSymbolAddress((void**)&pet1, g_et1);
    cudaGetSymbolAddress((void**)&pet2, g_et2);
    cudaGetSymbolAddress((void**)&pkv1, g_kv1);
    cudaGetSymbolAddress((void**)&pq1, g_q1);
    cudaGetSymbolAddress((void**)&pattn1, g_attn1);
    cudaGetSymbolAddress((void**)&po1, g_o1);
    cudaGetSymbolAddress((void**)&ph1, g_h1);
    cudaGetSymbolAddress((void**)&pemb1, g_emb1);
    cudaGetSymbolAddress((void**)&pinv1, g_inv1);
    cudaGetSymbolAddress((void**)&pkv2, g_kv2);
    cudaGetSymbolAddress((void**)&pq2, g_q2);
    cudaGetSymbolAddress((void**)&pattn2, g_attn2);
    cudaGetSymbolAddress((void**)&po2, g_o2);
    cudaGetSymbolAddress((void**)&ph2, g_h2);
    cudaGetSymbolAddress((void**)&pinv2, g_inv2);

    const int BIG = 1 << 30;

    // --- time encodings ---
    st_kernel<<<1, 128>>>(tb);
    et_kernel<100><<<(NP1 * 128 + 255) / 256, 256>>>(ts, tm1, tw, tb, pet1, NP1);
    et_kernel<10><<<(NP2 * 128 + 255) / 256, 256>>>(ts, tm2, tw, tb, pet2, NP2);

    // ============================== LAYER 0 (hop-1) ==============================
    {
        GemmParams p{};  // Q1: [20480,256] = [base(nbr2)||st] @ Wq0^T
        p.M = N1; p.N = 256; p.K = 256; p.Nsplit = BIG;
        p.W1 = Wq; p.b1 = bq; p.C = pq1;
        p.nf = nf; p.memv = mem; p.st = pst; p.idx = nb2;
        launch_gemm(MODE_QGATHER, p);
    }
    {
        GemmParams p{};  // KV1: [204800,512] = k_in @ [Wk0||Wv0]^T (k_in gathered on the fly)
        p.M = NP1; p.N = 512; p.K = 384; p.Nsplit = 256;
        p.W1 = Wk; p.b1 = bk; p.W2 = Wv; p.b2 = bv; p.C = pkv1;
        p.nf = nf; p.memv = mem; p.ef = ef; p.et = pet1; p.idx = nb1; p.eidx = ei1;
        launch_gemm(MODE_KIN_GATHER, p);
    }
    attn_kernel<<<N1, 320>>>(pq1, pkv1, nb1, pattn1, pinv1);
    {
        GemmParams p{};  // O1: attn @ Wo0^T (+ zero invalid rows)
        p.M = N1; p.N = 256; p.K = 256; p.Nsplit = BIG;
        p.W1 = Wo; p.b1 = bo; p.C = po1; p.Adense = pattn1; p.invalid = pinv1;
        launch_gemm(MODE_PLAIN, p);
    }
    {
        GemmParams p{};  // fc1: relu([o1 || base(nbr2)] @ f1w0^T)
        p.M = N1; p.N = 128; p.K = 384; p.Nsplit = BIG;
        p.W1 = f1w; p.b1 = f1b; p.C = ph1; p.Adense = po1;
        p.nf = nf; p.memv = mem; p.idx = nb2; p.relu = 1;
        launch_gemm(MODE_CONCAT, p);
    }
    {
        GemmParams p{};  // fc2 -> emb1
        p.M = N1; p.N = 128; p.K = 128; p.Nsplit = BIG;
        p.W1 = f2w; p.b1 = f2b; p.C = pemb1; p.Adense = ph1;
        launch_gemm(MODE_PLAIN, p);
    }

    // ============================== LAYER 1 (top) ==============================
    const float* Wq1 = Wq + 256 * 256;  const float* bq1 = bq + 256;
    const float* Wk1 = Wk + 256 * 384;  const float* bk1 = bk + 256;
    const float* Wv1 = Wv + 256 * 384;  const float* bv1 = bv + 256;
    const float* Wo1 = Wo + 256 * 256;  const float* bo1 = bo + 256;
    const float* f1w1 = f1w + 128 * 384; const float* f1b1 = f1b + 128;
    const float* f2w1 = f2w + 128 * 128; const float* f2b1 = f2b + 128;

    {
        GemmParams p{};  // Q2: [2048,256] = [base(src)||st] @ Wq1^T
        p.M = BB; p.N = 256; p.K = 256; p.Nsplit = BIG;
        p.W1 = Wq1; p.b1 = bq1; p.C = pq2;
        p.nf = nf; p.memv = mem; p.st = pst; p.idx = src;
        launch_gemm(MODE_QGATHER, p);
    }
    {
        GemmParams p{};  // KV2: [20480,512], k_in first 128 cols = emb1 (dense)
        p.M = NP2; p.N = 512; p.K = 384; p.Nsplit = 256;
        p.W1 = Wk1; p.b1 = bk1; p.W2 = Wv1; p.b2 = bv1; p.C = pkv2;
        p.Adense = pemb1; p.ef = ef; p.et = pet2; p.eidx = ei2;
        launch_gemm(MODE_KIN_DENSE, p);
    }
    attn_kernel<<<BB, 320>>>(pq2, pkv2, nb2, pattn2, pinv2);
    {
        GemmParams p{};  // O2
        p.M = BB; p.N = 256; p.K = 256; p.Nsplit = BIG;
        p.W1 = Wo1; p.b1 = bo1; p.C = po2; p.Adense = pattn2; p.invalid = pinv2;
        launch_gemm(MODE_PLAIN, p);
    }
    {
        GemmParams p{};  // fc1
        p.M = BB; p.N = 128; p.K = 384; p.Nsplit = BIG;
        p.W1 = f1w1; p.b1 = f1b1; p.C = ph2; p.Adense = po2;
        p.nf = nf; p.memv = mem; p.idx = src; p.relu = 1;
        launch_gemm(MODE_CONCAT, p);
    }
    {
        GemmParams p{};  // fc2 -> final output [2048,128]
        p.M = BB; p.N = 128; p.K = 128; p.Nsplit = BIG;
        p.W1 = f2w1; p.b1 = f2b1; p.C = out; p.Adense = ph2;
        launch_gemm(MODE_PLAIN, p);
    }
}

// round 3
// speedup vs baseline: 2.4479x; 2.4479x over previous
#include <cuda_runtime.h>
#include <cstdint>

// ---------------------------------------------------------------------------
// Problem constants
// ---------------------------------------------------------------------------
#define KNB 10
#define BB  2048
#define N1  20480
#define NP1 204800
#define NP2 20480
// D = T = 128, QD = 256, KD = 384, H = 2, hd = 128

// ---------------------------------------------------------------------------
// Scratch
// ---------------------------------------------------------------------------
__device__ float g_st[128];
__device__ float g_et1[(size_t)NP1 * 128];
__device__ float g_et2[(size_t)NP2 * 128];
__device__ float g_kv1[(size_t)NP1 * 512];
__device__ float g_q1 [(size_t)N1  * 256];
__device__ float g_attn1[(size_t)N1 * 256];
__device__ float g_o1 [(size_t)N1  * 256];
__device__ float g_h1 [(size_t)N1  * 128];
__device__ float g_emb1[(size_t)N1 * 128];
__device__ unsigned char g_inv1[N1];
__device__ float g_kv2[(size_t)NP2 * 512];
__device__ float g_q2 [(size_t)BB  * 256];
__device__ float g_attn2[(size_t)BB * 256];
__device__ float g_o2 [(size_t)BB  * 256];
__device__ float g_h2 [(size_t)BB  * 128];
__device__ unsigned char g_inv2[BB];

#define MODE_PLAIN      0
#define MODE_QGATHER    1
#define MODE_KIN_GATHER 2
#define MODE_KIN_DENSE  3
#define MODE_CONCAT     4

// ---------------------------------------------------------------------------
// tf32 helpers
// ---------------------------------------------------------------------------
__device__ __forceinline__ uint32_t f2tf32(float f) {
    uint32_t r;
    asm("cvt.rna.tf32.f32 %0, %1;" : "=r"(r) : "f"(f));
    return r;
}
__device__ __forceinline__ uint4 f4tf32(float4 v) {
    uint4 r;
    r.x = f2tf32(v.x); r.y = f2tf32(v.y); r.z = f2tf32(v.z); r.w = f2tf32(v.w);
    return r;
}
__device__ __forceinline__ void mma_tf32(float* c, const uint32_t* a, uint32_t b0, uint32_t b1) {
    asm volatile(
        "mma.sync.aligned.m16n8k8.row.col.f32.tf32.tf32.f32 "
        "{%0,%1,%2,%3}, {%4,%5,%6,%7}, {%8,%9}, {%0,%1,%2,%3};"
        : "+f"(c[0]), "+f"(c[1]), "+f"(c[2]), "+f"(c[3])
        : "r"(a[0]), "r"(a[1]), "r"(a[2]), "r"(a[3]), "r"(b0), "r"(b1));
}

// ===========================================================================
// tf32 mma.sync GEMM: C[m, noff+n] = sum_j A[m,j] * W[n,j] + bias[n]
// CTA computes a 128(m) x 128(n) tile; W points at the 128-row weight slice.
// 8 warps: warp (wid>>1) -> 32-row group, (wid&1) -> 64-col group.
// K staged in BK=32 chunks; A loaded via MODE-specific fused gather.
// ===========================================================================
struct TcParams {
    int Kdim, ldA, ldC, noff;
    const float* W;        // [128, Kdim] slice
    const float* bias;     // [128]
    float* C;
    int relu;
    const unsigned char* invalid;
    const float *Adense, *nf, *memv, *ef, *et, *st;
    const int *idx, *eidx;
};

template <int MODE>
__global__ void __launch_bounds__(256) mma_gemm(TcParams p) {
    __shared__ uint32_t As[128][36];
    __shared__ uint32_t Bs[128][36];
    const int tid = threadIdx.x;
    const int lane = tid & 31;
    const int wid = tid >> 5;
    const int bm = blockIdx.x * 128;
    const int row = tid >> 1;         // staging row (0..127)
    const int seg = tid & 1;          // staging 16-float half
    const int m = bm + row;
    const int wr = (wid >> 1) * 32;   // warp row base
    const int wc = (wid & 1) * 64;    // warp col base
    const int groupID = lane >> 2;
    const int tg = lane & 3;

    float acc[2][8][4];
#pragma unroll
    for (int mi = 0; mi < 2; mi++)
#pragma unroll
        for (int nj = 0; nj < 8; nj++)
#pragma unroll
            for (int q = 0; q < 4; q++) acc[mi][nj][q] = 0.f;

#pragma unroll 1
    for (int k0 = 0; k0 < p.Kdim; k0 += 32) {
        const int kb = k0 + seg * 16;
        // ---- stage A (128 x 32), MODE-specific source ----
        {
            const float* s0 = nullptr;
            const float* s1 = nullptr;
            if constexpr (MODE == MODE_PLAIN) {
                s0 = p.Adense + (size_t)m * p.ldA + kb;
            } else if constexpr (MODE == MODE_QGATHER) {
                if (kb < 128) {
                    int nd = __ldg(&p.idx[m]);
                    s0 = p.nf + (size_t)nd * 128 + kb;
                    s1 = p.memv + (size_t)nd * 128 + kb;
                } else {
                    s0 = p.st + (kb - 128);
                }
            } else if constexpr (MODE == MODE_KIN_GATHER) {
                if (kb < 128) {
                    int nd = __ldg(&p.idx[m]);
                    s0 = p.nf + (size_t)nd * 128 + kb;
                    s1 = p.memv + (size_t)nd * 128 + kb;
                } else if (kb < 256) {
                    int e = __ldg(&p.eidx[m]);
                    s0 = p.ef + (size_t)e * 128 + (kb - 128);
                } else {
                    s0 = p.et + (size_t)m * 128 + (kb - 256);
                }
            } else if constexpr (MODE == MODE_KIN_DENSE) {
                if (kb < 128) {
                    s0 = p.Adense + (size_t)m * 128 + kb;
                } else if (kb < 256) {
                    int e = __ldg(&p.eidx[m]);
                    s0 = p.ef + (size_t)e * 128 + (kb - 128);
                } else {
                    s0 = p.et + (size_t)m * 128 + (kb - 256);
                }
            } else {  // MODE_CONCAT
                if (kb < 256) {
                    s0 = p.Adense + (size_t)m * 256 + kb;
                } else {
                    int nd = __ldg(&p.idx[m]);
                    s0 = p.nf + (size_t)nd * 128 + (kb - 256);
                    s1 = p.memv + (size_t)nd * 128 + (kb - 256);
                }
            }
#pragma unroll
            for (int i = 0; i < 4; i++) {
                float4 v = *(const float4*)(s0 + i * 4);
                if (s1) {
                    float4 w = *(const float4*)(s1 + i * 4);
                    v.x += w.x; v.y += w.y; v.z += w.z; v.w += w.w;
                }
                *(uint4*)&As[row][seg * 16 + i * 4] = f4tf32(v);
            }
        }
        // ---- stage B (128 x 32): row = output col within chunk ----
        {
            const float* wsrc = p.W + (size_t)row * p.Kdim + kb;
#pragma unroll
            for (int i = 0; i < 4; i++)
                *(uint4*)&Bs[row][seg * 16 + i * 4] = f4tf32(*(const float4*)(wsrc + i * 4));
        }
        __syncthreads();
        // ---- 4 x k8 mma steps ----
#pragma unroll
        for (int kk = 0; kk < 4; kk++) {
            const int c0 = kk * 8 + tg;
            uint32_t a[2][4];
#pragma unroll
            for (int mi = 0; mi < 2; mi++) {
                int r0 = wr + mi * 16 + groupID;
                a[mi][0] = As[r0][c0];
                a[mi][1] = As[r0 + 8][c0];
                a[mi][2] = As[r0][c0 + 4];
                a[mi][3] = As[r0 + 8][c0 + 4];
            }
#pragma unroll
            for (int nj = 0; nj < 8; nj++) {
                int nb_ = wc + nj * 8 + groupID;
                uint32_t b0 = Bs[nb_][c0];
                uint32_t b1 = Bs[nb_][c0 + 4];
                mma_tf32(acc[0][nj], a[0], b0, b1);
                mma_tf32(acc[1][nj], a[1], b0, b1);
            }
        }
        __syncthreads();
    }

    // ---- epilogue ----
#pragma unroll
    for (int mi = 0; mi < 2; mi++) {
        const int r_lo = bm + wr + mi * 16 + groupID;
        const int r_hi = r_lo + 8;
        const bool z_lo = (p.invalid != nullptr) && p.invalid[r_lo];
        const bool z_hi = (p.invalid != nullptr) && p.invalid[r_hi];
        float* clo = p.C + (size_t)r_lo * p.ldC + p.noff;
        float* chi = p.C + (size_t)r_hi * p.ldC + p.noff;
#pragma unroll
        for (int nj = 0; nj < 8; nj++) {
            const int cl = wc + nj * 8 + tg * 2;
            const float b0 = __ldg(&p.bias[cl]);
            const float b1 = __ldg(&p.bias[cl + 1]);
            float v00 = acc[mi][nj][0] + b0, v01 = acc[mi][nj][1] + b1;
            float v10 = acc[mi][nj][2] + b0, v11 = acc[mi][nj][3] + b1;
            if (p.relu) {
                v00 = fmaxf(v00, 0.f); v01 = fmaxf(v01, 0.f);
                v10 = fmaxf(v10, 0.f); v11 = fmaxf(v11, 0.f);
            }
            if (z_lo) { v00 = 0.f; v01 = 0.f; }
            if (z_hi) { v10 = 0.f; v11 = 0.f; }
            *(float2*)(clo + cl) = make_float2(v00, v01);
            *(float2*)(chi + cl) = make_float2(v10, v11);
        }
    }
}

// ---------------------------------------------------------------------------
// fp32 SGEMM (small GEMMs: layer-1 Q/O/fc1, both fc2)
// ---------------------------------------------------------------------------
struct GemmParams {
    int M, N, K, Nsplit;
    const float *W1, *b1, *W2, *b2;
    float* C;
    int relu;
    const unsigned char* invalid;
    const float *Adense, *nf, *memv, *ef, *et, *st;
    const int *idx, *eidx;
};

template <int MODE>
__device__ __forceinline__ float loadA(const GemmParams& p, int m, int j) {
    if constexpr (MODE == MODE_PLAIN) {
        return p.Adense[(size_t)m * p.K + j];
    } else if constexpr (MODE == MODE_QGATHER) {
        if (j < 128) {
            int nd = __ldg(&p.idx[m]);
            return p.nf[(size_t)nd * 128 + j] + p.memv[(size_t)nd * 128 + j];
        }
        return p.st[j - 128];
    } else {
        if (j < 256) return p.Adense[(size_t)m * 256 + j];
        int nd = __ldg(&p.idx[m]);
        return p.nf[(size_t)nd * 128 + (j - 256)] + p.memv[(size_t)nd * 128 + (j - 256)];
    }
}

template <int MODE>
__global__ void __launch_bounds__(256) gemm_kernel(GemmParams p) {
    __shared__ __align__(16) float As[8][132];
    __shared__ __align__(16) float Bs[8][132];
    const int bm = blockIdx.y * 128;
    const int bn = blockIdx.x * 128;
    const int tid = threadIdx.x;
    const int tx = tid & 15;
    const int ty = tid >> 4;

    float acc[8][8];
#pragma unroll
    for (int i = 0; i < 8; i++)
#pragma unroll
        for (int j = 0; j < 8; j++) acc[i][j] = 0.f;

    for (int k0 = 0; k0 < p.K; k0 += 8) {
#pragma unroll
        for (int i = 0; i < 4; i++) {
            int l = tid * 4 + i;
            int row = l >> 3;
            int kk = l & 7;
            As[kk][row] = loadA<MODE>(p, bm + row, k0 + kk);
            int c = bn + row;
            const float* W = (c < p.Nsplit) ? p.W1 : p.W2;
            int cr = (c < p.Nsplit) ? c : (c - p.Nsplit);
            Bs[kk][row] = W[(size_t)cr * p.K + k0 + kk];
        }
        __syncthreads();
#pragma unroll
        for (int kk = 0; kk < 8; kk++) {
            float a[8], b[8];
            *(float4*)&a[0] = *(const float4*)&As[kk][ty * 4];
            *(float4*)&a[4] = *(const float4*)&As[kk][64 + ty * 4];
            *(float4*)&b[0] = *(const float4*)&Bs[kk][tx * 4];
            *(float4*)&b[4] = *(const float4*)&Bs[kk][64 + tx * 4];
#pragma unroll
            for (int i = 0; i < 8; i++)
#pragma unroll
                for (int j = 0; j < 8; j++)
                    acc[i][j] = fmaf(a[i], b[j], acc[i][j]);
        }
        __syncthreads();
    }

#pragma unroll
    for (int i = 0; i < 8; i++) {
        int m2 = bm + ((i < 4) ? (ty * 4 + i) : (64 + ty * 4 + i - 4));
        bool zero = (p.invalid != nullptr) && p.invalid[m2];
#pragma unroll
        for (int j = 0; j < 8; j++) {
            int n = bn + ((j < 4) ? (tx * 4 + j) : (64 + tx * 4 + j - 4));
            float bias = (n < p.Nsplit) ? p.b1[n] : p.b2[n - p.Nsplit];
            float v = acc[i][j] + bias;
            if (p.relu) v = fmaxf(v, 0.f);
            if (zero) v = 0.f;
            p.C[(size_t)m2 * p.N + n] = v;
        }
    }
}

// ---------------------------------------------------------------------------
// Time encoding
// ---------------------------------------------------------------------------
template <int DIV>
__global__ void et_kernel(const float* __restrict__ ts, const float* __restrict__ etm,
                          const float* __restrict__ w, const float* __restrict__ b,
                          float* __restrict__ outp, int npairs) {
    int idx = blockIdx.x * blockDim.x + threadIdx.x;
    if (idx >= npairs * 128) return;
    int m = idx >> 7;
    int j = idx & 127;
    float dt = ts[m / DIV] - etm[m];
    outp[idx] = __cosf(fmaf(dt, w[j], b[j]));
}

__global__ void st_kernel(const float* __restrict__ b) {
    g_st[threadIdx.x] = __cosf(b[threadIdx.x]);
}

// ---------------------------------------------------------------------------
// Temporal attention
// ---------------------------------------------------------------------------
__global__ void attn_kernel(const float* __restrict__ q, const float* __restrict__ kv,
                            const int* __restrict__ nbrs, float* __restrict__ outp,
                            unsigned char* __restrict__ invalid) {
    const int r = blockIdx.x;
    const int tid = threadIdx.x;
    const int warp = tid >> 5;
    const int lane = tid & 31;
    __shared__ float sq[256];
    __shared__ float sc[2][KNB];
    __shared__ float swt[2][KNB];
    __shared__ int smask[KNB];

    if (tid < 256) sq[tid] = q[(size_t)r * 256 + tid];
    if (tid < KNB) smask[tid] = (nbrs[r * KNB + tid] != 0) ? 1 : 0;
    __syncthreads();
    if (tid == 0) {
        int any = 0;
#pragma unroll
        for (int k = 0; k < KNB; k++) any |= smask[k];
        if (!any) smask[KNB - 1] = 1;
        invalid[r] = (unsigned char)(!any);
    }
    __syncthreads();

    if (warp < KNB) {
        const float* kp = kv + ((size_t)r * KNB + warp) * 512;
        float s0 = 0.f, s1 = 0.f;
#pragma unroll
        for (int i = 0; i < 4; i++) {
            int d = lane + 32 * i;
            s0 = fmaf(sq[d], kp[d], s0);
            s1 = fmaf(sq[128 + d], kp[128 + d], s1);
        }
#pragma unroll
        for (int o = 16; o > 0; o >>= 1) {
            s0 += __shfl_down_sync(0xffffffffu, s0, o);
            s1 += __shfl_down_sync(0xffffffffu, s1, o);
        }
        if (lane == 0) {
            const float scale = 0.08838834764831845f;
            sc[0][warp] = smask[warp] ? s0 * scale : -1e9f;
            sc[1][warp] = smask[warp] ? s1 * scale : -1e9f;
        }
    }
    __syncthreads();

    if (tid < 2) {
        float mx = -3.0e38f;
#pragma unroll
        for (int k = 0; k < KNB; k++) mx = fmaxf(mx, sc[tid][k]);
        float sum = 0.f;
#pragma unroll
        for (int k = 0; k < KNB; k++) {
            float e = __expf(sc[tid][k] - mx);
            swt[tid][k] = e;
            sum += e;
        }
        float inv = 1.0f / sum;
#pragma unroll
        for (int k = 0; k < KNB; k++) swt[tid][k] *= inv;
    }
    __syncthreads();

    if (tid < 256) {
        int h = tid >> 7;
        float o = 0.f;
#pragma unroll
        for (int k = 0; k < KNB; k++)
            o = fmaf(swt[h][k], kv[((size_t)r * KNB + k) * 512 + 256 + tid], o);
        outp[(size_t)r * 256 + tid] = o;
    }
}

// ---------------------------------------------------------------------------
// Host side
// ---------------------------------------------------------------------------
static void launch_gemm(int mode, const GemmParams& p) {
    dim3 grid(p.N / 128, p.M / 128);
    switch (mode) {
        case MODE_PLAIN:   gemm_kernel<MODE_PLAIN><<<grid, 256>>>(p); break;
        case MODE_QGATHER: gemm_kernel<MODE_QGATHER><<<grid, 256>>>(p); break;
        case MODE_CONCAT:  gemm_kernel<MODE_CONCAT><<<grid, 256>>>(p); break;
    }
}

static void launch_mma(int mode, int M, const TcParams& p) {
    dim3 grid(M / 128);
    switch (mode) {
        case MODE_PLAIN:      mma_gemm<MODE_PLAIN><<<grid, 256>>>(p); break;
        case MODE_QGATHER:    mma_gemm<MODE_QGATHER><<<grid, 256>>>(p); break;
        case MODE_KIN_GATHER: mma_gemm<MODE_KIN_GATHER><<<grid, 256>>>(p); break;
        case MODE_KIN_DENSE:  mma_gemm<MODE_KIN_DENSE><<<grid, 256>>>(p); break;
        case MODE_CONCAT:     mma_gemm<MODE_CONCAT><<<grid, 256>>>(p); break;
    }
}

extern "C" void kernel_launch(void* const* d_in, const int* in_sizes, int n_in,
                              void* d_out, int out_size) {
    const float* nf   = (const float*)d_in[0];
    const float* mem  = (const float*)d_in[1];
    const float* ef   = (const float*)d_in[2];
    const float* tw   = (const float*)d_in[3];
    const float* tb   = (const float*)d_in[4];
    const float* Wq   = (const float*)d_in[5];
    const float* bq   = (const float*)d_in[6];
    const float* Wk   = (const float*)d_in[7];
    const float* bk   = (const float*)d_in[8];
    const float* Wv   = (const float*)d_in[9];
    const float* bv   = (const float*)d_in[10];
    const float* Wo   = (const float*)d_in[11];
    const float* bo   = (const float*)d_in[12];
    const float* f1w  = (const float*)d_in[13];
    const float* f1b  = (const float*)d_in[14];
    const float* f2w  = (const float*)d_in[15];
    const float* f2b  = (const float*)d_in[16];
    const int*   src  = (const int*)d_in[17];
    const float* ts   = (const float*)d_in[18];
    const int*   nb2  = (const int*)d_in[19];
    const int*   ei2  = (const int*)d_in[20];
    const float* tm2  = (const float*)d_in[21];
    const int*   nb1  = (const int*)d_in[22];
    const int*   ei1  = (const int*)d_in[23];
    const float* tm1  = (const float*)d_in[24];
    float* out = (float*)d_out;

    float *pst, *pet1, *pet2, *pkv1, *pq1, *pattn1, *po1, *ph1, *pemb1;
    float *pkv2, *pq2, *pattn2, *po2, *ph2;
    unsigned char *pinv1, *pinv2;
    cudaGetSymbolAddress((void**)&pst, g_st);
    cudaGetSymbolAddress((void**)&pet1, g_et1);
    cudaGetSymbolAddress((void**)&pet2, g_et2);
    cudaGetSymbolAddress((void**)&pkv1, g_kv1);
    cudaGetSymbolAddress((void**)&pq1, g_q1);
    cudaGetSymbolAddress((void**)&pattn1, g_attn1);
    cudaGetSymbolAddress((void**)&po1, g_o1);
    cudaGetSymbolAddress((void**)&ph1, g_h1);
    cudaGetSymbolAddress((void**)&pemb1, g_emb1);
    cudaGetSymbolAddress((void**)&pinv1, g_inv1);
    cudaGetSymbolAddress((void**)&pkv2, g_kv2);
    cudaGetSymbolAddress((void**)&pq2, g_q2);
    cudaGetSymbolAddress((void**)&pattn2, g_attn2);
    cudaGetSymbolAddress((void**)&po2, g_o2);
    cudaGetSymbolAddress((void**)&ph2, g_h2);
    cudaGetSymbolAddress((void**)&pinv2, g_inv2);

    const int BIG = 1 << 30;

    // --- time encodings ---
    st_kernel<<<1, 128>>>(tb);
    et_kernel<100><<<(NP1 * 128 + 255) / 256, 256>>>(ts, tm1, tw, tb, pet1, NP1);
    et_kernel<10><<<(NP2 * 128 + 255) / 256, 256>>>(ts, tm2, tw, tb, pet2, NP2);

    // ============================== LAYER 0 (hop-1) ==============================
    // Q1 (tf32): [20480,256] over 2 column chunks
    for (int c = 0; c < 2; c++) {
        TcParams p{};
        p.Kdim = 256; p.ldC = 256; p.noff = c * 128;
        p.W = Wq + (size_t)c * 128 * 256; p.bias = bq + c * 128; p.C = pq1;
        p.nf = nf; p.memv = mem; p.st = pst; p.idx = nb2;
        launch_mma(MODE_QGATHER, N1, p);
    }
    // KV1 (tf32): [204800,512] over 4 column chunks (K: Wk, V: Wv)
    for (int c = 0; c < 4; c++) {
        TcParams p{};
        p.Kdim = 384; p.ldC = 512; p.noff = c * 128;
        const float* Wsrc = (c < 2) ? Wk : Wv;
        const float* bsrc = (c < 2) ? bk : bv;
        p.W = Wsrc + (size_t)(c & 1) * 128 * 384; p.bias = bsrc + (c & 1) * 128;
        p.C = pkv1;
        p.nf = nf; p.memv = mem; p.ef = ef; p.et = pet1; p.idx = nb1; p.eidx = ei1;
        launch_mma(MODE_KIN_GATHER, NP1, p);
    }
    attn_kernel<<<N1, 320>>>(pq1, pkv1, nb1, pattn1, pinv1);
    // O1 (tf32): 2 chunks, zero invalid rows
    for (int c = 0; c < 2; c++) {
        TcParams p{};
        p.Kdim = 256; p.ldA = 256; p.ldC = 256; p.noff = c * 128;
        p.W = Wo + (size_t)c * 128 * 256; p.bias = bo + c * 128; p.C = po1;
        p.Adense = pattn1; p.invalid = pinv1;
        launch_mma(MODE_PLAIN, N1, p);
    }
    {   // fc1 L0 (tf32): N=128, 1 chunk, relu
        TcParams p{};
        p.Kdim = 384; p.ldC = 128; p.noff = 0;
        p.W = f1w; p.bias = f1b; p.C = ph1;
        p.Adense = po1; p.nf = nf; p.memv = mem; p.idx = nb2; p.relu = 1;
        launch_mma(MODE_CONCAT, N1, p);
    }
    {   // fc2 L0 (fp32) -> emb1
        GemmParams p{};
        p.M = N1; p.N = 128; p.K = 128; p.Nsplit = BIG;
        p.W1 = f2w; p.b1 = f2b; p.C = pemb1; p.Adense = ph1;
        launch_gemm(MODE_PLAIN, p);
    }

    // ============================== LAYER 1 (top) ==============================
    const float* Wq1 = Wq + 256 * 256;  const float* bq1 = bq + 256;
    const float* Wk1 = Wk + 256 * 384;  const float* bk1 = bk + 256;
    const float* Wv1 = Wv + 256 * 384;  const float* bv1 = bv + 256;
    const float* Wo1 = Wo + 256 * 256;  const float* bo1 = bo + 256;
    const float* f1w1 = f1w + 128 * 384; const float* f1b1 = f1b + 128;
    const float* f2w1 = f2w + 128 * 128; const float* f2b1 = f2b + 128;

    {   // Q2 (fp32)
        GemmParams p{};
        p.M = BB; p.N = 256; p.K = 256; p.Nsplit = BIG;
        p.W1 = Wq1; p.b1 = bq1; p.C = pq2;
        p.nf = nf; p.memv = mem; p.st = pst; p.idx = src;
        launch_gemm(MODE_QGATHER, p);
    }
    // KV2 (tf32): 4 chunks, dense emb1 first segment
    for (int c = 0; c < 4; c++) {
        TcParams p{};
        p.Kdim = 384; p.ldC = 512; p.noff = c * 128;
        const float* Wsrc = (c < 2) ? Wk1 : Wv1;
        const float* bsrc = (c < 2) ? bk1 : bv1;
        p.W = Wsrc + (size_t)(c & 1) * 128 * 384; p.bias = bsrc + (c & 1) * 128;
        p.C = pkv2;
        p.Adense = pemb1; p.ef = ef; p.et = pet2; p.eidx = ei2;
        launch_mma(MODE_KIN_DENSE, NP2, p);
    }
    attn_kernel<<<BB, 320>>>(pq2, pkv2, nb2, pattn2, pinv2);
    {   // O2 (fp32)
        GemmParams p{};
        p.M = BB; p.N = 256; p.K = 256; p.Nsplit = BIG;
        p.W1 = Wo1; p.b1 = bo1; p.C = po2; p.Adense = pattn2; p.invalid = pinv2;
        launch_gemm(MODE_PLAIN, p);
    }
    {   // fc1 L1 (fp32)
        GemmParams p{};
        p.M = BB; p.N = 128; p.K = 384; p.Nsplit = BIG;
        p.W1 = f1w1; p.b1 = f1b1; p.C = ph2; p.Adense = po2;
        p.nf = nf; p.memv = mem; p.idx = src; p.relu = 1;
        launch_gemm(MODE_CONCAT, p);
    }
    {   // fc2 L1 (fp32) -> out
        GemmParams p{};
        p.M = BB; p.N = 128; p.K = 128; p.Nsplit = BIG;
        p.W1 = f2w1; p.b1 = f2b1; p.C = out; p.Adense = ph2;
        launch_gemm(MODE_PLAIN, p);
    }
}

// round 4
// speedup vs baseline: 2.6150x; 1.0683x over previous
#include <cuda_runtime.h>
#include <cstdint>

// ---------------------------------------------------------------------------
// Problem constants
// ---------------------------------------------------------------------------
#define KNB 10
#define BB  2048
#define N1  20480
#define NP1 204800
#define NP2 20480
// D = T = 128, QD = 256, KD = 384, H = 2, hd = 128

// ---------------------------------------------------------------------------
// Scratch
// ---------------------------------------------------------------------------
__device__ float g_st[128];
__device__ float g_kv1[(size_t)NP1 * 512];
__device__ float g_q1 [(size_t)N1  * 256];
__device__ float g_attn1[(size_t)N1 * 256];
__device__ float g_o1 [(size_t)N1  * 256];
__device__ float g_h1 [(size_t)N1  * 128];
__device__ float g_emb1[(size_t)N1 * 128];
__device__ unsigned char g_inv1[N1];
__device__ float g_kv2[(size_t)NP2 * 512];
__device__ float g_q2 [(size_t)BB  * 256];
__device__ float g_attn2[(size_t)BB * 256];
__device__ float g_o2 [(size_t)BB  * 256];
__device__ float g_h2 [(size_t)BB  * 128];
__device__ unsigned char g_inv2[BB];

#define MODE_PLAIN      0
#define MODE_QGATHER    1
#define MODE_CONCAT     4

// ---------------------------------------------------------------------------
// tf32 helpers
// ---------------------------------------------------------------------------
__device__ __forceinline__ uint32_t f2tf32(float f) {
    uint32_t r;
    asm("cvt.rna.tf32.f32 %0, %1;" : "=r"(r) : "f"(f));
    return r;
}
__device__ __forceinline__ uint4 f4tf32(float4 v) {
    uint4 r;
    r.x = f2tf32(v.x); r.y = f2tf32(v.y); r.z = f2tf32(v.z); r.w = f2tf32(v.w);
    return r;
}
__device__ __forceinline__ void mma_tf32(float* c, const uint32_t* a, uint32_t b0, uint32_t b1) {
    asm volatile(
        "mma.sync.aligned.m16n8k8.row.col.f32.tf32.tf32.f32 "
        "{%0,%1,%2,%3}, {%4,%5,%6,%7}, {%8,%9}, {%0,%1,%2,%3};"
        : "+f"(c[0]), "+f"(c[1]), "+f"(c[2]), "+f"(c[3])
        : "r"(a[0]), "r"(a[1]), "r"(a[2]), "r"(a[3]), "r"(b0), "r"(b1));
}

// ===========================================================================
// Fused KV projection kernel (tf32 mma.sync).
// CTA = 64 rows x 512 cols. A (64x384 tf32) resident in smem, gathered once:
//   cols [0,128):   base(idx[m]) = nf+mem   (GATHER) or Adense[m] (DENSE)
//   cols [128,256): ef[eidx[m]]
//   cols [256,384): cos((ts[m/DIV]-etm[m])*w + b)   (fused time encoding)
// Output cols: chunks 0,1 = K (Wk,bk), chunks 2,3 = V (Wv,bv). C row = 512.
// B double-buffered with register prefetch; one barrier per K-chunk.
// ===========================================================================
struct KvParams {
    const float *Wk, *bk, *Wv, *bv;   // [256,384], [256]
    float* C;                          // [M, 512]
    int DIV;
    const float *ts, *etm, *tw, *tb;
    const float *Adense, *nf, *memv, *ef;
    const int *idx, *eidx;
};

#define KV_AS_STRIDE 388
#define KV_AS_OFF 256
#define KV_BS_OFF (KV_AS_OFF + 64 * KV_AS_STRIDE * 4)          // 99584
#define KV_DSMEM (KV_BS_OFF + 2 * 128 * 36 * 4)                 // 136448

template <int DENSE>
__global__ void __launch_bounds__(256) kv_kernel(KvParams p) {
    extern __shared__ char smem[];
    float* dts = (float*)smem;
    uint32_t* As = (uint32_t*)(smem + KV_AS_OFF);
    uint32_t* Bs = (uint32_t*)(smem + KV_BS_OFF);

    const int tid = threadIdx.x;
    const int lane = tid & 31;
    const int wid = tid >> 5;
    const int bm = blockIdx.x * 64;
    const int gID = lane >> 2;
    const int tg = lane & 3;
    const int wr = (wid >> 2) * 32;      // warp row base (0 or 32)
    const int wcl = (wid & 3) * 32;      // warp col base within 128-chunk

    // ---------------- gather A ----------------
    {
        const int grow = tid >> 2;       // 0..63
        const int gseg = tid & 3;        // 0..3
        const int m = bm + grow;
        if (tid < 64) {
            int mm = bm + tid;
            dts[tid] = __ldg(&p.ts[mm / p.DIV]) - __ldg(&p.etm[mm]);
        }
        uint32_t* arow = As + (size_t)grow * KV_AS_STRIDE;
        // part 1: cols 0..127
        if (DENSE) {
            const float4* s = (const float4*)(p.Adense + (size_t)m * 128);
#pragma unroll
            for (int i = 0; i < 8; i++) {
                int cf = gseg + 4 * i;
                *(uint4*)(arow + cf * 4) = f4tf32(s[cf]);
            }
        } else {
            int nd = __ldg(&p.idx[m]);
            const float4* s0 = (const float4*)(p.nf + (size_t)nd * 128);
            const float4* s1 = (const float4*)(p.memv + (size_t)nd * 128);
#pragma unroll
            for (int i = 0; i < 8; i++) {
                int cf = gseg + 4 * i;
                float4 x = s0[cf], y = s1[cf];
                *(uint4*)(arow + cf * 4) =
                    f4tf32(make_float4(x.x + y.x, x.y + y.y, x.z + y.z, x.w + y.w));
            }
        }
        // part 2: cols 128..255 (edge features)
        {
            int e = __ldg(&p.eidx[m]);
            const float4* s = (const float4*)(p.ef + (size_t)e * 128);
#pragma unroll
            for (int i = 0; i < 8; i++) {
                int cf = gseg + 4 * i;
                *(uint4*)(arow + 128 + cf * 4) = f4tf32(s[cf]);
            }
        }
        __syncthreads();   // dts ready
        // part 3: cols 256..383 (fused time encoding)
        {
            float dt = dts[grow];
#pragma unroll
            for (int i = 0; i < 8; i++) {
                int j0 = (gseg + 4 * i) * 4;
                float4 v;
                v.x = __cosf(fmaf(dt, __ldg(&p.tw[j0 + 0]), __ldg(&p.tb[j0 + 0])));
                v.y = __cosf(fmaf(dt, __ldg(&p.tw[j0 + 1]), __ldg(&p.tb[j0 + 1])));
                v.z = __cosf(fmaf(dt, __ldg(&p.tw[j0 + 2]), __ldg(&p.tb[j0 + 2])));
                v.w = __cosf(fmaf(dt, __ldg(&p.tw[j0 + 3]), __ldg(&p.tb[j0 + 3])));
                *(uint4*)(arow + 256 + j0) = f4tf32(v);
            }
        }
    }

    // ---------------- main loop: 4 col-chunks x 12 K-chunks ----------------
    const int brow = tid >> 1;           // 0..127 (weight row within chunk)
    const int bseg = tid & 1;            // 16-float half of the 32-K slice

    // prefetch B chunk (cc=0, s=0)
    float4 breg[4];
    {
        const float* wsrc = p.Wk + (size_t)brow * 384 + bseg * 16;
#pragma unroll
        for (int i = 0; i < 4; i++) breg[i] = *(const float4*)(wsrc + i * 4);
    }

    int it = 0;
#pragma unroll 1
    for (int cc = 0; cc < 4; cc++) {
        float acc[2][4][4];
#pragma unroll
        for (int mi = 0; mi < 2; mi++)
#pragma unroll
            for (int nj = 0; nj < 4; nj++)
#pragma unroll
                for (int q = 0; q < 4; q++) acc[mi][nj][q] = 0.f;

#pragma unroll 1
        for (int s = 0; s < 12; s++) {
            const int buf = it & 1;
            uint32_t* bsl = Bs + buf * (128 * 36) + brow * 36 + bseg * 16;
#pragma unroll
            for (int i = 0; i < 4; i++) *(uint4*)(bsl + i * 4) = f4tf32(breg[i]);
            // prefetch next B chunk
            if (it < 47) {
                int nit = it + 1;
                int ccn = nit >> 2; ccn = nit / 12;
                int sn = nit - ccn * 12;
                const float* wbase = (ccn < 2) ? (p.Wk + (size_t)ccn * 128 * 384)
                                               : (p.Wv + (size_t)(ccn - 2) * 128 * 384);
                const float* wsrc = wbase + (size_t)brow * 384 + sn * 32 + bseg * 16;
#pragma unroll
                for (int i = 0; i < 4; i++) breg[i] = *(const float4*)(wsrc + i * 4);
            }
            __syncthreads();
            // MMA over this 32-K slice
#pragma unroll
            for (int kk = 0; kk < 4; kk++) {
                const int c0 = s * 32 + kk * 8 + tg;
                uint32_t a[2][4];
#pragma unroll
                for (int mi = 0; mi < 2; mi++) {
                    const uint32_t* ar0 = As + (size_t)(wr + mi * 16 + gID) * KV_AS_STRIDE;
                    const uint32_t* ar1 = ar0 + 8 * KV_AS_STRIDE;
                    a[mi][0] = ar0[c0];
                    a[mi][1] = ar1[c0];
                    a[mi][2] = ar0[c0 + 4];
                    a[mi][3] = ar1[c0 + 4];
                }
                const uint32_t* bb = Bs + buf * (128 * 36);
#pragma unroll
                for (int nj = 0; nj < 4; nj++) {
                    const uint32_t* br = bb + (size_t)(wcl + nj * 8 + gID) * 36 + kk * 8;
                    uint32_t b0 = br[tg];
                    uint32_t b1 = br[tg + 4];
                    mma_tf32(acc[0][nj], a[0], b0, b1);
                    mma_tf32(acc[1][nj], a[1], b0, b1);
                }
            }
            it++;
        }

        // epilogue for this col chunk
        const float* bias = (cc < 2) ? (p.bk + cc * 128) : (p.bv + (cc - 2) * 128);
#pragma unroll
        for (int mi = 0; mi < 2; mi++) {
            const int r_lo = bm + wr + mi * 16 + gID;
            float* clo = p.C + (size_t)r_lo * 512 + cc * 128 + wcl;
            float* chi = clo + 8 * 512;
#pragma unroll
            for (int nj = 0; nj < 4; nj++) {
                const int cl = nj * 8 + tg * 2;
                const float b0 = __ldg(&bias[wcl + cl]);
                const float b1 = __ldg(&bias[wcl + cl + 1]);
                *(float2*)(clo + cl) = make_float2(acc[mi][nj][0] + b0, acc[mi][nj][1] + b1);
                *(float2*)(chi + cl) = make_float2(acc[mi][nj][2] + b0, acc[mi][nj][3] + b1);
            }
        }
    }
}

// ===========================================================================
// tf32 mma.sync GEMM (Q / O / fc1): CTA = 128(m) x 128(n); gridDim.y = col chunk.
// ===========================================================================
struct TcParams {
    int Kdim, ldA, ldC;
    const float* W;        // chunk 0 weight base; chunk offset via blockIdx.y
    const float* bias;
    float* C;
    int relu;
    const unsigned char* invalid;
    const float *Adense, *nf, *memv, *st;
    const int *idx;
};

template <int MODE>
__global__ void __launch_bounds__(256) mma_gemm(TcParams p) {
    __shared__ uint32_t As[128][36];
    __shared__ uint32_t Bs[128][36];
    const int tid = threadIdx.x;
    const int lane = tid & 31;
    const int wid = tid >> 5;
    const int bm = blockIdx.x * 128;
    const int noff = blockIdx.y * 128;
    const float* W = p.W + (size_t)noff * p.Kdim;
    const float* bias = p.bias + noff;
    const int row = tid >> 1;
    const int seg = tid & 1;
    const int m = bm + row;
    const int wr = (wid >> 1) * 32;
    const int wc = (wid & 1) * 64;
    const int groupID = lane >> 2;
    const int tg = lane & 3;

    float acc[2][8][4];
#pragma unroll
    for (int mi = 0; mi < 2; mi++)
#pragma unroll
        for (int nj = 0; nj < 8; nj++)
#pragma unroll
            for (int q = 0; q < 4; q++) acc[mi][nj][q] = 0.f;

#pragma unroll 1
    for (int k0 = 0; k0 < p.Kdim; k0 += 32) {
        const int kb = k0 + seg * 16;
        {
            const float* s0 = nullptr;
            const float* s1 = nullptr;
            if constexpr (MODE == MODE_PLAIN) {
                s0 = p.Adense + (size_t)m * p.ldA + kb;
            } else if constexpr (MODE == MODE_QGATHER) {
                if (kb < 128) {
                    int nd = __ldg(&p.idx[m]);
                    s0 = p.nf + (size_t)nd * 128 + kb;
                    s1 = p.memv + (size_t)nd * 128 + kb;
                } else {
                    s0 = p.st + (kb - 128);
                }
            } else {  // MODE_CONCAT
                if (kb < 256) {
                    s0 = p.Adense + (size_t)m * 256 + kb;
                } else {
                    int nd = __ldg(&p.idx[m]);
                    s0 = p.nf + (size_t)nd * 128 + (kb - 256);
                    s1 = p.memv + (size_t)nd * 128 + (kb - 256);
                }
            }
#pragma unroll
            for (int i = 0; i < 4; i++) {
                float4 v = *(const float4*)(s0 + i * 4);
                if (s1) {
                    float4 w = *(const float4*)(s1 + i * 4);
                    v.x += w.x; v.y += w.y; v.z += w.z; v.w += w.w;
                }
                *(uint4*)&As[row][seg * 16 + i * 4] = f4tf32(v);
            }
        }
        {
            const float* wsrc = W + (size_t)row * p.Kdim + kb;
#pragma unroll
            for (int i = 0; i < 4; i++)
                *(uint4*)&Bs[row][seg * 16 + i * 4] = f4tf32(*(const float4*)(wsrc + i * 4));
        }
        __syncthreads();
#pragma unroll
        for (int kk = 0; kk < 4; kk++) {
            const int c0 = kk * 8 + tg;
            uint32_t a[2][4];
#pragma unroll
            for (int mi = 0; mi < 2; mi++) {
                int r0 = wr + mi * 16 + groupID;
                a[mi][0] = As[r0][c0];
                a[mi][1] = As[r0 + 8][c0];
                a[mi][2] = As[r0][c0 + 4];
                a[mi][3] = As[r0 + 8][c0 + 4];
            }
#pragma unroll
            for (int nj = 0; nj < 8; nj++) {
                int nb_ = wc + nj * 8 + groupID;
                uint32_t b0 = Bs[nb_][c0];
                uint32_t b1 = Bs[nb_][c0 + 4];
                mma_tf32(acc[0][nj], a[0], b0, b1);
                mma_tf32(acc[1][nj], a[1], b0, b1);
            }
        }
        __syncthreads();
    }

#pragma unroll
    for (int mi = 0; mi < 2; mi++) {
        const int r_lo = bm + wr + mi * 16 + groupID;
        const int r_hi = r_lo + 8;
        const bool z_lo = (p.invalid != nullptr) && p.invalid[r_lo];
        const bool z_hi = (p.invalid != nullptr) && p.invalid[r_hi];
        float* clo = p.C + (size_t)r_lo * p.ldC + noff;
        float* chi = p.C + (size_t)r_hi * p.ldC + noff;
#pragma unroll
        for (int nj = 0; nj < 8; nj++) {
            const int cl = wc + nj * 8 + tg * 2;
            const float b0 = __ldg(&bias[cl]);
            const float b1 = __ldg(&bias[cl + 1]);
            float v00 = acc[mi][nj][0] + b0, v01 = acc[mi][nj][1] + b1;
            float v10 = acc[mi][nj][2] + b0, v11 = acc[mi][nj][3] + b1;
            if (p.relu) {
                v00 = fmaxf(v00, 0.f); v01 = fmaxf(v01, 0.f);
                v10 = fmaxf(v10, 0.f); v11 = fmaxf(v11, 0.f);
            }
            if (z_lo) { v00 = 0.f; v01 = 0.f; }
            if (z_hi) { v10 = 0.f; v11 = 0.f; }
            *(float2*)(clo + cl) = make_float2(v00, v01);
            *(float2*)(chi + cl) = make_float2(v10, v11);
        }
    }
}

// ---------------------------------------------------------------------------
// fp32 SGEMM (fc2 only)
// ---------------------------------------------------------------------------
struct GemmParams {
    int M, N, K;
    const float *W1, *b1;
    float* C;
    const float* Adense;
};

__global__ void __launch_bounds__(256) gemm_kernel(GemmParams p) {
    __shared__ __align__(16) float As[8][132];
    __shared__ __align__(16) float Bs[8][132];
    const int bm = blockIdx.y * 128;
    const int bn = blockIdx.x * 128;
    const int tid = threadIdx.x;
    const int tx = tid & 15;
    const int ty = tid >> 4;

    float acc[8][8];
#pragma unroll
    for (int i = 0; i < 8; i++)
#pragma unroll
        for (int j = 0; j < 8; j++) acc[i][j] = 0.f;

    for (int k0 = 0; k0 < p.K; k0 += 8) {
#pragma unroll
        for (int i = 0; i < 4; i++) {
            int l = tid * 4 + i;
            int row = l >> 3;
            int kk = l & 7;
            As[kk][row] = p.Adense[(size_t)(bm + row) * p.K + k0 + kk];
            Bs[kk][row] = p.W1[(size_t)(bn + row) * p.K + k0 + kk];
        }
        __syncthreads();
#pragma unroll
        for (int kk = 0; kk < 8; kk++) {
            float a[8], b[8];
            *(float4*)&a[0] = *(const float4*)&As[kk][ty * 4];
            *(float4*)&a[4] = *(const float4*)&As[kk][64 + ty * 4];
            *(float4*)&b[0] = *(const float4*)&Bs[kk][tx * 4];
            *(float4*)&b[4] = *(const float4*)&Bs[kk][64 + tx * 4];
#pragma unroll
            for (int i = 0; i < 8; i++)
#pragma unroll
                for (int j = 0; j < 8; j++)
                    acc[i][j] = fmaf(a[i], b[j], acc[i][j]);
        }
        __syncthreads();
    }

#pragma unroll
    for (int i = 0; i < 8; i++) {
        int m2 = bm + ((i < 4) ? (ty * 4 + i) : (64 + ty * 4 + i - 4));
#pragma unroll
        for (int j = 0; j < 8; j++) {
            int n = bn + ((j < 4) ? (tx * 4 + j) : (64 + tx * 4 + j - 4));
            p.C[(size_t)m2 * p.N + n] = acc[i][j] + p.b1[n];
        }
    }
}

__global__ void st_kernel(const float* __restrict__ b) {
    g_st[threadIdx.x] = __cosf(b[threadIdx.x]);
}

// ---------------------------------------------------------------------------
// Temporal attention
// ---------------------------------------------------------------------------
__global__ void attn_kernel(const float* __restrict__ q, const float* __restrict__ kv,
                            const int* __restrict__ nbrs, float* __restrict__ outp,
                            unsigned char* __restrict__ invalid) {
    const int r = blockIdx.x;
    const int tid = threadIdx.x;
    const int warp = tid >> 5;
    const int lane = tid & 31;
    __shared__ float sq[256];
    __shared__ float sc[2][KNB];
    __shared__ float swt[2][KNB];
    __shared__ int smask[KNB];

    if (tid < 256) sq[tid] = q[(size_t)r * 256 + tid];
    if (tid < KNB) smask[tid] = (nbrs[r * KNB + tid] != 0) ? 1 : 0;
    __syncthreads();
    if (tid == 0) {
        int any = 0;
#pragma unroll
        for (int k = 0; k < KNB; k++) any |= smask[k];
        if (!any) smask[KNB - 1] = 1;
        invalid[r] = (unsigned char)(!any);
    }
    __syncthreads();

    if (warp < KNB) {
        const float* kp = kv + ((size_t)r * KNB + warp) * 512;
        float s0 = 0.f, s1 = 0.f;
#pragma unroll
        for (int i = 0; i < 4; i++) {
            int d = lane + 32 * i;
            s0 = fmaf(sq[d], kp[d], s0);
            s1 = fmaf(sq[128 + d], kp[128 + d], s1);
        }
#pragma unroll
        for (int o = 16; o > 0; o >>= 1) {
            s0 += __shfl_down_sync(0xffffffffu, s0, o);
            s1 += __shfl_down_sync(0xffffffffu, s1, o);
        }
        if (lane == 0) {
            const float scale = 0.08838834764831845f;
            sc[0][warp] = smask[warp] ? s0 * scale : -1e9f;
            sc[1][warp] = smask[warp] ? s1 * scale : -1e9f;
        }
    }
    __syncthreads();

    if (tid < 2) {
        float mx = -3.0e38f;
#pragma unroll
        for (int k = 0; k < KNB; k++) mx = fmaxf(mx, sc[tid][k]);
        float sum = 0.f;
#pragma unroll
        for (int k = 0; k < KNB; k++) {
            float e = __expf(sc[tid][k] - mx);
            swt[tid][k] = e;
            sum += e;
        }
        float inv = 1.0f / sum;
#pragma unroll
        for (int k = 0; k < KNB; k++) swt[tid][k] *= inv;
    }
    __syncthreads();

    if (tid < 256) {
        int h = tid >> 7;
        float o = 0.f;
#pragma unroll
        for (int k = 0; k < KNB; k++)
            o = fmaf(swt[h][k], kv[((size_t)r * KNB + k) * 512 + 256 + tid], o);
        outp[(size_t)r * 256 + tid] = o;
    }
}

// ---------------------------------------------------------------------------
// Host side
// ---------------------------------------------------------------------------
static void launch_mma(int mode, int M, int nchunks, const TcParams& p) {
    dim3 grid(M / 128, nchunks);
    switch (mode) {
        case MODE_PLAIN:   mma_gemm<MODE_PLAIN><<<grid, 256>>>(p); break;
        case MODE_QGATHER: mma_gemm<MODE_QGATHER><<<grid, 256>>>(p); break;
        case MODE_CONCAT:  mma_gemm<MODE_CONCAT><<<grid, 256>>>(p); break;
    }
}

extern "C" void kernel_launch(void* const* d_in, const int* in_sizes, int n_in,
                              void* d_out, int out_size) {
    const float* nf   = (const float*)d_in[0];
    const float* mem  = (const float*)d_in[1];
    const float* ef   = (const float*)d_in[2];
    const float* tw   = (const float*)d_in[3];
    const float* tb   = (const float*)d_in[4];
    const float* Wq   = (const float*)d_in[5];
    const float* bq   = (const float*)d_in[6];
    const float* Wk   = (const float*)d_in[7];
    const float* bk   = (const float*)d_in[8];
    const float* Wv   = (const float*)d_in[9];
    const float* bv   = (const float*)d_in[10];
    const float* Wo   = (const float*)d_in[11];
    const float* bo   = (const float*)d_in[12];
    const float* f1w  = (const float*)d_in[13];
    const float* f1b  = (const float*)d_in[14];
    const float* f2w  = (const float*)d_in[15];
    const float* f2b  = (const float*)d_in[16];
    const int*   src  = (const int*)d_in[17];
    const float* ts   = (const float*)d_in[18];
    const int*   nb2  = (const int*)d_in[19];
    const int*   ei2  = (const int*)d_in[20];
    const float* tm2  = (const float*)d_in[21];
    const int*   nb1  = (const int*)d_in[22];
    const int*   ei1  = (const int*)d_in[23];
    const float* tm1  = (const float*)d_in[24];
    float* out = (float*)d_out;

    float *pst, *pkv1, *pq1, *pattn1, *po1, *ph1, *pemb1;
    float *pkv2, *pq2, *pattn2, *po2, *ph2;
    unsigned char *pinv1, *pinv2;
    cudaGetSymbolAddress((void**)&pst, g_st);
    cudaGetSymbolAddress((void**)&pkv1, g_kv1);
    cudaGetSymbolAddress((void**)&pq1, g_q1);
    cudaGetSymbolAddress((void**)&pattn1, g_attn1);
    cudaGetSymbolAddress((void**)&po1, g_o1);
    cudaGetSymbolAddress((void**)&ph1, g_h1);
    cudaGetSymbolAddress((void**)&pemb1, g_emb1);
    cudaGetSymbolAddress((void**)&pinv1, g_inv1);
    cudaGetSymbolAddress((void**)&pkv2, g_kv2);
    cudaGetSymbolAddress((void**)&pq2, g_q2);
    cudaGetSymbolAddress((void**)&pattn2, g_attn2);
    cudaGetSymbolAddress((void**)&po2, g_o2);
    cudaGetSymbolAddress((void**)&ph2, g_h2);
    cudaGetSymbolAddress((void**)&pinv2, g_inv2);

    cudaFuncSetAttribute(kv_kernel<0>, cudaFuncAttributeMaxDynamicSharedMemorySize, KV_DSMEM);
    cudaFuncSetAttribute(kv_kernel<1>, cudaFuncAttributeMaxDynamicSharedMemorySize, KV_DSMEM);

    st_kernel<<<1, 128>>>(tb);

    // ============================== LAYER 0 (hop-1) ==============================
    {   // Q1 (tf32): [20480,256], 2 col chunks via grid.y
        TcParams p{};
        p.Kdim = 256; p.ldC = 256;
        p.W = Wq; p.bias = bq; p.C = pq1;
        p.nf = nf; p.memv = mem; p.st = pst; p.idx = nb2;
        launch_mma(MODE_QGATHER, N1, 2, p);
    }
    {   // KV1 (tf32, fused): one launch, gather + time-enc fused
        KvParams p{};
        p.Wk = Wk; p.bk = bk; p.Wv = Wv; p.bv = bv; p.C = pkv1;
        p.DIV = 100; p.ts = ts; p.etm = tm1; p.tw = tw; p.tb = tb;
        p.nf = nf; p.memv = mem; p.ef = ef; p.idx = nb1; p.eidx = ei1;
        kv_kernel<0><<<NP1 / 64, 256, KV_DSMEM>>>(p);
    }
    attn_kernel<<<N1, 320>>>(pq1, pkv1, nb1, pattn1, pinv1);
    {   // O1 (tf32): 2 chunks, zero invalid rows
        TcParams p{};
        p.Kdim = 256; p.ldA = 256; p.ldC = 256;
        p.W = Wo; p.bias = bo; p.C = po1;
        p.Adense = pattn1; p.invalid = pinv1;
        launch_mma(MODE_PLAIN, N1, 2, p);
    }
    {   // fc1 L0 (tf32): relu
        TcParams p{};
        p.Kdim = 384; p.ldC = 128;
        p.W = f1w; p.bias = f1b; p.C = ph1;
        p.Adense = po1; p.nf = nf; p.memv = mem; p.idx = nb2; p.relu = 1;
        launch_mma(MODE_CONCAT, N1, 1, p);
    }
    {   // fc2 L0 (fp32) -> emb1
        GemmParams p{};
        p.M = N1; p.N = 128; p.K = 128;
        p.W1 = f2w; p.b1 = f2b; p.C = pemb1; p.Adense = ph1;
        gemm_kernel<<<dim3(1, N1 / 128), 256>>>(p);
    }

    // ============================== LAYER 1 (top) ==============================
    const float* Wq1 = Wq + 256 * 256;  const float* bq1 = bq + 256;
    const float* Wk1 = Wk + 256 * 384;  const float* bk1 = bk + 256;
    const float* Wv1 = Wv + 256 * 384;  const float* bv1 = bv + 256;
    const float* Wo1 = Wo + 256 * 256;  const float* bo1 = bo + 256;
    const float* f1w1 = f1w + 128 * 384; const float* f1b1 = f1b + 128;
    const float* f2w1 = f2w + 128 * 128; const float* f2b1 = f2b + 128;

    {   // Q2 (tf32)
        TcParams p{};
        p.Kdim = 256; p.ldC = 256;
        p.W = Wq1; p.bias = bq1; p.C = pq2;
        p.nf = nf; p.memv = mem; p.st = pst; p.idx = src;
        launch_mma(MODE_QGATHER, BB, 2, p);
    }
    {   // KV2 (tf32, fused): dense emb1 first segment
        KvParams p{};
        p.Wk = Wk1; p.bk = bk1; p.Wv = Wv1; p.bv = bv1; p.C = pkv2;
        p.DIV = 10; p.ts = ts; p.etm = tm2; p.tw = tw; p.tb = tb;
        p.Adense = pemb1; p.ef = ef; p.eidx = ei2;
        kv_kernel<1><<<NP2 / 64, 256, KV_DSMEM>>>(p);
    }
    attn_kernel<<<BB, 320>>>(pq2, pkv2, nb2, pattn2, pinv2);
    {   // O2 (tf32)
        TcParams p{};
        p.Kdim = 256; p.ldA = 256; p.ldC = 256;
        p.W = Wo1; p.bias = bo1; p.C = po2;
        p.Adense = pattn2; p.invalid = pinv2;
        launch_mma(MODE_PLAIN, BB, 2, p);
    }
    {   // fc1 L1 (tf32)
        TcParams p{};
        p.Kdim = 384; p.ldC = 128;
        p.W = f1w1; p.bias = f1b1; p.C = ph2;
        p.Adense = po2; p.nf = nf; p.memv = mem; p.idx = src; p.relu = 1;
        launch_mma(MODE_CONCAT, BB, 1, p);
    }
    {   // fc2 L1 (fp32) -> out
        GemmParams p{};
        p.M = BB; p.N = 128; p.K = 128;
        p.W1 = f2w1; p.b1 = f2b1; p.C = out; p.Adense = ph2;
        gemm_kernel<<<dim3(1, BB / 128), 256>>>(p);
    }
}

// round 5
// speedup vs baseline: 4.4781x; 1.7124x over previous
#include <cuda_runtime.h>
#include <cstdint>

// ---------------------------------------------------------------------------
// Problem constants
// ---------------------------------------------------------------------------
#define KNB 10
#define BB  2048
#define N1  20480
#define NP1 204800
#define NP2 20480
// D = T = 128, QD = 256, KD = 384, H = 2, hd = 128

// ---------------------------------------------------------------------------
// Scratch
// ---------------------------------------------------------------------------
__device__ float g_st[128];
__device__ float g_kv1[(size_t)NP1 * 512];
__device__ float g_q1 [(size_t)N1  * 256];
__device__ float g_attn1[(size_t)N1 * 256];
__device__ float g_o1 [(size_t)N1  * 256];
__device__ float g_h1 [(size_t)N1  * 128];
__device__ float g_emb1[(size_t)N1 * 128];
__device__ unsigned char g_inv1[N1];
__device__ float g_kv2[(size_t)NP2 * 512];
__device__ float g_q2 [(size_t)BB  * 256];
__device__ float g_attn2[(size_t)BB * 256];
__device__ float g_o2 [(size_t)BB  * 256];
__device__ float g_h2 [(size_t)BB  * 128];
__device__ unsigned char g_inv2[BB];
// pre-permuted fragment-ordered tf32 weights for KV (2 layers x 512 n x 384 k)
__device__ uint32_t g_bp[2 * 512 * 384];

#define MODE_PLAIN      0
#define MODE_QGATHER    1
#define MODE_CONCAT     4

// ---------------------------------------------------------------------------
// tf32 helpers
// ---------------------------------------------------------------------------
__device__ __forceinline__ uint32_t f2tf32(float f) {
    uint32_t r;
    asm("cvt.rna.tf32.f32 %0, %1;" : "=r"(r) : "f"(f));
    return r;
}
__device__ __forceinline__ uint4 f4tf32(float4 v) {
    uint4 r;
    r.x = f2tf32(v.x); r.y = f2tf32(v.y); r.z = f2tf32(v.z); r.w = f2tf32(v.w);
    return r;
}
__device__ __forceinline__ void mma_tf32(float* c, const uint32_t* a, uint32_t b0, uint32_t b1) {
    asm volatile(
        "mma.sync.aligned.m16n8k8.row.col.f32.tf32.tf32.f32 "
        "{%0,%1,%2,%3}, {%4,%5,%6,%7}, {%8,%9}, {%0,%1,%2,%3};"
        : "+f"(c[0]), "+f"(c[1]), "+f"(c[2]), "+f"(c[3])
        : "r"(a[0]), "r"(a[1]), "r"(a[2]), "r"(a[3]), "r"(b0), "r"(b1));
}

// ===========================================================================
// B pre-permutation: Wk||Wv [512 n][384 k] fp32 -> fragment-ordered tf32.
// Frag tile = (n-tile nt: 8 n) x (k-pair ktp: 16 k). Lane = (n&7)*4 + (k&3).
// Reg r = (klo>>3)*2 + ((klo&7)>>2), klo = k&15.
// dst[((nt*24 + ktp)*32 + lane)*4 + r]
// ===========================================================================
__global__ void prep_b_kernel(const float* __restrict__ Wk, const float* __restrict__ Wv,
                              uint32_t* __restrict__ dst) {
    int idx = blockIdx.x * blockDim.x + threadIdx.x;   // 2 * 512 * 384
    if (idx >= 2 * 512 * 384) return;
    int l = idx / (512 * 384);
    int rem = idx - l * (512 * 384);
    int n = rem / 384;
    int k = rem - n * 384;
    const float* W = (n < 256) ? (Wk + (size_t)l * 256 * 384 + (size_t)n * 384)
                               : (Wv + (size_t)l * 256 * 384 + (size_t)(n - 256) * 384);
    float v = W[k];
    int nt = n >> 3, gid = n & 7;
    int ktp = k >> 4, klo = k & 15;
    int kk = klo >> 3, remk = klo & 7, hi = remk >> 2, tg = remk & 3;
    int r = kk * 2 + hi;
    int lane = gid * 4 + tg;
    dst[(size_t)l * (512 * 384) + (((size_t)nt * 24 + ktp) * 32 + lane) * 4 + r] = f2tf32(v);
}

// ===========================================================================
// KV projection kernel v2 (tf32 mma.sync, fragment-permuted operands).
// CTA = 64 rows x 512 cols; 8 warps, each 64 rows x 64 cols (mi=4, nj=8).
// A (64x384) gathered once into fragment-permuted smem (98KB), read LDS.128.
// B read directly from pre-permuted gmem (L2-resident) via LDG.128,
// double-buffered in registers. NO __syncthreads in the main loop.
//   A cols [0,128):   nf+mem gather (or Adense), [128,256): ef gather,
//   [256,384): cos((ts - etm)*w + b) fused.
// ===========================================================================
struct KvParams {
    const uint32_t* Bp;               // pre-permuted weights for this layer
    const float *bk, *bv;             // [256] each
    float* C;                          // [M, 512]
    int DIV;
    const float *ts, *etm, *tw, *tb;
    const float *Adense, *nf, *memv, *ef;
    const int *idx, *eidx;
};

#define KV_DSMEM (98304 + 256)

__device__ __forceinline__ void kv_stash(uint32_t* As, int m, int k, uint32_t val) {
    int kt = k >> 3, mi = m >> 4;
    int r16 = m & 15, gid = r16 & 7, hi_r = r16 >> 3;
    int tg = k & 3, hi_k = (k >> 2) & 1;
    As[(((kt * 4 + mi) * 32) + gid * 4 + tg) * 4 + hi_r + 2 * hi_k] = val;
}
__device__ __forceinline__ void kv_stash4(uint32_t* As, int m, int c0, uint4 v) {
    kv_stash(As, m, c0 + 0, v.x);
    kv_stash(As, m, c0 + 1, v.y);
    kv_stash(As, m, c0 + 2, v.z);
    kv_stash(As, m, c0 + 3, v.w);
}

template <int DENSE>
__global__ void __launch_bounds__(256) kv_kernel(KvParams p) {
    extern __shared__ char smem[];
    uint32_t* As = (uint32_t*)smem;                 // 24576 uint32 = 98304 B
    float* dts = (float*)(smem + 98304);            // 64 floats

    const int tid = threadIdx.x;
    const int lane = tid & 31;
    const int wc = tid >> 5;          // warp = col group (0..7)
    const int bm = blockIdx.x * 64;
    const int gID = lane >> 2;
    const int tg = lane & 3;

    // ---------------- gather A into permuted smem ----------------
    {
        const int grow = tid >> 2;    // 0..63
        const int gseg = tid & 3;     // 0..3
        const int m = bm + grow;
        if (tid < 64) {
            int mm = bm + tid;
            dts[tid] = __ldg(&p.ts[mm / p.DIV]) - __ldg(&p.etm[mm]);
        }
        // part 1: cols 0..127
        if (DENSE) {
            const float4* s = (const float4*)(p.Adense + (size_t)m * 128);
#pragma unroll
            for (int i = 0; i < 8; i++) {
                int cf = gseg + 4 * i;
                kv_stash4(As, grow, cf * 4, f4tf32(s[cf]));
            }
        } else {
            int nd = __ldg(&p.idx[m]);
            const float4* s0 = (const float4*)(p.nf + (size_t)nd * 128);
            const float4* s1 = (const float4*)(p.memv + (size_t)nd * 128);
#pragma unroll
            for (int i = 0; i < 8; i++) {
                int cf = gseg + 4 * i;
                float4 x = s0[cf], y = s1[cf];
                kv_stash4(As, grow, cf * 4,
                          f4tf32(make_float4(x.x + y.x, x.y + y.y, x.z + y.z, x.w + y.w)));
            }
        }
        // part 2: cols 128..255 (edge features)
        {
            int e = __ldg(&p.eidx[m]);
            const float4* s = (const float4*)(p.ef + (size_t)e * 128);
#pragma unroll
            for (int i = 0; i < 8; i++) {
                int cf = gseg + 4 * i;
                kv_stash4(As, grow, 128 + cf * 4, f4tf32(s[cf]));
            }
        }
        __syncthreads();   // dts ready
        // part 3: cols 256..383 (fused time encoding)
        {
            float dt = dts[grow];
#pragma unroll
            for (int i = 0; i < 8; i++) {
                int j0 = (gseg + 4 * i) * 4;
                float4 v;
                v.x = __cosf(fmaf(dt, __ldg(&p.tw[j0 + 0]), __ldg(&p.tb[j0 + 0])));
                v.y = __cosf(fmaf(dt, __ldg(&p.tw[j0 + 1]), __ldg(&p.tb[j0 + 1])));
                v.z = __cosf(fmaf(dt, __ldg(&p.tw[j0 + 2]), __ldg(&p.tb[j0 + 2])));
                v.w = __cosf(fmaf(dt, __ldg(&p.tw[j0 + 3]), __ldg(&p.tb[j0 + 3])));
                kv_stash4(As, grow, 256 + j0, f4tf32(v));
            }
        }
    }
    __syncthreads();   // A fully staged; main loop is sync-free

    // ---------------- main loop ----------------
    const uint4* As4 = (const uint4*)As;
    const char* bpw = (const char*)p.Bp + ((size_t)wc * 8) * 24 * 512;  // nt base

    float acc[4][8][4];
#pragma unroll
    for (int mi = 0; mi < 4; mi++)
#pragma unroll
        for (int nj = 0; nj < 8; nj++)
#pragma unroll
            for (int q = 0; q < 4; q++) acc[mi][nj][q] = 0.f;

    uint4 bA[8], bB[8];

#define KV_LDB(buf, ktp_) { \
    _Pragma("unroll") \
    for (int nj = 0; nj < 8; nj++) \
        buf[nj] = *(const uint4*)(bpw + (size_t)nj * (24 * 512) + (ktp_) * 512 + lane * 16); }

#define KV_STEP(buf, ktp_) { \
    _Pragma("unroll") \
    for (int kk = 0; kk < 2; kk++) { \
        const int kt = (ktp_) * 2 + kk; \
        _Pragma("unroll") \
        for (int mi = 0; mi < 4; mi++) { \
            uint4 av = As4[(kt * 4 + mi) * 32 + lane]; \
            uint32_t aa[4] = {av.x, av.y, av.z, av.w}; \
            _Pragma("unroll") \
            for (int nj = 0; nj < 8; nj++) { \
                uint32_t b0 = kk ? buf[nj].z : buf[nj].x; \
                uint32_t b1 = kk ? buf[nj].w : buf[nj].y; \
                mma_tf32(acc[mi][nj], aa, b0, b1); \
            } \
        } \
    } }

    KV_LDB(bA, 0);
#pragma unroll 1
    for (int ktp = 0; ktp < 24; ktp += 2) {
        KV_LDB(bB, ktp + 1);
        KV_STEP(bA, ktp);
        if (ktp + 2 < 24) KV_LDB(bA, ktp + 2);
        KV_STEP(bB, ktp + 1);
    }
#undef KV_LDB
#undef KV_STEP

    // ---------------- epilogue ----------------
#pragma unroll
    for (int mi = 0; mi < 4; mi++) {
        const int r_lo = bm + mi * 16 + gID;
        float* clo = p.C + (size_t)r_lo * 512;
        float* chi = clo + (size_t)8 * 512;
#pragma unroll
        for (int nj = 0; nj < 8; nj++) {
            const int col = wc * 64 + nj * 8 + tg * 2;
            const float b0 = (col < 256) ? __ldg(&p.bk[col]) : __ldg(&p.bv[col - 256]);
            const float b1 = (col + 1 < 256) ? __ldg(&p.bk[col + 1]) : __ldg(&p.bv[col + 1 - 256]);
            *(float2*)(clo + col) = make_float2(acc[mi][nj][0] + b0, acc[mi][nj][1] + b1);
            *(float2*)(chi + col) = make_float2(acc[mi][nj][2] + b0, acc[mi][nj][3] + b1);
        }
    }
}

// ===========================================================================
// tf32 mma.sync GEMM (Q / O / fc1): CTA = 128(m) x 128(n); gridDim.y = col chunk.
// ===========================================================================
struct TcParams {
    int Kdim, ldA, ldC;
    const float* W;
    const float* bias;
    float* C;
    int relu;
    const unsigned char* invalid;
    const float *Adense, *nf, *memv, *st;
    const int *idx;
};

template <int MODE>
__global__ void __launch_bounds__(256) mma_gemm(TcParams p) {
    __shared__ uint32_t As[128][36];
    __shared__ uint32_t Bs[128][36];
    const int tid = threadIdx.x;
    const int lane = tid & 31;
    const int wid = tid >> 5;
    const int bm = blockIdx.x * 128;
    const int noff = blockIdx.y * 128;
    const float* W = p.W + (size_t)noff * p.Kdim;
    const float* bias = p.bias + noff;
    const int row = tid >> 1;
    const int seg = tid & 1;
    const int m = bm + row;
    const int wr = (wid >> 1) * 32;
    const int wc = (wid & 1) * 64;
    const int groupID = lane >> 2;
    const int tg = lane & 3;

    float acc[2][8][4];
#pragma unroll
    for (int mi = 0; mi < 2; mi++)
#pragma unroll
        for (int nj = 0; nj < 8; nj++)
#pragma unroll
            for (int q = 0; q < 4; q++) acc[mi][nj][q] = 0.f;

#pragma unroll 1
    for (int k0 = 0; k0 < p.Kdim; k0 += 32) {
        const int kb = k0 + seg * 16;
        {
            const float* s0 = nullptr;
            const float* s1 = nullptr;
            if constexpr (MODE == MODE_PLAIN) {
                s0 = p.Adense + (size_t)m * p.ldA + kb;
            } else if constexpr (MODE == MODE_QGATHER) {
                if (kb < 128) {
                    int nd = __ldg(&p.idx[m]);
                    s0 = p.nf + (size_t)nd * 128 + kb;
                    s1 = p.memv + (size_t)nd * 128 + kb;
                } else {
                    s0 = p.st + (kb - 128);
                }
            } else {  // MODE_CONCAT
                if (kb < 256) {
                    s0 = p.Adense + (size_t)m * 256 + kb;
                } else {
                    int nd = __ldg(&p.idx[m]);
                    s0 = p.nf + (size_t)nd * 128 + (kb - 256);
                    s1 = p.memv + (size_t)nd * 128 + (kb - 256);
                }
            }
#pragma unroll
            for (int i = 0; i < 4; i++) {
                float4 v = *(const float4*)(s0 + i * 4);
                if (s1) {
                    float4 w = *(const float4*)(s1 + i * 4);
                    v.x += w.x; v.y += w.y; v.z += w.z; v.w += w.w;
                }
                *(uint4*)&As[row][seg * 16 + i * 4] = f4tf32(v);
            }
        }
        {
            const float* wsrc = W + (size_t)row * p.Kdim + kb;
#pragma unroll
            for (int i = 0; i < 4; i++)
                *(uint4*)&Bs[row][seg * 16 + i * 4] = f4tf32(*(const float4*)(wsrc + i * 4));
        }
        __syncthreads();
#pragma unroll
        for (int kk = 0; kk < 4; kk++) {
            const int c0 = kk * 8 + tg;
            uint32_t a[2][4];
#pragma unroll
            for (int mi = 0; mi < 2; mi++) {
                int r0 = wr + mi * 16 + groupID;
                a[mi][0] = As[r0][c0];
                a[mi][1] = As[r0 + 8][c0];
                a[mi][2] = As[r0][c0 + 4];
                a[mi][3] = As[r0 + 8][c0 + 4];
            }
#pragma unroll
            for (int nj = 0; nj < 8; nj++) {
                int nb_ = wc + nj * 8 + groupID;
                uint32_t b0 = Bs[nb_][c0];
                uint32_t b1 = Bs[nb_][c0 + 4];
                mma_tf32(acc[0][nj], a[0], b0, b1);
                mma_tf32(acc[1][nj], a[1], b0, b1);
            }
        }
        __syncthreads();
    }

#pragma unroll
    for (int mi = 0; mi < 2; mi++) {
        const int r_lo = bm + wr + mi * 16 + groupID;
        const int r_hi = r_lo + 8;
        const bool z_lo = (p.invalid != nullptr) && p.invalid[r_lo];
        const bool z_hi = (p.invalid != nullptr) && p.invalid[r_hi];
        float* clo = p.C + (size_t)r_lo * p.ldC + noff;
        float* chi = p.C + (size_t)r_hi * p.ldC + noff;
#pragma unroll
        for (int nj = 0; nj < 8; nj++) {
            const int cl = wc + nj * 8 + tg * 2;
            const float b0 = __ldg(&bias[cl]);
            const float b1 = __ldg(&bias[cl + 1]);
            float v00 = acc[mi][nj][0] + b0, v01 = acc[mi][nj][1] + b1;
            float v10 = acc[mi][nj][2] + b0, v11 = acc[mi][nj][3] + b1;
            if (p.relu) {
                v00 = fmaxf(v00, 0.f); v01 = fmaxf(v01, 0.f);
                v10 = fmaxf(v10, 0.f); v11 = fmaxf(v11, 0.f);
            }
            if (z_lo) { v00 = 0.f; v01 = 0.f; }
            if (z_hi) { v10 = 0.f; v11 = 0.f; }
            *(float2*)(clo + cl) = make_float2(v00, v01);
            *(float2*)(chi + cl) = make_float2(v10, v11);
        }
    }
}

// ---------------------------------------------------------------------------
// fp32 SGEMM (fc2 only)
// ---------------------------------------------------------------------------
struct GemmParams {
    int M, N, K;
    const float *W1, *b1;
    float* C;
    const float* Adense;
};

__global__ void __launch_bounds__(256) gemm_kernel(GemmParams p) {
    __shared__ __align__(16) float As[8][132];
    __shared__ __align__(16) float Bs[8][132];
    const int bm = blockIdx.y * 128;
    const int bn = blockIdx.x * 128;
    const int tid = threadIdx.x;
    const int tx = tid & 15;
    const int ty = tid >> 4;

    float acc[8][8];
#pragma unroll
    for (int i = 0; i < 8; i++)
#pragma unroll
        for (int j = 0; j < 8; j++) acc[i][j] = 0.f;

    for (int k0 = 0; k0 < p.K; k0 += 8) {
#pragma unroll
        for (int i = 0; i < 4; i++) {
            int l = tid * 4 + i;
            int row = l >> 3;
            int kk = l & 7;
            As[kk][row] = p.Adense[(size_t)(bm + row) * p.K + k0 + kk];
            Bs[kk][row] = p.W1[(size_t)(bn + row) * p.K + k0 + kk];
        }
        __syncthreads();
#pragma unroll
        for (int kk = 0; kk < 8; kk++) {
            float a[8], b[8];
            *(float4*)&a[0] = *(const float4*)&As[kk][ty * 4];
            *(float4*)&a[4] = *(const float4*)&As[kk][64 + ty * 4];
            *(float4*)&b[0] = *(const float4*)&Bs[kk][tx * 4];
            *(float4*)&b[4] = *(const float4*)&Bs[kk][64 + tx * 4];
#pragma unroll
            for (int i = 0; i < 8; i++)
#pragma unroll
                for (int j = 0; j < 8; j++)
                    acc[i][j] = fmaf(a[i], b[j], acc[i][j]);
        }
        __syncthreads();
    }

#pragma unroll
    for (int i = 0; i < 8; i++) {
        int m2 = bm + ((i < 4) ? (ty * 4 + i) : (64 + ty * 4 + i - 4));
#pragma unroll
        for (int j = 0; j < 8; j++) {
            int n = bn + ((j < 4) ? (tx * 4 + j) : (64 + tx * 4 + j - 4));
            p.C[(size_t)m2 * p.N + n] = acc[i][j] + p.b1[n];
        }
    }
}

__global__ void st_kernel(const float* __restrict__ b) {
    g_st[threadIdx.x] = __cosf(b[threadIdx.x]);
}

// ---------------------------------------------------------------------------
// Temporal attention
// ---------------------------------------------------------------------------
__global__ void attn_kernel(const float* __restrict__ q, const float* __restrict__ kv,
                            const int* __restrict__ nbrs, float* __restrict__ outp,
                            unsigned char* __restrict__ invalid) {
    const int r = blockIdx.x;
    const int tid = threadIdx.x;
    const int warp = tid >> 5;
    const int lane = tid & 31;
    __shared__ float sq[256];
    __shared__ float sc[2][KNB];
    __shared__ float swt[2][KNB];
    __shared__ int smask[KNB];

    if (tid < 256) sq[tid] = q[(size_t)r * 256 + tid];
    if (tid < KNB) smask[tid] = (nbrs[r * KNB + tid] != 0) ? 1 : 0;
    __syncthreads();
    if (tid == 0) {
        int any = 0;
#pragma unroll
        for (int k = 0; k < KNB; k++) any |= smask[k];
        if (!any) smask[KNB - 1] = 1;
        invalid[r] = (unsigned char)(!any);
    }
    __syncthreads();

    if (warp < KNB) {
        const float* kp = kv + ((size_t)r * KNB + warp) * 512;
        float s0 = 0.f, s1 = 0.f;
#pragma unroll
        for (int i = 0; i < 4; i++) {
            int d = lane + 32 * i;
            s0 = fmaf(sq[d], kp[d], s0);
            s1 = fmaf(sq[128 + d], kp[128 + d], s1);
        }
#pragma unroll
        for (int o = 16; o > 0; o >>= 1) {
            s0 += __shfl_down_sync(0xffffffffu, s0, o);
            s1 += __shfl_down_sync(0xffffffffu, s1, o);
        }
        if (lane == 0) {
            const float scale = 0.08838834764831845f;
            sc[0][warp] = smask[warp] ? s0 * scale : -1e9f;
            sc[1][warp] = smask[warp] ? s1 * scale : -1e9f;
        }
    }
    __syncthreads();

    if (tid < 2) {
        float mx = -3.0e38f;
#pragma unroll
        for (int k = 0; k < KNB; k++) mx = fmaxf(mx, sc[tid][k]);
        float sum = 0.f;
#pragma unroll
        for (int k = 0; k < KNB; k++) {
            float e = __expf(sc[tid][k] - mx);
            swt[tid][k] = e;
            sum += e;
        }
        float inv = 1.0f / sum;
#pragma unroll
        for (int k = 0; k < KNB; k++) swt[tid][k] *= inv;
    }
    __syncthreads();

    if (tid < 256) {
        int h = tid >> 7;
        float o = 0.f;
#pragma unroll
        for (int k = 0; k < KNB; k++)
            o = fmaf(swt[h][k], kv[((size_t)r * KNB + k) * 512 + 256 + tid], o);
        outp[(size_t)r * 256 + tid] = o;
    }
}

// ---------------------------------------------------------------------------
// Host side
// ---------------------------------------------------------------------------
static void launch_mma(int mode, int M, int nchunks, const TcParams& p) {
    dim3 grid(M / 128, nchunks);
    switch (mode) {
        case MODE_PLAIN:   mma_gemm<MODE_PLAIN><<<grid, 256>>>(p); break;
        case MODE_QGATHER: mma_gemm<MODE_QGATHER><<<grid, 256>>>(p); break;
        case MODE_CONCAT:  mma_gemm<MODE_CONCAT><<<grid, 256>>>(p); break;
    }
}

extern "C" void kernel_launch(void* const* d_in, const int* in_sizes, int n_in,
                              void* d_out, int out_size) {
    const float* nf   = (const float*)d_in[0];
    const float* mem  = (const float*)d_in[1];
    const float* ef   = (const float*)d_in[2];
    const float* tw   = (const float*)d_in[3];
    const float* tb   = (const float*)d_in[4];
    const float* Wq   = (const float*)d_in[5];
    const float* bq   = (const float*)d_in[6];
    const float* Wk   = (const float*)d_in[7];
    const float* bk   = (const float*)d_in[8];
    const float* Wv   = (const float*)d_in[9];
    const float* bv   = (const float*)d_in[10];
    const float* Wo   = (const float*)d_in[11];
    const float* bo   = (const float*)d_in[12];
    const float* f1w  = (const float*)d_in[13];
    const float* f1b  = (const float*)d_in[14];
    const float* f2w  = (const float*)d_in[15];
    const float* f2b  = (const float*)d_in[16];
    const int*   src  = (const int*)d_in[17];
    const float* ts   = (const float*)d_in[18];
    const int*   nb2  = (const int*)d_in[19];
    const int*   ei2  = (const int*)d_in[20];
    const float* tm2  = (const float*)d_in[21];
    const int*   nb1  = (const int*)d_in[22];
    const int*   ei1  = (const int*)d_in[23];
    const float* tm1  = (const float*)d_in[24];
    float* out = (float*)d_out;

    float *pst, *pkv1, *pq1, *pattn1, *po1, *ph1, *pemb1;
    float *pkv2, *pq2, *pattn2, *po2, *ph2;
    unsigned char *pinv1, *pinv2;
    uint32_t* pbp;
    cudaGetSymbolAddress((void**)&pst, g_st);
    cudaGetSymbolAddress((void**)&pkv1, g_kv1);
    cudaGetSymbolAddress((void**)&pq1, g_q1);
    cudaGetSymbolAddress((void**)&pattn1, g_attn1);
    cudaGetSymbolAddress((void**)&po1, g_o1);
    cudaGetSymbolAddress((void**)&ph1, g_h1);
    cudaGetSymbolAddress((void**)&pemb1, g_emb1);
    cudaGetSymbolAddress((void**)&pinv1, g_inv1);
    cudaGetSymbolAddress((void**)&pkv2, g_kv2);
    cudaGetSymbolAddress((void**)&pq2, g_q2);
    cudaGetSymbolAddress((void**)&pattn2, g_attn2);
    cudaGetSymbolAddress((void**)&po2, g_o2);
    cudaGetSymbolAddress((void**)&ph2, g_h2);
    cudaGetSymbolAddress((void**)&pinv2, g_inv2);
    cudaGetSymbolAddress((void**)&pbp, g_bp);

    cudaFuncSetAttribute(kv_kernel<0>, cudaFuncAttributeMaxDynamicSharedMemorySize, KV_DSMEM);
    cudaFuncSetAttribute(kv_kernel<1>, cudaFuncAttributeMaxDynamicSharedMemorySize, KV_DSMEM);

    st_kernel<<<1, 128>>>(tb);
    prep_b_kernel<<<(2 * 512 * 384 + 255) / 256, 256>>>(Wk, Wv, pbp);

    // ============================== LAYER 0 (hop-1) ==============================
    {   // Q1 (tf32): [20480,256], 2 col chunks via grid.y
        TcParams p{};
        p.Kdim = 256; p.ldC = 256;
        p.W = Wq; p.bias = bq; p.C = pq1;
        p.nf = nf; p.memv = mem; p.st = pst; p.idx = nb2;
        launch_mma(MODE_QGATHER, N1, 2, p);
    }
    {   // KV1 (tf32 v2)
        KvParams p{};
        p.Bp = pbp; p.bk = bk; p.bv = bv; p.C = pkv1;
        p.DIV = 100; p.ts = ts; p.etm = tm1; p.tw = tw; p.tb = tb;
        p.nf = nf; p.memv = mem; p.ef = ef; p.idx = nb1; p.eidx = ei1;
        kv_kernel<0><<<NP1 / 64, 256, KV_DSMEM>>>(p);
    }
    attn_kernel<<<N1, 320>>>(pq1, pkv1, nb1, pattn1, pinv1);
    {   // O1 (tf32): 2 chunks, zero invalid rows
        TcParams p{};
        p.Kdim = 256; p.ldA = 256; p.ldC = 256;
        p.W = Wo; p.bias = bo; p.C = po1;
        p.Adense = pattn1; p.invalid = pinv1;
        launch_mma(MODE_PLAIN, N1, 2, p);
    }
    {   // fc1 L0 (tf32): relu
        TcParams p{};
        p.Kdim = 384; p.ldC = 128;
        p.W = f1w; p.bias = f1b; p.C = ph1;
        p.Adense = po1; p.nf = nf; p.memv = mem; p.idx = nb2; p.relu = 1;
        launch_mma(MODE_CONCAT, N1, 1, p);
    }
    {   // fc2 L0 (fp32) -> emb1
        GemmParams p{};
        p.M = N1; p.N = 128; p.K = 128;
        p.W1 = f2w; p.b1 = f2b; p.C = pemb1; p.Adense = ph1;
        gemm_kernel<<<dim3(1, N1 / 128), 256>>>(p);
    }

    // ============================== LAYER 1 (top) ==============================
    const float* Wq1 = Wq + 256 * 256;  const float* bq1 = bq + 256;
    const float* bk1 = bk + 256;
    const float* bv1 = bv + 256;
    const float* Wo1 = Wo + 256 * 256;  const float* bo1 = bo + 256;
    const float* f1w1 = f1w + 128 * 384; const float* f1b1 = f1b + 128;
    const float* f2w1 = f2w + 128 * 128; const float* f2b1 = f2b + 128;

    {   // Q2 (tf32)
        TcParams p{};
        p.Kdim = 256; p.ldC = 256;
        p.W = Wq1; p.bias = bq1; p.C = pq2;
        p.nf = nf; p.memv = mem; p.st = pst; p.idx = src;
        launch_mma(MODE_QGATHER, BB, 2, p);
    }
    {   // KV2 (tf32 v2, dense)
        KvParams p{};
        p.Bp = pbp + 512 * 384; p.bk = bk1; p.bv = bv1; p.C = pkv2;
        p.DIV = 10; p.ts = ts; p.etm = tm2; p.tw = tw; p.tb = tb;
        p.Adense = pemb1; p.ef = ef; p.eidx = ei2;
        kv_kernel<1><<<NP2 / 64, 256, KV_DSMEM>>>(p);
    }
    attn_kernel<<<BB, 320>>>(pq2, pkv2, nb2, pattn2, pinv2);
    {   // O2 (tf32)
        TcParams p{};
        p.Kdim = 256; p.ldA = 256; p.ldC = 256;
        p.W = Wo1; p.bias = bo1; p.C = po2;
        p.Adense = pattn2; p.invalid = pinv2;
        launch_mma(MODE_PLAIN, BB, 2, p);
    }
    {   // fc1 L1 (tf32)
        TcParams p{};
        p.Kdim = 384; p.ldC = 128;
        p.W = f1w1; p.bias = f1b1; p.C = ph2;
        p.Adense = po2; p.nf = nf; p.memv = mem; p.idx = src; p.relu = 1;
        launch_mma(MODE_CONCAT, BB, 1, p);
    }
    {   // fc2 L1 (fp32) -> out
        GemmParams p{};
        p.M = BB; p.N = 128; p.K = 128;
        p.W1 = f2w1; p.b1 = f2b1; p.C = out; p.Adense = ph2;
        gemm_kernel<<<dim3(1, BB / 128), 256>>>(p);
    }
}

// round 6
// speedup vs baseline: 4.9177x; 1.0982x over previous
#include <cuda_runtime.h>
#include <cstdint>

// ---------------------------------------------------------------------------
// Problem constants
// ---------------------------------------------------------------------------
#define KNB 10
#define BB  2048
#define N1  20480
#define NP1 204800
#define NP2 20480
// D = T = 128, QD = 256, KD = 384, H = 2, hd = 128

// ---------------------------------------------------------------------------
// Scratch
// ---------------------------------------------------------------------------
__device__ float g_st[128];
__device__ float g_kv1[(size_t)NP1 * 512];
__device__ float g_q1 [(size_t)N1  * 256];
__device__ float g_attn1[(size_t)N1 * 256];
__device__ float g_o1 [(size_t)N1  * 256];
__device__ float g_h1 [(size_t)N1  * 128];
__device__ float g_emb1[(size_t)N1 * 128];
__device__ unsigned char g_inv1[N1];
__device__ float g_kv2[(size_t)NP2 * 512];
__device__ float g_q2 [(size_t)BB  * 256];
__device__ float g_attn2[(size_t)BB * 256];
__device__ float g_o2 [(size_t)BB  * 256];
__device__ float g_h2 [(size_t)BB  * 128];
__device__ unsigned char g_inv2[BB];
// pre-permuted fragment-ordered tf32 weights for KV (2 layers x 512 n x 384 k)
__device__ uint32_t g_bp[2 * 512 * 384];

#define MODE_PLAIN      0
#define MODE_QGATHER    1
#define MODE_CONCAT     4

// ---------------------------------------------------------------------------
// tf32 helpers
// ---------------------------------------------------------------------------
__device__ __forceinline__ uint32_t f2tf32(float f) {
    uint32_t r;
    asm("cvt.rna.tf32.f32 %0, %1;" : "=r"(r) : "f"(f));
    return r;
}
__device__ __forceinline__ uint4 f4tf32(float4 v) {
    uint4 r;
    r.x = f2tf32(v.x); r.y = f2tf32(v.y); r.z = f2tf32(v.z); r.w = f2tf32(v.w);
    return r;
}
__device__ __forceinline__ void mma_tf32(float* c, const uint32_t* a, uint32_t b0, uint32_t b1) {
    asm volatile(
        "mma.sync.aligned.m16n8k8.row.col.f32.tf32.tf32.f32 "
        "{%0,%1,%2,%3}, {%4,%5,%6,%7}, {%8,%9}, {%0,%1,%2,%3};"
        : "+f"(c[0]), "+f"(c[1]), "+f"(c[2]), "+f"(c[3])
        : "r"(a[0]), "r"(a[1]), "r"(a[2]), "r"(a[3]), "r"(b0), "r"(b1));
}

// ===========================================================================
// B pre-permutation: Wk||Wv [512 n][384 k] fp32 -> fragment-ordered tf32.
// ===========================================================================
__global__ void prep_b_kernel(const float* __restrict__ Wk, const float* __restrict__ Wv,
                              uint32_t* __restrict__ dst) {
    int idx = blockIdx.x * blockDim.x + threadIdx.x;   // 2 * 512 * 384
    if (idx >= 2 * 512 * 384) return;
    int l = idx / (512 * 384);
    int rem = idx - l * (512 * 384);
    int n = rem / 384;
    int k = rem - n * 384;
    const float* W = (n < 256) ? (Wk + (size_t)l * 256 * 384 + (size_t)n * 384)
                               : (Wv + (size_t)l * 256 * 384 + (size_t)(n - 256) * 384);
    float v = W[k];
    int nt = n >> 3, gid = n & 7;
    int ktp = k >> 4, klo = k & 15;
    int kk = klo >> 3, remk = klo & 7, hi = remk >> 2, tg = remk & 3;
    int r = kk * 2 + hi;
    int lane = gid * 4 + tg;
    dst[(size_t)l * (512 * 384) + (((size_t)nt * 24 + ktp) * 32 + lane) * 4 + r] = f2tf32(v);
}

// ===========================================================================
// KV projection kernel v3 (tf32 mma.sync, fragment-permuted operands).
// CTA = 64 rows x 512 cols; 8 warps, each 64 rows x 64 cols.
// A gathered once into fragment-permuted smem; A frags DOUBLE-BUFFERED in
// registers per kt; B (pre-permuted, L2-resident) double-buffered per ktp.
// No __syncthreads in the main loop.
// ===========================================================================
struct KvParams {
    const uint32_t* Bp;
    const float *bk, *bv;
    float* C;
    int DIV;
    const float *ts, *etm, *tw, *tb;
    const float *Adense, *nf, *memv, *ef;
    const int *idx, *eidx;
};

#define KV_DSMEM (98304 + 256)

__device__ __forceinline__ void kv_stash(uint32_t* As, int m, int k, uint32_t val) {
    int kt = k >> 3, mi = m >> 4;
    int r16 = m & 15, gid = r16 & 7, hi_r = r16 >> 3;
    int tg = k & 3, hi_k = (k >> 2) & 1;
    As[(((kt * 4 + mi) * 32) + gid * 4 + tg) * 4 + hi_r + 2 * hi_k] = val;
}
__device__ __forceinline__ void kv_stash4(uint32_t* As, int m, int c0, uint4 v) {
    kv_stash(As, m, c0 + 0, v.x);
    kv_stash(As, m, c0 + 1, v.y);
    kv_stash(As, m, c0 + 2, v.z);
    kv_stash(As, m, c0 + 3, v.w);
}

template <int DENSE>
__global__ void __launch_bounds__(256) kv_kernel(KvParams p) {
    extern __shared__ char smem[];
    uint32_t* As = (uint32_t*)smem;                 // 24576 uint32 = 98304 B
    float* dts = (float*)(smem + 98304);            // 64 floats

    const int tid = threadIdx.x;
    const int lane = tid & 31;
    const int wc = tid >> 5;          // warp = col group (0..7)
    const int bm = blockIdx.x * 64;
    const int gID = lane >> 2;
    const int tg = lane & 3;

    // ---------------- gather A into permuted smem ----------------
    {
        const int grow = tid >> 2;    // 0..63
        const int gseg = tid & 3;     // 0..3
        const int m = bm + grow;
        if (tid < 64) {
            int mm = bm + tid;
            dts[tid] = __ldg(&p.ts[mm / p.DIV]) - __ldg(&p.etm[mm]);
        }
        if (DENSE) {
            const float4* s = (const float4*)(p.Adense + (size_t)m * 128);
#pragma unroll
            for (int i = 0; i < 8; i++) {
                int cf = gseg + 4 * i;
                kv_stash4(As, grow, cf * 4, f4tf32(s[cf]));
            }
        } else {
            int nd = __ldg(&p.idx[m]);
            const float4* s0 = (const float4*)(p.nf + (size_t)nd * 128);
            const float4* s1 = (const float4*)(p.memv + (size_t)nd * 128);
#pragma unroll
            for (int i = 0; i < 8; i++) {
                int cf = gseg + 4 * i;
                float4 x = s0[cf], y = s1[cf];
                kv_stash4(As, grow, cf * 4,
                          f4tf32(make_float4(x.x + y.x, x.y + y.y, x.z + y.z, x.w + y.w)));
            }
        }
        {
            int e = __ldg(&p.eidx[m]);
            const float4* s = (const float4*)(p.ef + (size_t)e * 128);
#pragma unroll
            for (int i = 0; i < 8; i++) {
                int cf = gseg + 4 * i;
                kv_stash4(As, grow, 128 + cf * 4, f4tf32(s[cf]));
            }
        }
        __syncthreads();   // dts ready
        {
            float dt = dts[grow];
#pragma unroll
            for (int i = 0; i < 8; i++) {
                int j0 = (gseg + 4 * i) * 4;
                float4 v;
                v.x = __cosf(fmaf(dt, __ldg(&p.tw[j0 + 0]), __ldg(&p.tb[j0 + 0])));
                v.y = __cosf(fmaf(dt, __ldg(&p.tw[j0 + 1]), __ldg(&p.tb[j0 + 1])));
                v.z = __cosf(fmaf(dt, __ldg(&p.tw[j0 + 2]), __ldg(&p.tb[j0 + 2])));
                v.w = __cosf(fmaf(dt, __ldg(&p.tw[j0 + 3]), __ldg(&p.tb[j0 + 3])));
                kv_stash4(As, grow, 256 + j0, f4tf32(v));
            }
        }
    }
    __syncthreads();   // A fully staged; main loop is sync-free

    // ---------------- main loop ----------------
    const uint4* As4 = (const uint4*)As;
    const char* bpw = (const char*)p.Bp + ((size_t)wc * 8) * 24 * 512;

    float acc[4][8][4];
#pragma unroll
    for (int mi = 0; mi < 4; mi++)
#pragma unroll
        for (int nj = 0; nj < 8; nj++)
#pragma unroll
            for (int q = 0; q < 4; q++) acc[mi][nj][q] = 0.f;

    uint4 bA[8], bB[8];
    uint4 aCur[4], aNxt[4];

#define KV_LDB(buf, ktp_) { \
    _Pragma("unroll") \
    for (int nj = 0; nj < 8; nj++) \
        buf[nj] = *(const uint4*)(bpw + (size_t)nj * (24 * 512) + (ktp_) * 512 + lane * 16); }

#define KV_LDA(dst, kt_) { \
    _Pragma("unroll") \
    for (int mi = 0; mi < 4; mi++) \
        dst[mi] = As4[((kt_) * 4 + mi) * 32 + lane]; }

#define KV_MMA(a_, buf, kk) { \
    _Pragma("unroll") \
    for (int mi = 0; mi < 4; mi++) { \
        uint32_t aa[4] = {a_[mi].x, a_[mi].y, a_[mi].z, a_[mi].w}; \
        _Pragma("unroll") \
        for (int nj = 0; nj < 8; nj++) { \
            uint32_t b0 = (kk) ? buf[nj].z : buf[nj].x; \
            uint32_t b1 = (kk) ? buf[nj].w : buf[nj].y; \
            mma_tf32(acc[mi][nj], aa, b0, b1); \
        } \
    } }

    KV_LDA(aCur, 0);
    KV_LDB(bA, 0);
#pragma unroll 1
    for (int ktp = 0; ktp < 24; ktp += 2) {
        const int kt0 = ktp * 2;
        KV_LDB(bB, ktp + 1);
        KV_LDA(aNxt, kt0 + 1);
        KV_MMA(aCur, bA, 0);
        KV_LDA(aCur, kt0 + 2);
        KV_MMA(aNxt, bA, 1);
        if (ktp + 2 < 24) KV_LDB(bA, ktp + 2);
        KV_LDA(aNxt, kt0 + 3);
        KV_MMA(aCur, bB, 0);
        {
            const int ktn = (kt0 + 4 < 48) ? (kt0 + 4) : 47;
            KV_LDA(aCur, ktn);
        }
        KV_MMA(aNxt, bB, 1);
    }
#undef KV_LDB
#undef KV_LDA
#undef KV_MMA

    // ---------------- epilogue ----------------
#pragma unroll
    for (int mi = 0; mi < 4; mi++) {
        const int r_lo = bm + mi * 16 + gID;
        float* clo = p.C + (size_t)r_lo * 512;
        float* chi = clo + (size_t)8 * 512;
#pragma unroll
        for (int nj = 0; nj < 8; nj++) {
            const int col = wc * 64 + nj * 8 + tg * 2;
            const float b0 = (col < 256) ? __ldg(&p.bk[col]) : __ldg(&p.bv[col - 256]);
            const float b1 = (col + 1 < 256) ? __ldg(&p.bk[col + 1]) : __ldg(&p.bv[col + 1 - 256]);
            *(float2*)(clo + col) = make_float2(acc[mi][nj][0] + b0, acc[mi][nj][1] + b1);
            *(float2*)(chi + col) = make_float2(acc[mi][nj][2] + b0, acc[mi][nj][3] + b1);
        }
    }
}

// ===========================================================================
// tf32 mma.sync GEMM (Q / O / fc1 / fc2): CTA = 128(m) x 128(n).
// ===========================================================================
struct TcParams {
    int Kdim, ldA, ldC;
    const float* W;
    const float* bias;
    float* C;
    int relu;
    const unsigned char* invalid;
    const float *Adense, *nf, *memv, *st;
    const int *idx;
};

template <int MODE>
__global__ void __launch_bounds__(256) mma_gemm(TcParams p) {
    __shared__ uint32_t As[128][36];
    __shared__ uint32_t Bs[128][36];
    const int tid = threadIdx.x;
    const int lane = tid & 31;
    const int wid = tid >> 5;
    const int bm = blockIdx.x * 128;
    const int noff = blockIdx.y * 128;
    const float* W = p.W + (size_t)noff * p.Kdim;
    const float* bias = p.bias + noff;
    const int row = tid >> 1;
    const int seg = tid & 1;
    const int m = bm + row;
    const int wr = (wid >> 1) * 32;
    const int wc = (wid & 1) * 64;
    const int groupID = lane >> 2;
    const int tg = lane & 3;

    float acc[2][8][4];
#pragma unroll
    for (int mi = 0; mi < 2; mi++)
#pragma unroll
        for (int nj = 0; nj < 8; nj++)
#pragma unroll
            for (int q = 0; q < 4; q++) acc[mi][nj][q] = 0.f;

#pragma unroll 1
    for (int k0 = 0; k0 < p.Kdim; k0 += 32) {
        const int kb = k0 + seg * 16;
        {
            const float* s0 = nullptr;
            const float* s1 = nullptr;
            if constexpr (MODE == MODE_PLAIN) {
                s0 = p.Adense + (size_t)m * p.ldA + kb;
            } else if constexpr (MODE == MODE_QGATHER) {
                if (kb < 128) {
                    int nd = __ldg(&p.idx[m]);
                    s0 = p.nf + (size_t)nd * 128 + kb;
                    s1 = p.memv + (size_t)nd * 128 + kb;
                } else {
                    s0 = p.st + (kb - 128);
                }
            } else {  // MODE_CONCAT
                if (kb < 256) {
                    s0 = p.Adense + (size_t)m * 256 + kb;
                } else {
                    int nd = __ldg(&p.idx[m]);
                    s0 = p.nf + (size_t)nd * 128 + (kb - 256);
                    s1 = p.memv + (size_t)nd * 128 + (kb - 256);
                }
            }
#pragma unroll
            for (int i = 0; i < 4; i++) {
                float4 v = *(const float4*)(s0 + i * 4);
                if (s1) {
                    float4 w = *(const float4*)(s1 + i * 4);
                    v.x += w.x; v.y += w.y; v.z += w.z; v.w += w.w;
                }
                *(uint4*)&As[row][seg * 16 + i * 4] = f4tf32(v);
            }
        }
        {
            const float* wsrc = W + (size_t)row * p.Kdim + kb;
#pragma unroll
            for (int i = 0; i < 4; i++)
                *(uint4*)&Bs[row][seg * 16 + i * 4] = f4tf32(*(const float4*)(wsrc + i * 4));
        }
        __syncthreads();
#pragma unroll
        for (int kk = 0; kk < 4; kk++) {
            const int c0 = kk * 8 + tg;
            uint32_t a[2][4];
#pragma unroll
            for (int mi = 0; mi < 2; mi++) {
                int r0 = wr + mi * 16 + groupID;
                a[mi][0] = As[r0][c0];
                a[mi][1] = As[r0 + 8][c0];
                a[mi][2] = As[r0][c0 + 4];
                a[mi][3] = As[r0 + 8][c0 + 4];
            }
#pragma unroll
            for (int nj = 0; nj < 8; nj++) {
                int nb_ = wc + nj * 8 + groupID;
                uint32_t b0 = Bs[nb_][c0];
                uint32_t b1 = Bs[nb_][c0 + 4];
                mma_tf32(acc[0][nj], a[0], b0, b1);
                mma_tf32(acc[1][nj], a[1], b0, b1);
            }
        }
        __syncthreads();
    }

#pragma unroll
    for (int mi = 0; mi < 2; mi++) {
        const int r_lo = bm + wr + mi * 16 + groupID;
        const int r_hi = r_lo + 8;
        const bool z_lo = (p.invalid != nullptr) && p.invalid[r_lo];
        const bool z_hi = (p.invalid != nullptr) && p.invalid[r_hi];
        float* clo = p.C + (size_t)r_lo * p.ldC + noff;
        float* chi = p.C + (size_t)r_hi * p.ldC + noff;
#pragma unroll
        for (int nj = 0; nj < 8; nj++) {
            const int cl = wc + nj * 8 + tg * 2;
            const float b0 = __ldg(&bias[cl]);
            const float b1 = __ldg(&bias[cl + 1]);
            float v00 = acc[mi][nj][0] + b0, v01 = acc[mi][nj][1] + b1;
            float v10 = acc[mi][nj][2] + b0, v11 = acc[mi][nj][3] + b1;
            if (p.relu) {
                v00 = fmaxf(v00, 0.f); v01 = fmaxf(v01, 0.f);
                v10 = fmaxf(v10, 0.f); v11 = fmaxf(v11, 0.f);
            }
            if (z_lo) { v00 = 0.f; v01 = 0.f; }
            if (z_hi) { v10 = 0.f; v11 = 0.f; }
            *(float2*)(clo + cl) = make_float2(v00, v01);
            *(float2*)(chi + cl) = make_float2(v10, v11);
        }
    }
}

__global__ void st_kernel(const float* __restrict__ b) {
    g_st[threadIdx.x] = __cosf(b[threadIdx.x]);
}

// ---------------------------------------------------------------------------
// Temporal attention
// ---------------------------------------------------------------------------
__global__ void attn_kernel(const float* __restrict__ q, const float* __restrict__ kv,
                            const int* __restrict__ nbrs, float* __restrict__ outp,
                            unsigned char* __restrict__ invalid) {
    const int r = blockIdx.x;
    const int tid = threadIdx.x;
    const int warp = tid >> 5;
    const int lane = tid & 31;
    __shared__ float sq[256];
    __shared__ float sc[2][KNB];
    __shared__ float swt[2][KNB];
    __shared__ int smask[KNB];

    if (tid < 256) sq[tid] = q[(size_t)r * 256 + tid];
    if (tid < KNB) smask[tid] = (nbrs[r * KNB + tid] != 0) ? 1 : 0;
    __syncthreads();
    if (tid == 0) {
        int any = 0;
#pragma unroll
        for (int k = 0; k < KNB; k++) any |= smask[k];
        if (!any) smask[KNB - 1] = 1;
        invalid[r] = (unsigned char)(!any);
    }
    __syncthreads();

    if (warp < KNB) {
        const float* kp = kv + ((size_t)r * KNB + warp) * 512;
        float s0 = 0.f, s1 = 0.f;
#pragma unroll
        for (int i = 0; i < 4; i++) {
            int d = lane + 32 * i;
            s0 = fmaf(sq[d], kp[d], s0);
            s1 = fmaf(sq[128 + d], kp[128 + d], s1);
        }
#pragma unroll
        for (int o = 16; o > 0; o >>= 1) {
            s0 += __shfl_down_sync(0xffffffffu, s0, o);
            s1 += __shfl_down_sync(0xffffffffu, s1, o);
        }
        if (lane == 0) {
            const float scale = 0.08838834764831845f;
            sc[0][warp] = smask[warp] ? s0 * scale : -1e9f;
            sc[1][warp] = smask[warp] ? s1 * scale : -1e9f;
        }
    }
    __syncthreads();

    if (tid < 2) {
        float mx = -3.0e38f;
#pragma unroll
        for (int k = 0; k < KNB; k++) mx = fmaxf(mx, sc[tid][k]);
        float sum = 0.f;
#pragma unroll
        for (int k = 0; k < KNB; k++) {
            float e = __expf(sc[tid][k] - mx);
            swt[tid][k] = e;
            sum += e;
        }
        float inv = 1.0f / sum;
#pragma unroll
        for (int k = 0; k < KNB; k++) swt[tid][k] *= inv;
    }
    __syncthreads();

    if (tid < 256) {
        int h = tid >> 7;
        float o = 0.f;
#pragma unroll
        for (int k = 0; k < KNB; k++)
            o = fmaf(swt[h][k], kv[((size_t)r * KNB + k) * 512 + 256 + tid], o);
        outp[(size_t)r * 256 + tid] = o;
    }
}

// ---------------------------------------------------------------------------
// Host side
// ---------------------------------------------------------------------------
static void launch_mma(int mode, int M, int nchunks, const TcParams& p, cudaStream_t s) {
    dim3 grid(M / 128, nchunks);
    switch (mode) {
        case MODE_PLAIN:   mma_gemm<MODE_PLAIN><<<grid, 256, 0, s>>>(p); break;
        case MODE_QGATHER: mma_gemm<MODE_QGATHER><<<grid, 256, 0, s>>>(p); break;
        case MODE_CONCAT:  mma_gemm<MODE_CONCAT><<<grid, 256, 0, s>>>(p); break;
    }
}

extern "C" void kernel_launch(void* const* d_in, const int* in_sizes, int n_in,
                              void* d_out, int out_size) {
    const float* nf   = (const float*)d_in[0];
    const float* mem  = (const float*)d_in[1];
    const float* ef   = (const float*)d_in[2];
    const float* tw   = (const float*)d_in[3];
    const float* tb   = (const float*)d_in[4];
    const float* Wq   = (const float*)d_in[5];
    const float* bq   = (const float*)d_in[6];
    const float* Wk   = (const float*)d_in[7];
    const float* bk   = (const float*)d_in[8];
    const float* Wv   = (const float*)d_in[9];
    const float* bv   = (const float*)d_in[10];
    const float* Wo   = (const float*)d_in[11];
    const float* bo   = (const float*)d_in[12];
    const float* f1w  = (const float*)d_in[13];
    const float* f1b  = (const float*)d_in[14];
    const float* f2w  = (const float*)d_in[15];
    const float* f2b  = (const float*)d_in[16];
    const int*   src  = (const int*)d_in[17];
    const float* ts   = (const float*)d_in[18];
    const int*   nb2  = (const int*)d_in[19];
    const int*   ei2  = (const int*)d_in[20];
    const float* tm2  = (const float*)d_in[21];
    const int*   nb1  = (const int*)d_in[22];
    const int*   ei1  = (const int*)d_in[23];
    const float* tm1  = (const float*)d_in[24];
    float* out = (float*)d_out;

    float *pst, *pkv1, *pq1, *pattn1, *po1, *ph1, *pemb1;
    float *pkv2, *pq2, *pattn2, *po2, *ph2;
    unsigned char *pinv1, *pinv2;
    uint32_t* pbp;
    cudaGetSymbolAddress((void**)&pst, g_st);
    cudaGetSymbolAddress((void**)&pkv1, g_kv1);
    cudaGetSymbolAddress((void**)&pq1, g_q1);
    cudaGetSymbolAddress((void**)&pattn1, g_attn1);
    cudaGetSymbolAddress((void**)&po1, g_o1);
    cudaGetSymbolAddress((void**)&ph1, g_h1);
    cudaGetSymbolAddress((void**)&pemb1, g_emb1);
    cudaGetSymbolAddress((void**)&pinv1, g_inv1);
    cudaGetSymbolAddress((void**)&pkv2, g_kv2);
    cudaGetSymbolAddress((void**)&pq2, g_q2);
    cudaGetSymbolAddress((void**)&pattn2, g_attn2);
    cudaGetSymbolAddress((void**)&po2, g_o2);
    cudaGetSymbolAddress((void**)&ph2, g_h2);
    cudaGetSymbolAddress((void**)&pinv2, g_inv2);
    cudaGetSymbolAddress((void**)&pbp, g_bp);

    static cudaStream_t s_side = nullptr;
    static cudaEvent_t ev_fork = nullptr, ev_join = nullptr;
    if (s_side == nullptr) {
        cudaStreamCreateWithFlags(&s_side, cudaStreamNonBlocking);
        cudaEventCreateWithFlags(&ev_fork, cudaEventDisableTiming);
        cudaEventCreateWithFlags(&ev_join, cudaEventDisableTiming);
        cudaFuncSetAttribute(kv_kernel<0>, cudaFuncAttributeMaxDynamicSharedMemorySize, KV_DSMEM);
        cudaFuncSetAttribute(kv_kernel<1>, cudaFuncAttributeMaxDynamicSharedMemorySize, KV_DSMEM);
    }

    const cudaStream_t s0 = 0;

    st_kernel<<<1, 128, 0, s0>>>(tb);
    prep_b_kernel<<<(2 * 512 * 384 + 255) / 256, 256, 0, s0>>>(Wk, Wv, pbp);

    const float* Wq1 = Wq + 256 * 256;  const float* bq1 = bq + 256;
    const float* bk1 = bk + 256;
    const float* bv1 = bv + 256;
    const float* Wo1 = Wo + 256 * 256;  const float* bo1 = bo + 256;
    const float* f1w1 = f1w + 128 * 384; const float* f1b1 = f1b + 128;
    const float* f2w1 = f2w + 128 * 128; const float* f2b1 = f2b + 128;

    // ---- fork: Q1 + Q2 on side stream, concurrent with KV1 on stream 0 ----
    cudaEventRecord(ev_fork, s0);
    cudaStreamWaitEvent(s_side, ev_fork, 0);
    {   // Q1 (tf32): [20480,256], 2 col chunks
        TcParams p{};
        p.Kdim = 256; p.ldC = 256;
        p.W = Wq; p.bias = bq; p.C = pq1;
        p.nf = nf; p.memv = mem; p.st = pst; p.idx = nb2;
        launch_mma(MODE_QGATHER, N1, 2, p, s_side);
    }
    {   // Q2 (tf32)
        TcParams p{};
        p.Kdim = 256; p.ldC = 256;
        p.W = Wq1; p.bias = bq1; p.C = pq2;
        p.nf = nf; p.memv = mem; p.st = pst; p.idx = src;
        launch_mma(MODE_QGATHER, BB, 2, p, s_side);
    }
    cudaEventRecord(ev_join, s_side);

    {   // KV1 (tf32 v3) on stream 0, overlapped with Q1/Q2
        KvParams p{};
        p.Bp = pbp; p.bk = bk; p.bv = bv; p.C = pkv1;
        p.DIV = 100; p.ts = ts; p.etm = tm1; p.tw = tw; p.tb = tb;
        p.nf = nf; p.memv = mem; p.ef = ef; p.idx = nb1; p.eidx = ei1;
        kv_kernel<0><<<NP1 / 64, 256, KV_DSMEM, s0>>>(p);
    }
    cudaStreamWaitEvent(s0, ev_join, 0);   // join: attn1 needs Q1 (and later Q2)

    attn_kernel<<<N1, 320, 0, s0>>>(pq1, pkv1, nb1, pattn1, pinv1);
    {   // O1 (tf32): 2 chunks, zero invalid rows
        TcParams p{};
        p.Kdim = 256; p.ldA = 256; p.ldC = 256;
        p.W = Wo; p.bias = bo; p.C = po1;
        p.Adense = pattn1; p.invalid = pinv1;
        launch_mma(MODE_PLAIN, N1, 2, p, s0);
    }
    {   // fc1 L0 (tf32): relu
        TcParams p{};
        p.Kdim = 384; p.ldC = 128;
        p.W = f1w; p.bias = f1b; p.C = ph1;
        p.Adense = po1; p.nf = nf; p.memv = mem; p.idx = nb2; p.relu = 1;
        launch_mma(MODE_CONCAT, N1, 1, p, s0);
    }
    {   // fc2 L0 (tf32) -> emb1
        TcParams p{};
        p.Kdim = 128; p.ldA = 128; p.ldC = 128;
        p.W = f2w; p.bias = f2b; p.C = pemb1; p.Adense = ph1;
        launch_mma(MODE_PLAIN, N1, 1, p, s0);
    }
    {   // KV2 (tf32 v3, dense)
        KvParams p{};
        p.Bp = pbp + 512 * 384; p.bk = bk1; p.bv = bv1; p.C = pkv2;
        p.DIV = 10; p.ts = ts; p.etm = tm2; p.tw = tw; p.tb = tb;
        p.Adense = pemb1; p.ef = ef; p.eidx = ei2;
        kv_kernel<1><<<NP2 / 64, 256, KV_DSMEM, s0>>>(p);
    }
    attn_kernel<<<BB, 320, 0, s0>>>(pq2, pkv2, nb2, pattn2, pinv2);
    {   // O2 (tf32)
        TcParams p{};
        p.Kdim = 256; p.ldA = 256; p.ldC = 256;
        p.W = Wo1; p.bias = bo1; p.C = po2;
        p.Adense = pattn2; p.invalid = pinv2;
        launch_mma(MODE_PLAIN, BB, 2, p, s0);
    }
    {   // fc1 L1 (tf32)
        TcParams p{};
        p.Kdim = 384; p.ldC = 128;
        p.W = f1w1; p.bias = f1b1; p.C = ph2;
        p.Adense = po2; p.nf = nf; p.memv = mem; p.idx = src; p.relu = 1;
        launch_mma(MODE_CONCAT, BB, 1, p, s0);
    }
    {   // fc2 L1 (tf32) -> out
        TcParams p{};
        p.Kdim = 128; p.ldA = 128; p.ldC = 128;
        p.W = f2w1; p.bias = f2b1; p.C = out; p.Adense = ph2;
        launch_mma(MODE_PLAIN, BB, 1, p, s0);
    }
}

// round 7
// speedup vs baseline: 5.1734x; 1.0520x over previous
#include <cuda_runtime.h>
#include <cuda_fp16.h>
#include <cstdint>

// ---------------------------------------------------------------------------
// Problem constants
// ---------------------------------------------------------------------------
#define KNB 10
#define BB  2048
#define N1  20480
#define NP1 204800
#define NP2 20480
// D = T = 128, QD = 256, KD = 384, H = 2, hd = 128

// ---------------------------------------------------------------------------
// Scratch
// ---------------------------------------------------------------------------
__device__ float g_st[128];
__device__ __half g_kv1[(size_t)NP1 * 512];
__device__ float g_q1 [(size_t)N1  * 256];
__device__ float g_attn1[(size_t)N1 * 256];
__device__ float g_o1 [(size_t)N1  * 256];
__device__ float g_h1 [(size_t)N1  * 128];
__device__ float g_emb1[(size_t)N1 * 128];
__device__ unsigned char g_inv1[N1];
__device__ __half g_kv2[(size_t)NP2 * 512];
__device__ float g_q2 [(size_t)BB  * 256];
__device__ float g_attn2[(size_t)BB * 256];
__device__ float g_o2 [(size_t)BB  * 256];
__device__ float g_h2 [(size_t)BB  * 128];
__device__ unsigned char g_inv2[BB];
// pre-permuted fragment-ordered tf32 weights for KV (2 layers x 512 n x 384 k)
__device__ uint32_t g_bp[2 * 512 * 384];

#define MODE_PLAIN      0
#define MODE_QGATHER    1
#define MODE_CONCAT     4

// ---------------------------------------------------------------------------
// tf32 helpers
// ---------------------------------------------------------------------------
__device__ __forceinline__ uint32_t f2tf32(float f) {
    uint32_t r;
    asm("cvt.rna.tf32.f32 %0, %1;" : "=r"(r) : "f"(f));
    return r;
}
__device__ __forceinline__ uint4 f4tf32(float4 v) {
    uint4 r;
    r.x = f2tf32(v.x); r.y = f2tf32(v.y); r.z = f2tf32(v.z); r.w = f2tf32(v.w);
    return r;
}
__device__ __forceinline__ void mma_tf32(float* c, const uint32_t* a, uint32_t b0, uint32_t b1) {
    asm volatile(
        "mma.sync.aligned.m16n8k8.row.col.f32.tf32.tf32.f32 "
        "{%0,%1,%2,%3}, {%4,%5,%6,%7}, {%8,%9}, {%0,%1,%2,%3};"
        : "+f"(c[0]), "+f"(c[1]), "+f"(c[2]), "+f"(c[3])
        : "r"(a[0]), "r"(a[1]), "r"(a[2]), "r"(a[3]), "r"(b0), "r"(b1));
}

// ===========================================================================
// B pre-permutation: Wk||Wv [512 n][384 k] fp32 -> fragment-ordered tf32.
// ===========================================================================
__global__ void prep_b_kernel(const float* __restrict__ Wk, const float* __restrict__ Wv,
                              uint32_t* __restrict__ dst) {
    int idx = blockIdx.x * blockDim.x + threadIdx.x;   // 2 * 512 * 384
    if (idx >= 2 * 512 * 384) return;
    int l = idx / (512 * 384);
    int rem = idx - l * (512 * 384);
    int n = rem / 384;
    int k = rem - n * 384;
    const float* W = (n < 256) ? (Wk + (size_t)l * 256 * 384 + (size_t)n * 384)
                               : (Wv + (size_t)l * 256 * 384 + (size_t)(n - 256) * 384);
    float v = W[k];
    int nt = n >> 3, gid = n & 7;
    int ktp = k >> 4, klo = k & 15;
    int kk = klo >> 3, remk = klo & 7, hi = remk >> 2, tg = remk & 3;
    int r = kk * 2 + hi;
    int lane = gid * 4 + tg;
    dst[(size_t)l * (512 * 384) + (((size_t)nt * 24 + ktp) * 32 + lane) * 4 + r] = f2tf32(v);
}

// ===========================================================================
// KV projection kernel v4 (tf32 mma.sync, fragment-permuted operands).
// CTA = 64 rows x 512 cols, 512 threads (16 warps); warp w: ALL 64 rows x
// cols [w*32, w*32+32)  (mi=4, nj=4, acc=64 regs -> no spills, 4 warps/SMSP).
// A gathered once into fragment-permuted smem (LDS.128 per frag);
// B (pre-permuted, L2-resident, unique per warp) double-buffered in regs.
// Output written fp16. No __syncthreads in the main loop.
// ===========================================================================
struct KvParams {
    const uint32_t* Bp;
    const float *bk, *bv;
    __half* C;                         // [M, 512] fp16
    int DIV;
    const float *ts, *etm, *tw, *tb;
    const float *Adense, *nf, *memv, *ef;
    const int *idx, *eidx;
};

#define KV_DSMEM (98304 + 256)

__device__ __forceinline__ void kv_stash(uint32_t* As, int m, int k, uint32_t val) {
    int kt = k >> 3, mi = m >> 4;
    int r16 = m & 15, gid = r16 & 7, hi_r = r16 >> 3;
    int tg = k & 3, hi_k = (k >> 2) & 1;
    As[(((kt * 4 + mi) * 32) + gid * 4 + tg) * 4 + hi_r + 2 * hi_k] = val;
}
__device__ __forceinline__ void kv_stash4(uint32_t* As, int m, int c0, uint4 v) {
    kv_stash(As, m, c0 + 0, v.x);
    kv_stash(As, m, c0 + 1, v.y);
    kv_stash(As, m, c0 + 2, v.z);
    kv_stash(As, m, c0 + 3, v.w);
}

template <int DENSE>
__global__ void __launch_bounds__(512, 1) kv_kernel(KvParams p) {
    extern __shared__ char smem[];
    uint32_t* As = (uint32_t*)smem;                 // 24576 uint32 = 98304 B
    float* dts = (float*)(smem + 98304);            // 64 floats

    const int tid = threadIdx.x;
    const int lane = tid & 31;
    const int wid = tid >> 5;          // warp = 32-col group (0..15)
    const int bm = blockIdx.x * 64;
    const int gID = lane >> 2;
    const int tg = lane & 3;

    // ---------------- gather A into permuted smem (512 threads) ----------------
    {
        const int grow = tid >> 3;    // 0..63
        const int gseg = tid & 7;     // 0..7
        const int m = bm + grow;
        if (tid < 64) {
            int mm = bm + tid;
            dts[tid] = __ldg(&p.ts[mm / p.DIV]) - __ldg(&p.etm[mm]);
        }
        if (DENSE) {
            const float4* s = (const float4*)(p.Adense + (size_t)m * 128);
#pragma unroll
            for (int i = 0; i < 4; i++) {
                int cf = gseg + 8 * i;
                kv_stash4(As, grow, cf * 4, f4tf32(s[cf]));
            }
        } else {
            int nd = __ldg(&p.idx[m]);
            const float4* s0 = (const float4*)(p.nf + (size_t)nd * 128);
            const float4* s1 = (const float4*)(p.memv + (size_t)nd * 128);
#pragma unroll
            for (int i = 0; i < 4; i++) {
                int cf = gseg + 8 * i;
                float4 x = s0[cf], y = s1[cf];
                kv_stash4(As, grow, cf * 4,
                          f4tf32(make_float4(x.x + y.x, x.y + y.y, x.z + y.z, x.w + y.w)));
            }
        }
        {
            int e = __ldg(&p.eidx[m]);
            const float4* s = (const float4*)(p.ef + (size_t)e * 128);
#pragma unroll
            for (int i = 0; i < 4; i++) {
                int cf = gseg + 8 * i;
                kv_stash4(As, grow, 128 + cf * 4, f4tf32(s[cf]));
            }
        }
        __syncthreads();   // dts ready
        {
            float dt = dts[grow];
#pragma unroll
            for (int i = 0; i < 4; i++) {
                int j0 = (gseg + 8 * i) * 4;
                float4 v;
                v.x = __cosf(fmaf(dt, __ldg(&p.tw[j0 + 0]), __ldg(&p.tb[j0 + 0])));
                v.y = __cosf(fmaf(dt, __ldg(&p.tw[j0 + 1]), __ldg(&p.tb[j0 + 1])));
                v.z = __cosf(fmaf(dt, __ldg(&p.tw[j0 + 2]), __ldg(&p.tb[j0 + 2])));
                v.w = __cosf(fmaf(dt, __ldg(&p.tw[j0 + 3]), __ldg(&p.tb[j0 + 3])));
                kv_stash4(As, grow, 256 + j0, f4tf32(v));
            }
        }
    }
    __syncthreads();   // A fully staged; main loop is sync-free

    // ---------------- main loop ----------------
    const uint4* As4 = (const uint4*)As;
    const char* bpw = (const char*)p.Bp + ((size_t)wid * 4) * 24 * 512;

    float acc[4][4][4];
#pragma unroll
    for (int mi = 0; mi < 4; mi++)
#pragma unroll
        for (int nj = 0; nj < 4; nj++)
#pragma unroll
            for (int q = 0; q < 4; q++) acc[mi][nj][q] = 0.f;

    uint4 bA[4], bB[4];

#define KV_LDB(buf, ktp_) { \
    _Pragma("unroll") \
    for (int nj = 0; nj < 4; nj++) \
        buf[nj] = *(const uint4*)(bpw + (size_t)nj * (24 * 512) + (ktp_) * 512 + lane * 16); }

#define KV_STEP(buf, ktp_) { \
    _Pragma("unroll") \
    for (int kk = 0; kk < 2; kk++) { \
        const int kt = (ktp_) * 2 + kk; \
        _Pragma("unroll") \
        for (int mi = 0; mi < 4; mi++) { \
            uint4 av = As4[(kt * 4 + mi) * 32 + lane]; \
            uint32_t aa[4] = {av.x, av.y, av.z, av.w}; \
            _Pragma("unroll") \
            for (int nj = 0; nj < 4; nj++) { \
                uint32_t b0 = kk ? buf[nj].z : buf[nj].x; \
                uint32_t b1 = kk ? buf[nj].w : buf[nj].y; \
                mma_tf32(acc[mi][nj], aa, b0, b1); \
            } \
        } \
    } }

    KV_LDB(bA, 0);
#pragma unroll 1
    for (int ktp = 0; ktp < 24; ktp += 2) {
        KV_LDB(bB, ktp + 1);
        KV_STEP(bA, ktp);
        if (ktp + 2 < 24) KV_LDB(bA, ktp + 2);
        KV_STEP(bB, ktp + 1);
    }
#undef KV_LDB
#undef KV_STEP

    // ---------------- epilogue (fp16) ----------------
#pragma unroll
    for (int mi = 0; mi < 4; mi++) {
        const int r_lo = bm + mi * 16 + gID;
        __half* clo = p.C + (size_t)r_lo * 512;
        __half* chi = clo + (size_t)8 * 512;
#pragma unroll
        for (int nj = 0; nj < 4; nj++) {
            const int col = wid * 32 + nj * 8 + tg * 2;
            const float b0 = (col < 256) ? __ldg(&p.bk[col]) : __ldg(&p.bv[col - 256]);
            const float b1 = (col + 1 < 256) ? __ldg(&p.bk[col + 1]) : __ldg(&p.bv[col + 1 - 256]);
            __half2 lo = __floats2half2_rn(acc[mi][nj][0] + b0, acc[mi][nj][1] + b1);
            __half2 hi = __floats2half2_rn(acc[mi][nj][2] + b0, acc[mi][nj][3] + b1);
            *(__half2*)(clo + col) = lo;
            *(__half2*)(chi + col) = hi;
        }
    }
}

// ===========================================================================
// tf32 mma.sync GEMM (Q / O / fc1 / fc2): CTA = 128(m) x 128(n).
// ===========================================================================
struct TcParams {
    int Kdim, ldA, ldC;
    const float* W;
    const float* bias;
    float* C;
    int relu;
    const unsigned char* invalid;
    const float *Adense, *nf, *memv, *st;
    const int *idx;
};

template <int MODE>
__global__ void __launch_bounds__(256) mma_gemm(TcParams p) {
    __shared__ uint32_t As[128][36];
    __shared__ uint32_t Bs[128][36];
    const int tid = threadIdx.x;
    const int lane = tid & 31;
    const int wid = tid >> 5;
    const int bm = blockIdx.x * 128;
    const int noff = blockIdx.y * 128;
    const float* W = p.W + (size_t)noff * p.Kdim;
    const float* bias = p.bias + noff;
    const int row = tid >> 1;
    const int seg = tid & 1;
    const int m = bm + row;
    const int wr = (wid >> 1) * 32;
    const int wc = (wid & 1) * 64;
    const int groupID = lane >> 2;
    const int tg = lane & 3;

    float acc[2][8][4];
#pragma unroll
    for (int mi = 0; mi < 2; mi++)
#pragma unroll
        for (int nj = 0; nj < 8; nj++)
#pragma unroll
            for (int q = 0; q < 4; q++) acc[mi][nj][q] = 0.f;

#pragma unroll 1
    for (int k0 = 0; k0 < p.Kdim; k0 += 32) {
        const int kb = k0 + seg * 16;
        {
            const float* s0 = nullptr;
            const float* s1 = nullptr;
            if constexpr (MODE == MODE_PLAIN) {
                s0 = p.Adense + (size_t)m * p.ldA + kb;
            } else if constexpr (MODE == MODE_QGATHER) {
                if (kb < 128) {
                    int nd = __ldg(&p.idx[m]);
                    s0 = p.nf + (size_t)nd * 128 + kb;
                    s1 = p.memv + (size_t)nd * 128 + kb;
                } else {
                    s0 = p.st + (kb - 128);
                }
            } else {  // MODE_CONCAT
                if (kb < 256) {
                    s0 = p.Adense + (size_t)m * 256 + kb;
                } else {
                    int nd = __ldg(&p.idx[m]);
                    s0 = p.nf + (size_t)nd * 128 + (kb - 256);
                    s1 = p.memv + (size_t)nd * 128 + (kb - 256);
                }
            }
#pragma unroll
            for (int i = 0; i < 4; i++) {
                float4 v = *(const float4*)(s0 + i * 4);
                if (s1) {
                    float4 w = *(const float4*)(s1 + i * 4);
                    v.x += w.x; v.y += w.y; v.z += w.z; v.w += w.w;
                }
                *(uint4*)&As[row][seg * 16 + i * 4] = f4tf32(v);
            }
        }
        {
            const float* wsrc = W + (size_t)row * p.Kdim + kb;
#pragma unroll
            for (int i = 0; i < 4; i++)
                *(uint4*)&Bs[row][seg * 16 + i * 4] = f4tf32(*(const float4*)(wsrc + i * 4));
        }
        __syncthreads();
#pragma unroll
        for (int kk = 0; kk < 4; kk++) {
            const int c0 = kk * 8 + tg;
            uint32_t a[2][4];
#pragma unroll
            for (int mi = 0; mi < 2; mi++) {
                int r0 = wr + mi * 16 + groupID;
                a[mi][0] = As[r0][c0];
                a[mi][1] = As[r0 + 8][c0];
                a[mi][2] = As[r0][c0 + 4];
                a[mi][3] = As[r0 + 8][c0 + 4];
            }
#pragma unroll
            for (int nj = 0; nj < 8; nj++) {
                int nb_ = wc + nj * 8 + groupID;
                uint32_t b0 = Bs[nb_][c0];
                uint32_t b1 = Bs[nb_][c0 + 4];
                mma_tf32(acc[0][nj], a[0], b0, b1);
                mma_tf32(acc[1][nj], a[1], b0, b1);
            }
        }
        __syncthreads();
    }

#pragma unroll
    for (int mi = 0; mi < 2; mi++) {
        const int r_lo = bm + wr + mi * 16 + groupID;
        const int r_hi = r_lo + 8;
        const bool z_lo = (p.invalid != nullptr) && p.invalid[r_lo];
        const bool z_hi = (p.invalid != nullptr) && p.invalid[r_hi];
        float* clo = p.C + (size_t)r_lo * p.ldC + noff;
        float* chi = p.C + (size_t)r_hi * p.ldC + noff;
#pragma unroll
        for (int nj = 0; nj < 8; nj++) {
            const int cl = wc + nj * 8 + tg * 2;
            const float b0 = __ldg(&bias[cl]);
            const float b1 = __ldg(&bias[cl + 1]);
            float v00 = acc[mi][nj][0] + b0, v01 = acc[mi][nj][1] + b1;
            float v10 = acc[mi][nj][2] + b0, v11 = acc[mi][nj][3] + b1;
            if (p.relu) {
                v00 = fmaxf(v00, 0.f); v01 = fmaxf(v01, 0.f);
                v10 = fmaxf(v10, 0.f); v11 = fmaxf(v11, 0.f);
            }
            if (z_lo) { v00 = 0.f; v01 = 0.f; }
            if (z_hi) { v10 = 0.f; v11 = 0.f; }
            *(float2*)(clo + cl) = make_float2(v00, v01);
            *(float2*)(chi + cl) = make_float2(v10, v11);
        }
    }
}

__global__ void st_kernel(const float* __restrict__ b) {
    g_st[threadIdx.x] = __cosf(b[threadIdx.x]);
}

// ---------------------------------------------------------------------------
// Temporal attention (kv in fp16)
// ---------------------------------------------------------------------------
__global__ void attn_kernel(const float* __restrict__ q, const __half* __restrict__ kv,
                            const int* __restrict__ nbrs, float* __restrict__ outp,
                            unsigned char* __restrict__ invalid) {
    const int r = blockIdx.x;
    const int tid = threadIdx.x;
    const int warp = tid >> 5;
    const int lane = tid & 31;
    __shared__ float sq[256];
    __shared__ float sc[2][KNB];
    __shared__ float swt[2][KNB];
    __shared__ int smask[KNB];

    if (tid < 256) sq[tid] = q[(size_t)r * 256 + tid];
    if (tid < KNB) smask[tid] = (nbrs[r * KNB + tid] != 0) ? 1 : 0;
    __syncthreads();
    if (tid == 0) {
        int any = 0;
#pragma unroll
        for (int k = 0; k < KNB; k++) any |= smask[k];
        if (!any) smask[KNB - 1] = 1;
        invalid[r] = (unsigned char)(!any);
    }
    __syncthreads();

    if (warp < KNB) {
        const __half* kp = kv + ((size_t)r * KNB + warp) * 512;
        float s0 = 0.f, s1 = 0.f;
#pragma unroll
        for (int i = 0; i < 4; i++) {
            int d = lane + 32 * i;
            s0 = fmaf(sq[d], __half2float(__ldg(&kp[d])), s0);
            s1 = fmaf(sq[128 + d], __half2float(__ldg(&kp[128 + d])), s1);
        }
#pragma unroll
        for (int o = 16; o > 0; o >>= 1) {
            s0 += __shfl_down_sync(0xffffffffu, s0, o);
            s1 += __shfl_down_sync(0xffffffffu, s1, o);
        }
        if (lane == 0) {
            const float scale = 0.08838834764831845f;
            sc[0][warp] = smask[warp] ? s0 * scale : -1e9f;
            sc[1][warp] = smask[warp] ? s1 * scale : -1e9f;
        }
    }
    __syncthreads();

    if (tid < 2) {
        float mx = -3.0e38f;
#pragma unroll
        for (int k = 0; k < KNB; k++) mx = fmaxf(mx, sc[tid][k]);
        float sum = 0.f;
#pragma unroll
        for (int k = 0; k < KNB; k++) {
            float e = __expf(sc[tid][k] - mx);
            swt[tid][k] = e;
            sum += e;
        }
        float inv = 1.0f / sum;
#pragma unroll
        for (int k = 0; k < KNB; k++) swt[tid][k] *= inv;
    }
    __syncthreads();

    if (tid < 256) {
        int h = tid >> 7;
        float o = 0.f;
#pragma unroll
        for (int k = 0; k < KNB; k++)
            o = fmaf(swt[h][k], __half2float(__ldg(&kv[((size_t)r * KNB + k) * 512 + 256 + tid])), o);
        outp[(size_t)r * 256 + tid] = o;
    }
}

// ---------------------------------------------------------------------------
// Host side
// ---------------------------------------------------------------------------
static void launch_mma(int mode, int M, int nchunks, const TcParams& p, cudaStream_t s) {
    dim3 grid(M / 128, nchunks);
    switch (mode) {
        case MODE_PLAIN:   mma_gemm<MODE_PLAIN><<<grid, 256, 0, s>>>(p); break;
        case MODE_QGATHER: mma_gemm<MODE_QGATHER><<<grid, 256, 0, s>>>(p); break;
        case MODE_CONCAT:  mma_gemm<MODE_CONCAT><<<grid, 256, 0, s>>>(p); break;
    }
}

extern "C" void kernel_launch(void* const* d_in, const int* in_sizes, int n_in,
                              void* d_out, int out_size) {
    const float* nf   = (const float*)d_in[0];
    const float* mem  = (const float*)d_in[1];
    const float* ef   = (const float*)d_in[2];
    const float* tw   = (const float*)d_in[3];
    const float* tb   = (const float*)d_in[4];
    const float* Wq   = (const float*)d_in[5];
    const float* bq   = (const float*)d_in[6];
    const float* Wk   = (const float*)d_in[7];
    const float* bk   = (const float*)d_in[8];
    const float* Wv   = (const float*)d_in[9];
    const float* bv   = (const float*)d_in[10];
    const float* Wo   = (const float*)d_in[11];
    const float* bo   = (const float*)d_in[12];
    const float* f1w  = (const float*)d_in[13];
    const float* f1b  = (const float*)d_in[14];
    const float* f2w  = (const float*)d_in[15];
    const float* f2b  = (const float*)d_in[16];
    const int*   src  = (const int*)d_in[17];
    const float* ts   = (const float*)d_in[18];
    const int*   nb2  = (const int*)d_in[19];
    const int*   ei2  = (const int*)d_in[20];
    const float* tm2  = (const float*)d_in[21];
    const int*   nb1  = (const int*)d_in[22];
    const int*   ei1  = (const int*)d_in[23];
    const float* tm1  = (const float*)d_in[24];
    float* out = (float*)d_out;

    float *pst, *pq1, *pattn1, *po1, *ph1, *pemb1;
    float *pq2, *pattn2, *po2, *ph2;
    __half *pkv1, *pkv2;
    unsigned char *pinv1, *pinv2;
    uint32_t* pbp;
    cudaGetSymbolAddress((void**)&pst, g_st);
    cudaGetSymbolAddress((void**)&pkv1, g_kv1);
    cudaGetSymbolAddress((void**)&pq1, g_q1);
    cudaGetSymbolAddress((void**)&pattn1, g_attn1);
    cudaGetSymbolAddress((void**)&po1, g_o1);
    cudaGetSymbolAddress((void**)&ph1, g_h1);
    cudaGetSymbolAddress((void**)&pemb1, g_emb1);
    cudaGetSymbolAddress((void**)&pinv1, g_inv1);
    cudaGetSymbolAddress((void**)&pkv2, g_kv2);
    cudaGetSymbolAddress((void**)&pq2, g_q2);
    cudaGetSymbolAddress((void**)&pattn2, g_attn2);
    cudaGetSymbolAddress((void**)&po2, g_o2);
    cudaGetSymbolAddress((void**)&ph2, g_h2);
    cudaGetSymbolAddress((void**)&pinv2, g_inv2);
    cudaGetSymbolAddress((void**)&pbp, g_bp);

    static cudaStream_t s_side = nullptr;
    static cudaEvent_t ev_fork = nullptr, ev_join = nullptr;
    if (s_side == nullptr) {
        cudaStreamCreateWithFlags(&s_side, cudaStreamNonBlocking);
        cudaEventCreateWithFlags(&ev_fork, cudaEventDisableTiming);
        cudaEventCreateWithFlags(&ev_join, cudaEventDisableTiming);
        cudaFuncSetAttribute(kv_kernel<0>, cudaFuncAttributeMaxDynamicSharedMemorySize, KV_DSMEM);
        cudaFuncSetAttribute(kv_kernel<1>, cudaFuncAttributeMaxDynamicSharedMemorySize, KV_DSMEM);
    }

    const cudaStream_t s0 = 0;

    st_kernel<<<1, 128, 0, s0>>>(tb);
    prep_b_kernel<<<(2 * 512 * 384 + 255) / 256, 256, 0, s0>>>(Wk, Wv, pbp);

    const float* Wq1 = Wq + 256 * 256;  const float* bq1 = bq + 256;
    const float* bk1 = bk + 256;
    const float* bv1 = bv + 256;
    const float* Wo1 = Wo + 256 * 256;  const float* bo1 = bo + 256;
    const float* f1w1 = f1w + 128 * 384; const float* f1b1 = f1b + 128;
    const float* f2w1 = f2w + 128 * 128; const float* f2b1 = f2b + 128;

    // ---- fork: Q1 + Q2 on side stream, concurrent with KV1 on stream 0 ----
    cudaEventRecord(ev_fork, s0);
    cudaStreamWaitEvent(s_side, ev_fork, 0);
    {   // Q1 (tf32): [20480,256], 2 col chunks
        TcParams p{};
        p.Kdim = 256; p.ldC = 256;
        p.W = Wq; p.bias = bq; p.C = pq1;
        p.nf = nf; p.memv = mem; p.st = pst; p.idx = nb2;
        launch_mma(MODE_QGATHER, N1, 2, p, s_side);
    }
    {   // Q2 (tf32)
        TcParams p{};
        p.Kdim = 256; p.ldC = 256;
        p.W = Wq1; p.bias = bq1; p.C = pq2;
        p.nf = nf; p.memv = mem; p.st = pst; p.idx = src;
        launch_mma(MODE_QGATHER, BB, 2, p, s_side);
    }
    cudaEventRecord(ev_join, s_side);

    {   // KV1 (tf32 v4) on stream 0, overlapped with Q1/Q2
        KvParams p{};
        p.Bp = pbp; p.bk = bk; p.bv = bv; p.C = pkv1;
        p.DIV = 100; p.ts = ts; p.etm = tm1; p.tw = tw; p.tb = tb;
        p.nf = nf; p.memv = mem; p.ef = ef; p.idx = nb1; p.eidx = ei1;
        kv_kernel<0><<<NP1 / 64, 512, KV_DSMEM, s0>>>(p);
    }
    cudaStreamWaitEvent(s0, ev_join, 0);

    attn_kernel<<<N1, 320, 0, s0>>>(pq1, pkv1, nb1, pattn1, pinv1);
    {   // O1 (tf32): 2 chunks, zero invalid rows
        TcParams p{};
        p.Kdim = 256; p.ldA = 256; p.ldC = 256;
        p.W = Wo; p.bias = bo; p.C = po1;
        p.Adense = pattn1; p.invalid = pinv1;
        launch_mma(MODE_PLAIN, N1, 2, p, s0);
    }
    {   // fc1 L0 (tf32): relu
        TcParams p{};
        p.Kdim = 384; p.ldC = 128;
        p.W = f1w; p.bias = f1b; p.C = ph1;
        p.Adense = po1; p.nf = nf; p.memv = mem; p.idx = nb2; p.relu = 1;
        launch_mma(MODE_CONCAT, N1, 1, p, s0);
    }
    {   // fc2 L0 (tf32) -> emb1
        TcParams p{};
        p.Kdim = 128; p.ldA = 128; p.ldC = 128;
        p.W = f2w; p.bias = f2b; p.C = pemb1; p.Adense = ph1;
        launch_mma(MODE_PLAIN, N1, 1, p, s0);
    }
    {   // KV2 (tf32 v4, dense)
        KvParams p{};
        p.Bp = pbp + 512 * 384; p.bk = bk1; p.bv = bv1; p.C = pkv2;
        p.DIV = 10; p.ts = ts; p.etm = tm2; p.tw = tw; p.tb = tb;
        p.Adense = pemb1; p.ef = ef; p.eidx = ei2;
        kv_kernel<1><<<NP2 / 64, 512, KV_DSMEM, s0>>>(p);
    }
    attn_kernel<<<BB, 320, 0, s0>>>(pq2, pkv2, nb2, pattn2, pinv2);
    {   // O2 (tf32)
        TcParams p{};
        p.Kdim = 256; p.ldA = 256; p.ldC = 256;
        p.W = Wo1; p.bias = bo1; p.C = po2;
        p.Adense = pattn2; p.invalid = pinv2;
        launch_mma(MODE_PLAIN, BB, 2, p, s0);
    }
    {   // fc1 L1 (tf32)
        TcParams p{};
        p.Kdim = 384; p.ldC = 128;
        p.W = f1w1; p.bias = f1b1; p.C = ph2;
        p.Adense = po2; p.nf = nf; p.memv = mem; p.idx = src; p.relu = 1;
        launch_mma(MODE_CONCAT, BB, 1, p, s0);
    }
    {   // fc2 L1 (tf32) -> out
        TcParams p{};
        p.Kdim = 128; p.ldA = 128; p.ldC = 128;
        p.W = f2w1; p.bias = f2b1; p.C = out; p.Adense = ph2;
        launch_mma(MODE_PLAIN, BB, 1, p, s0);
    }
}

// round 8
// speedup vs baseline: 6.2421x; 1.2066x over previous
#include <cuda_runtime.h>
#include <cuda_fp16.h>
#include <cstdint>

// ---------------------------------------------------------------------------
// Problem constants
// ---------------------------------------------------------------------------
#define KNB 10
#define BB  2048
#define N1  20480
#define NP1 204800
#define NP2 20480
// D = T = 128, QD = 256, KD = 384, H = 2, hd = 128

// ---------------------------------------------------------------------------
// Scratch
// ---------------------------------------------------------------------------
__device__ float g_st[128];
__device__ __half g_kv1[(size_t)NP1 * 512];
__device__ float g_q1 [(size_t)N1  * 256];
__device__ float g_attn1[(size_t)N1 * 256];
__device__ float g_o1 [(size_t)N1  * 256];
__device__ float g_h1 [(size_t)N1  * 128];
__device__ float g_emb1[(size_t)N1 * 128];
__device__ unsigned char g_inv1[N1];
__device__ __half g_kv2[(size_t)NP2 * 512];
__device__ float g_q2 [(size_t)BB  * 256];
__device__ float g_attn2[(size_t)BB * 256];
__device__ float g_o2 [(size_t)BB  * 256];
__device__ float g_h2 [(size_t)BB  * 128];
__device__ unsigned char g_inv2[BB];
// pre-permuted fragment-ordered fp16 weights for KV (2 layers x 512 n x 384 k)
__device__ __half g_bph[2 * 512 * 384];

#define MODE_PLAIN      0
#define MODE_QGATHER    1
#define MODE_CONCAT     4

// ---------------------------------------------------------------------------
// tf32 helpers (mma_gemm for Q/O/fc kernels)
// ---------------------------------------------------------------------------
__device__ __forceinline__ uint32_t f2tf32(float f) {
    uint32_t r;
    asm("cvt.rna.tf32.f32 %0, %1;" : "=r"(r) : "f"(f));
    return r;
}
__device__ __forceinline__ uint4 f4tf32(float4 v) {
    uint4 r;
    r.x = f2tf32(v.x); r.y = f2tf32(v.y); r.z = f2tf32(v.z); r.w = f2tf32(v.w);
    return r;
}
__device__ __forceinline__ void mma_tf32(float* c, const uint32_t* a, uint32_t b0, uint32_t b1) {
    asm volatile(
        "mma.sync.aligned.m16n8k8.row.col.f32.tf32.tf32.f32 "
        "{%0,%1,%2,%3}, {%4,%5,%6,%7}, {%8,%9}, {%0,%1,%2,%3};"
        : "+f"(c[0]), "+f"(c[1]), "+f"(c[2]), "+f"(c[3])
        : "r"(a[0]), "r"(a[1]), "r"(a[2]), "r"(a[3]), "r"(b0), "r"(b1));
}
__device__ __forceinline__ void mma_f16(float* c, const uint32_t* a, uint32_t b0, uint32_t b1) {
    asm volatile(
        "mma.sync.aligned.m16n8k16.row.col.f32.f16.f16.f32 "
        "{%0,%1,%2,%3}, {%4,%5,%6,%7}, {%8,%9}, {%0,%1,%2,%3};"
        : "+f"(c[0]), "+f"(c[1]), "+f"(c[2]), "+f"(c[3])
        : "r"(a[0]), "r"(a[1]), "r"(a[2]), "r"(a[3]), "r"(b0), "r"(b1));
}

// ===========================================================================
// B pre-permutation: Wk||Wv [512 n][384 k] fp32 -> fragment-ordered fp16
// for m16n8k16. Tile = (nt: 8 n) x (ktp: 32 k = 2 k16 sub-tiles). Per lane:
// uint4 = [kt0.b0, kt0.b1, kt1.b0, kt1.b1] (each uint32 = half2 k-pair).
// ===========================================================================
__global__ void prep_b_kernel(const float* __restrict__ Wk, const float* __restrict__ Wv,
                              __half* __restrict__ dst) {
    int idx = blockIdx.x * blockDim.x + threadIdx.x;   // 2 * 512 * 384
    if (idx >= 2 * 512 * 384) return;
    int l = idx / (512 * 384);
    int rem = idx - l * (512 * 384);
    int n = rem / 384;
    int k = rem - n * 384;
    const float* W = (n < 256) ? (Wk + (size_t)l * 256 * 384 + (size_t)n * 384)
                               : (Wv + (size_t)l * 256 * 384 + (size_t)(n - 256) * 384);
    float v = W[k];
    int nt = n >> 3, gid = n & 7;
    int ktp = k >> 5, k32 = k & 31;
    int kt_in = k32 >> 4, klo = k32 & 15;
    int tg = (klo & 7) >> 1, reg = klo >> 3, par = k & 1;
    int lane = gid * 4 + tg;
    size_t off = ((((size_t)l * 64 + nt) * 12 + ktp) * 32 + lane) * 8 + (kt_in * 2 + reg) * 2 + par;
    dst[off] = __float2half_rn(v);
}

// ===========================================================================
// KV projection kernel v5: fp16 mma.sync m16n8k16, persistent CTAs with
// cp.async block pipeline.
// CTA = 64 rows x 512 cols, 512 threads (16 warps, warp = 64 rows x 32 cols).
// Per block: raw gather data (64 x 384 f32) prefetched via cp.async during
// the PREVIOUS block's MMA main loop; convert phase builds fragment-permuted
// fp16 A in smem (48KB) incl. fused time encoding; main loop is sync-free.
// ===========================================================================
struct KvParams {
    const __half* Bp;
    const float *bk, *bv;
    __half* C;                         // [M, 512] fp16
    int DIV, nblk;
    const float *ts, *etm, *tw, *tb;
    const float *Adense, *nf, *memv, *ef;
    const int *idx, *eidx;
};

#define KV_PERM_BYTES 49152
#define KV_RAW_BYTES  98304
#define KV_DSMEM (KV_PERM_BYTES + KV_RAW_BYTES)

__device__ __forceinline__ uint32_t smem_u32p(const void* p) {
    uint32_t a;
    asm("{ .reg .u64 t; cvta.to.shared.u64 t, %1; cvt.u32.u64 %0, t; }" : "=r"(a) : "l"(p));
    return a;
}

// stash one half2 (k even pair) for row m, col k into fragment-permuted A
__device__ __forceinline__ void kv_stash_h2(uint32_t* As, int m, int k, uint32_t h2) {
    int kt = k >> 4, mi = m >> 4;
    int r16 = m & 15, gid = r16 & 7, hi_r = r16 >> 3;
    int klo = k & 15, tg = (klo & 7) >> 1;
    int reg = hi_r + ((klo >> 3) << 1);
    As[(((kt * 4 + mi) * 32) + gid * 4 + tg) * 4 + reg] = h2;
}
__device__ __forceinline__ uint32_t f2h2(float a, float b) {
    __half2 h = __floats2half2_rn(a, b);
    return *(uint32_t*)&h;
}

template <int DENSE>
__device__ __forceinline__ void kv_prefetch(uint32_t raw_smem, int bm, const KvParams& p, int tid) {
#pragma unroll 1
    for (int c = tid; c < 6144; c += 512) {
        int row = c / 96;
        int off4 = c - row * 96;
        int sec = off4 >> 5;
        int within = off4 & 31;
        int m = bm + row;
        const float* src;
        if (sec == 0) {
            src = DENSE ? (p.Adense + (size_t)m * 128 + within * 4)
                        : (p.nf + (size_t)__ldg(&p.idx[m]) * 128 + within * 4);
        } else if (sec == 1) {
            if (DENSE) continue;
            src = p.memv + (size_t)__ldg(&p.idx[m]) * 128 + within * 4;
        } else {
            src = p.ef + (size_t)__ldg(&p.eidx[m]) * 128 + within * 4;
        }
        uint32_t dst = raw_smem + c * 16;
        asm volatile("cp.async.cg.shared.global [%0], [%1], 16;" :: "r"(dst), "l"(src));
    }
    asm volatile("cp.async.commit_group;" ::: "memory");
}

template <int DENSE>
__global__ void __launch_bounds__(512, 1) kv_kernel(KvParams p) {
    extern __shared__ char smem[];
    uint32_t* As = (uint32_t*)smem;                    // 48KB permuted fp16 A
    const float4* raw4 = (const float4*)(smem + KV_PERM_BYTES);
    const uint32_t raw_u32 = smem_u32p(smem + KV_PERM_BYTES);

    const int tid = threadIdx.x;
    const int lane = tid & 31;
    const int wid = tid >> 5;          // warp = 32-col group (0..15)
    const int gID = lane >> 2;
    const int tg = lane & 3;
    const uint4* As4 = (const uint4*)As;
    const char* bpw = (const char*)p.Bp + (size_t)(wid * 4) * 6144;

    int blk = blockIdx.x;
    if (blk < p.nblk) kv_prefetch<DENSE>(raw_u32, blk * 64, p, tid);

#pragma unroll 1
    for (; blk < p.nblk; blk += gridDim.x) {
        const int bm = blk * 64;
        asm volatile("cp.async.wait_group 0;" ::: "memory");
        __syncthreads();   // raw ready; all warps done with previous perm A

        // ---------------- convert: raw -> fragment-permuted fp16 A ----------------
        {
            const int grow = tid >> 3;     // 0..63
            const int gseg = tid & 7;      // 0..7
            const int m = bm + grow;
#pragma unroll
            for (int i = 0; i < 4; i++) {
                int cf = gseg + 8 * i;     // float4 index within 128-col section
                // sec 0 (+ sec 1 add for gather)
                float4 v = raw4[grow * 96 + cf];
                if (!DENSE) {
                    float4 y = raw4[grow * 96 + 32 + cf];
                    v.x += y.x; v.y += y.y; v.z += y.z; v.w += y.w;
                }
                int k = cf * 4;
                kv_stash_h2(As, grow, k, f2h2(v.x, v.y));
                kv_stash_h2(As, grow, k + 2, f2h2(v.z, v.w));
                // sec 2: edge features -> cols 128..255
                float4 e = raw4[grow * 96 + 64 + cf];
                kv_stash_h2(As, grow, 128 + k, f2h2(e.x, e.y));
                kv_stash_h2(As, grow, 128 + k + 2, f2h2(e.z, e.w));
            }
            // cols 256..383: fused time encoding
            float dt = __ldg(&p.ts[m / p.DIV]) - __ldg(&p.etm[m]);
#pragma unroll
            for (int i = 0; i < 4; i++) {
                int j0 = (gseg + 8 * i) * 4;
                float c0 = __cosf(fmaf(dt, __ldg(&p.tw[j0 + 0]), __ldg(&p.tb[j0 + 0])));
                float c1 = __cosf(fmaf(dt, __ldg(&p.tw[j0 + 1]), __ldg(&p.tb[j0 + 1])));
                float c2 = __cosf(fmaf(dt, __ldg(&p.tw[j0 + 2]), __ldg(&p.tb[j0 + 2])));
                float c3 = __cosf(fmaf(dt, __ldg(&p.tw[j0 + 3]), __ldg(&p.tb[j0 + 3])));
                kv_stash_h2(As, grow, 256 + j0, f2h2(c0, c1));
                kv_stash_h2(As, grow, 256 + j0 + 2, f2h2(c2, c3));
            }
        }
        __syncthreads();   // perm A staged

        // prefetch next block's raw data (overlaps with main loop below)
        {
            int nxt = blk + gridDim.x;
            if (nxt < p.nblk) kv_prefetch<DENSE>(raw_u32, nxt * 64, p, tid);
        }

        // ---------------- main loop (sync-free) ----------------
        float acc[4][4][4];
#pragma unroll
        for (int mi = 0; mi < 4; mi++)
#pragma unroll
            for (int nj = 0; nj < 4; nj++)
#pragma unroll
                for (int q = 0; q < 4; q++) acc[mi][nj][q] = 0.f;

        uint4 bA[4], bB[4];

#define KV_LDB(buf, ktp_) { \
    _Pragma("unroll") \
    for (int nj = 0; nj < 4; nj++) \
        buf[nj] = *(const uint4*)(bpw + (size_t)nj * 6144 + (ktp_) * 512 + lane * 16); }

#define KV_STEP(buf, ktp_) { \
    _Pragma("unroll") \
    for (int kt_in = 0; kt_in < 2; kt_in++) { \
        const int kt = (ktp_) * 2 + kt_in; \
        _Pragma("unroll") \
        for (int mi = 0; mi < 4; mi++) { \
            uint4 av = As4[(kt * 4 + mi) * 32 + lane]; \
            uint32_t aa[4] = {av.x, av.y, av.z, av.w}; \
            _Pragma("unroll") \
            for (int nj = 0; nj < 4; nj++) { \
                uint32_t b0 = kt_in ? buf[nj].z : buf[nj].x; \
                uint32_t b1 = kt_in ? buf[nj].w : buf[nj].y; \
                mma_f16(acc[mi][nj], aa, b0, b1); \
            } \
        } \
    } }

        KV_LDB(bA, 0);
#pragma unroll 1
        for (int ktp = 0; ktp < 12; ktp += 2) {
            KV_LDB(bB, ktp + 1);
            KV_STEP(bA, ktp);
            if (ktp + 2 < 12) KV_LDB(bA, ktp + 2);
            KV_STEP(bB, ktp + 1);
        }
#undef KV_LDB
#undef KV_STEP

        // ---------------- epilogue (fp16 out) ----------------
#pragma unroll
        for (int mi = 0; mi < 4; mi++) {
            const int r_lo = bm + mi * 16 + gID;
            __half* clo = p.C + (size_t)r_lo * 512;
            __half* chi = clo + (size_t)8 * 512;
#pragma unroll
            for (int nj = 0; nj < 4; nj++) {
                const int col = wid * 32 + nj * 8 + tg * 2;
                const float b0 = (col < 256) ? __ldg(&p.bk[col]) : __ldg(&p.bv[col - 256]);
                const float b1 = (col + 1 < 256) ? __ldg(&p.bk[col + 1]) : __ldg(&p.bv[col + 1 - 256]);
                *(__half2*)(clo + col) = __floats2half2_rn(acc[mi][nj][0] + b0, acc[mi][nj][1] + b1);
                *(__half2*)(chi + col) = __floats2half2_rn(acc[mi][nj][2] + b0, acc[mi][nj][3] + b1);
            }
        }
    }
}

// ===========================================================================
// tf32 mma.sync GEMM (Q / O / fc1 / fc2): CTA = 128(m) x 128(n).
// ===========================================================================
struct TcParams {
    int Kdim, ldA, ldC;
    const float* W;
    const float* bias;
    float* C;
    int relu;
    const unsigned char* invalid;
    const float *Adense, *nf, *memv, *st;
    const int *idx;
};

template <int MODE>
__global__ void __launch_bounds__(256) mma_gemm(TcParams p) {
    __shared__ uint32_t As[128][36];
    __shared__ uint32_t Bs[128][36];
    const int tid = threadIdx.x;
    const int lane = tid & 31;
    const int wid = tid >> 5;
    const int bm = blockIdx.x * 128;
    const int noff = blockIdx.y * 128;
    const float* W = p.W + (size_t)noff * p.Kdim;
    const float* bias = p.bias + noff;
    const int row = tid >> 1;
    const int seg = tid & 1;
    const int m = bm + row;
    const int wr = (wid >> 1) * 32;
    const int wc = (wid & 1) * 64;
    const int groupID = lane >> 2;
    const int tg = lane & 3;

    float acc[2][8][4];
#pragma unroll
    for (int mi = 0; mi < 2; mi++)
#pragma unroll
        for (int nj = 0; nj < 8; nj++)
#pragma unroll
            for (int q = 0; q < 4; q++) acc[mi][nj][q] = 0.f;

#pragma unroll 1
    for (int k0 = 0; k0 < p.Kdim; k0 += 32) {
        const int kb = k0 + seg * 16;
        {
            const float* s0 = nullptr;
            const float* s1 = nullptr;
            if constexpr (MODE == MODE_PLAIN) {
                s0 = p.Adense + (size_t)m * p.ldA + kb;
            } else if constexpr (MODE == MODE_QGATHER) {
                if (kb < 128) {
                    int nd = __ldg(&p.idx[m]);
                    s0 = p.nf + (size_t)nd * 128 + kb;
                    s1 = p.memv + (size_t)nd * 128 + kb;
                } else {
                    s0 = p.st + (kb - 128);
                }
            } else {  // MODE_CONCAT
                if (kb < 256) {
                    s0 = p.Adense + (size_t)m * 256 + kb;
                } else {
                    int nd = __ldg(&p.idx[m]);
                    s0 = p.nf + (size_t)nd * 128 + (kb - 256);
                    s1 = p.memv + (size_t)nd * 128 + (kb - 256);
                }
            }
#pragma unroll
            for (int i = 0; i < 4; i++) {
                float4 v = *(const float4*)(s0 + i * 4);
                if (s1) {
                    float4 w = *(const float4*)(s1 + i * 4);
                    v.x += w.x; v.y += w.y; v.z += w.z; v.w += w.w;
                }
                *(uint4*)&As[row][seg * 16 + i * 4] = f4tf32(v);
            }
        }
        {
            const float* wsrc = W + (size_t)row * p.Kdim + kb;
#pragma unroll
            for (int i = 0; i < 4; i++)
                *(uint4*)&Bs[row][seg * 16 + i * 4] = f4tf32(*(const float4*)(wsrc + i * 4));
        }
        __syncthreads();
#pragma unroll
        for (int kk = 0; kk < 4; kk++) {
            const int c0 = kk * 8 + tg;
            uint32_t a[2][4];
#pragma unroll
            for (int mi = 0; mi < 2; mi++) {
                int r0 = wr + mi * 16 + groupID;
                a[mi][0] = As[r0][c0];
                a[mi][1] = As[r0 + 8][c0];
                a[mi][2] = As[r0][c0 + 4];
                a[mi][3] = As[r0 + 8][c0 + 4];
            }
#pragma unroll
            for (int nj = 0; nj < 8; nj++) {
                int nb_ = wc + nj * 8 + groupID;
                uint32_t b0 = Bs[nb_][c0];
                uint32_t b1 = Bs[nb_][c0 + 4];
                mma_tf32(acc[0][nj], a[0], b0, b1);
                mma_tf32(acc[1][nj], a[1], b0, b1);
            }
        }
        __syncthreads();
    }

#pragma unroll
    for (int mi = 0; mi < 2; mi++) {
        const int r_lo = bm + wr + mi * 16 + groupID;
        const int r_hi = r_lo + 8;
        const bool z_lo = (p.invalid != nullptr) && p.invalid[r_lo];
        const bool z_hi = (p.invalid != nullptr) && p.invalid[r_hi];
        float* clo = p.C + (size_t)r_lo * p.ldC + noff;
        float* chi = p.C + (size_t)r_hi * p.ldC + noff;
#pragma unroll
        for (int nj = 0; nj < 8; nj++) {
            const int cl = wc + nj * 8 + tg * 2;
            const float b0 = __ldg(&bias[cl]);
            const float b1 = __ldg(&bias[cl + 1]);
            float v00 = acc[mi][nj][0] + b0, v01 = acc[mi][nj][1] + b1;
            float v10 = acc[mi][nj][2] + b0, v11 = acc[mi][nj][3] + b1;
            if (p.relu) {
                v00 = fmaxf(v00, 0.f); v01 = fmaxf(v01, 0.f);
                v10 = fmaxf(v10, 0.f); v11 = fmaxf(v11, 0.f);
            }
            if (z_lo) { v00 = 0.f; v01 = 0.f; }
            if (z_hi) { v10 = 0.f; v11 = 0.f; }
            *(float2*)(clo + cl) = make_float2(v00, v01);
            *(float2*)(chi + cl) = make_float2(v10, v11);
        }
    }
}

__global__ void st_kernel(const float* __restrict__ b) {
    g_st[threadIdx.x] = __cosf(b[threadIdx.x]);
}

// ---------------------------------------------------------------------------
// Temporal attention (kv in fp16)
// ---------------------------------------------------------------------------
__global__ void attn_kernel(const float* __restrict__ q, const __half* __restrict__ kv,
                            const int* __restrict__ nbrs, float* __restrict__ outp,
                            unsigned char* __restrict__ invalid) {
    const int r = blockIdx.x;
    const int tid = threadIdx.x;
    const int warp = tid >> 5;
    const int lane = tid & 31;
    __shared__ float sq[256];
    __shared__ float sc[2][KNB];
    __shared__ float swt[2][KNB];
    __shared__ int smask[KNB];

    if (tid < 256) sq[tid] = q[(size_t)r * 256 + tid];
    if (tid < KNB) smask[tid] = (nbrs[r * KNB + tid] != 0) ? 1 : 0;
    __syncthreads();
    if (tid == 0) {
        int any = 0;
#pragma unroll
        for (int k = 0; k < KNB; k++) any |= smask[k];
        if (!any) smask[KNB - 1] = 1;
        invalid[r] = (unsigned char)(!any);
    }
    __syncthreads();

    if (warp < KNB) {
        const __half* kp = kv + ((size_t)r * KNB + warp) * 512;
        float s0 = 0.f, s1 = 0.f;
#pragma unroll
        for (int i = 0; i < 4; i++) {
            int d = lane + 32 * i;
            s0 = fmaf(sq[d], __half2float(__ldg(&kp[d])), s0);
            s1 = fmaf(sq[128 + d], __half2float(__ldg(&kp[128 + d])), s1);
        }
#pragma unroll
        for (int o = 16; o > 0; o >>= 1) {
            s0 += __shfl_down_sync(0xffffffffu, s0, o);
            s1 += __shfl_down_sync(0xffffffffu, s1, o);
        }
        if (lane == 0) {
            const float scale = 0.08838834764831845f;
            sc[0][warp] = smask[warp] ? s0 * scale : -1e9f;
            sc[1][warp] = smask[warp] ? s1 * scale : -1e9f;
        }
    }
    __syncthreads();

    if (tid < 2) {
        float mx = -3.0e38f;
#pragma unroll
        for (int k = 0; k < KNB; k++) mx = fmaxf(mx, sc[tid][k]);
        float sum = 0.f;
#pragma unroll
        for (int k = 0; k < KNB; k++) {
            float e = __expf(sc[tid][k] - mx);
            swt[tid][k] = e;
            sum += e;
        }
        float inv = 1.0f / sum;
#pragma unroll
        for (int k = 0; k < KNB; k++) swt[tid][k] *= inv;
    }
    __syncthreads();

    if (tid < 256) {
        int h = tid >> 7;
        float o = 0.f;
#pragma unroll
        for (int k = 0; k < KNB; k++)
            o = fmaf(swt[h][k], __half2float(__ldg(&kv[((size_t)r * KNB + k) * 512 + 256 + tid])), o);
        outp[(size_t)r * 256 + tid] = o;
    }
}

// ---------------------------------------------------------------------------
// Host side
// ---------------------------------------------------------------------------
static void launch_mma(int mode, int M, int nchunks, const TcParams& p, cudaStream_t s) {
    dim3 grid(M / 128, nchunks);
    switch (mode) {
        case MODE_PLAIN:   mma_gemm<MODE_PLAIN><<<grid, 256, 0, s>>>(p); break;
        case MODE_QGATHER: mma_gemm<MODE_QGATHER><<<grid, 256, 0, s>>>(p); break;
        case MODE_CONCAT:  mma_gemm<MODE_CONCAT><<<grid, 256, 0, s>>>(p); break;
    }
}

extern "C" void kernel_launch(void* const* d_in, const int* in_sizes, int n_in,
                              void* d_out, int out_size) {
    const float* nf   = (const float*)d_in[0];
    const float* mem  = (const float*)d_in[1];
    const float* ef   = (const float*)d_in[2];
    const float* tw   = (const float*)d_in[3];
    const float* tb   = (const float*)d_in[4];
    const float* Wq   = (const float*)d_in[5];
    const float* bq   = (const float*)d_in[6];
    const float* Wk   = (const float*)d_in[7];
    const float* bk   = (const float*)d_in[8];
    const float* Wv   = (const float*)d_in[9];
    const float* bv   = (const float*)d_in[10];
    const float* Wo   = (const float*)d_in[11];
    const float* bo   = (const float*)d_in[12];
    const float* f1w  = (const float*)d_in[13];
    const float* f1b  = (const float*)d_in[14];
    const float* f2w  = (const float*)d_in[15];
    const float* f2b  = (const float*)d_in[16];
    const int*   src  = (const int*)d_in[17];
    const float* ts   = (const float*)d_in[18];
    const int*   nb2  = (const int*)d_in[19];
    const int*   ei2  = (const int*)d_in[20];
    const float* tm2  = (const float*)d_in[21];
    const int*   nb1  = (const int*)d_in[22];
    const int*   ei1  = (const int*)d_in[23];
    const float* tm1  = (const float*)d_in[24];
    float* out = (float*)d_out;

    float *pst, *pq1, *pattn1, *po1, *ph1, *pemb1;
    float *pq2, *pattn2, *po2, *ph2;
    __half *pkv1, *pkv2, *pbph;
    unsigned char *pinv1, *pinv2;
    cudaGetSymbolAddress((void**)&pst, g_st);
    cudaGetSymbolAddress((void**)&pkv1, g_kv1);
    cudaGetSymbolAddress((void**)&pq1, g_q1);
    cudaGetSymbolAddress((void**)&pattn1, g_attn1);
    cudaGetSymbolAddress((void**)&po1, g_o1);
    cudaGetSymbolAddress((void**)&ph1, g_h1);
    cudaGetSymbolAddress((void**)&pemb1, g_emb1);
    cudaGetSymbolAddress((void**)&pinv1, g_inv1);
    cudaGetSymbolAddress((void**)&pkv2, g_kv2);
    cudaGetSymbolAddress((void**)&pq2, g_q2);
    cudaGetSymbolAddress((void**)&pattn2, g_attn2);
    cudaGetSymbolAddress((void**)&po2, g_o2);
    cudaGetSymbolAddress((void**)&ph2, g_h2);
    cudaGetSymbolAddress((void**)&pinv2, g_inv2);
    cudaGetSymbolAddress((void**)&pbph, g_bph);

    static cudaStream_t s_side = nullptr;
    static cudaEvent_t ev_fork = nullptr, ev_join = nullptr;
    if (s_side == nullptr) {
        cudaStreamCreateWithFlags(&s_side, cudaStreamNonBlocking);
        cudaEventCreateWithFlags(&ev_fork, cudaEventDisableTiming);
        cudaEventCreateWithFlags(&ev_join, cudaEventDisableTiming);
        cudaFuncSetAttribute(kv_kernel<0>, cudaFuncAttributeMaxDynamicSharedMemorySize, KV_DSMEM);
        cudaFuncSetAttribute(kv_kernel<1>, cudaFuncAttributeMaxDynamicSharedMemorySize, KV_DSMEM);
    }

    const cudaStream_t s0 = 0;

    st_kernel<<<1, 128, 0, s0>>>(tb);
    prep_b_kernel<<<(2 * 512 * 384 + 255) / 256, 256, 0, s0>>>(Wk, Wv, pbph);

    const float* Wq1 = Wq + 256 * 256;  const float* bq1 = bq + 256;
    const float* bk1 = bk + 256;
    const float* bv1 = bv + 256;
    const float* Wo1 = Wo + 256 * 256;  const float* bo1 = bo + 256;
    const float* f1w1 = f1w + 128 * 384; const float* f1b1 = f1b + 128;
    const float* f2w1 = f2w + 128 * 128; const float* f2b1 = f2b + 128;

    // ---- fork: Q1 + Q2 on side stream, concurrent with KV1 (136 SMs) ----
    cudaEventRecord(ev_fork, s0);
    cudaStreamWaitEvent(s_side, ev_fork, 0);
    {   // Q1 (tf32): [20480,256], 2 col chunks
        TcParams p{};
        p.Kdim = 256; p.ldC = 256;
        p.W = Wq; p.bias = bq; p.C = pq1;
        p.nf = nf; p.memv = mem; p.st = pst; p.idx = nb2;
        launch_mma(MODE_QGATHER, N1, 2, p, s_side);
    }
    {   // Q2 (tf32)
        TcParams p{};
        p.Kdim = 256; p.ldC = 256;
        p.W = Wq1; p.bias = bq1; p.C = pq2;
        p.nf = nf; p.memv = mem; p.st = pst; p.idx = src;
        launch_mma(MODE_QGATHER, BB, 2, p, s_side);
    }
    cudaEventRecord(ev_join, s_side);

    {   // KV1 (fp16 v5, persistent) on stream 0
        KvParams p{};
        p.Bp = pbph; p.bk = bk; p.bv = bv; p.C = pkv1;
        p.DIV = 100; p.nblk = NP1 / 64;
        p.ts = ts; p.etm = tm1; p.tw = tw; p.tb = tb;
        p.nf = nf; p.memv = mem; p.ef = ef; p.idx = nb1; p.eidx = ei1;
        kv_kernel<0><<<136, 512, KV_DSMEM, s0>>>(p);
    }
    cudaStreamWaitEvent(s0, ev_join, 0);

    attn_kernel<<<N1, 320, 0, s0>>>(pq1, pkv1, nb1, pattn1, pinv1);
    {   // O1 (tf32): 2 chunks, zero invalid rows
        TcParams p{};
        p.Kdim = 256; p.ldA = 256; p.ldC = 256;
        p.W = Wo; p.bias = bo; p.C = po1;
        p.Adense = pattn1; p.invalid = pinv1;
        launch_mma(MODE_PLAIN, N1, 2, p, s0);
    }
    {   // fc1 L0 (tf32): relu
        TcParams p{};
        p.Kdim = 384; p.ldC = 128;
        p.W = f1w; p.bias = f1b; p.C = ph1;
        p.Adense = po1; p.nf = nf; p.memv = mem; p.idx = nb2; p.relu = 1;
        launch_mma(MODE_CONCAT, N1, 1, p, s0);
    }
    {   // fc2 L0 (tf32) -> emb1
        TcParams p{};
        p.Kdim = 128; p.ldA = 128; p.ldC = 128;
        p.W = f2w; p.bias = f2b; p.C = pemb1; p.Adense = ph1;
        launch_mma(MODE_PLAIN, N1, 1, p, s0);
    }
    {   // KV2 (fp16 v5, dense, persistent)
        KvParams p{};
        p.Bp = pbph + 512 * 384; p.bk = bk1; p.bv = bv1; p.C = pkv2;
        p.DIV = 10; p.nblk = NP2 / 64;
        p.ts = ts; p.etm = tm2; p.tw = tw; p.tb = tb;
        p.Adense = pemb1; p.ef = ef; p.eidx = ei2;
        kv_kernel<1><<<148, 512, KV_DSMEM, s0>>>(p);
    }
    attn_kernel<<<BB, 320, 0, s0>>>(pq2, pkv2, nb2, pattn2, pinv2);
    {   // O2 (tf32)
        TcParams p{};
        p.Kdim = 256; p.ldA = 256; p.ldC = 256;
        p.W = Wo1; p.bias = bo1; p.C = po2;
        p.Adense = pattn2; p.invalid = pinv2;
        launch_mma(MODE_PLAIN, BB, 2, p, s0);
    }
    {   // fc1 L1 (tf32)
        TcParams p{};
        p.Kdim = 384; p.ldC = 128;
        p.W = f1w1; p.bias = f1b1; p.C = ph2;
        p.Adense = po2; p.nf = nf; p.memv = mem; p.idx = src; p.relu = 1;
        launch_mma(MODE_CONCAT, BB, 1, p, s0);
    }
    {   // fc2 L1 (tf32) -> out
        TcParams p{};
        p.Kdim = 128; p.ldA = 128; p.ldC = 128;
        p.W = f2w1; p.bias = f2b1; p.C = out; p.Adense = ph2;
        launch_mma(MODE_PLAIN, BB, 1, p, s0);
    }
}

// round 9
// speedup vs baseline: 7.1931x; 1.1523x over previous
#include <cuda_runtime.h>
#include <cuda_fp16.h>
#include <cstdint>

// ---------------------------------------------------------------------------
// Problem constants
// ---------------------------------------------------------------------------
#define KNB 10
#define BB  2048
#define N1  20480
#define NP1 204800
#define NP2 20480
// D = T = 128, QD = 256, KD = 384, H = 2, hd = 128

// ---------------------------------------------------------------------------
// Scratch
// ---------------------------------------------------------------------------
__device__ float g_st[128];
__device__ __half g_kv1[(size_t)NP1 * 512];
__device__ float g_q1 [(size_t)N1  * 256];
__device__ float g_attn1[(size_t)N1 * 256];
__device__ float g_h1 [(size_t)N1  * 128];
__device__ float g_emb1[(size_t)N1 * 128];
__device__ unsigned char g_inv1[N1];
__device__ __half g_kv2[(size_t)NP2 * 512];
__device__ float g_q2 [(size_t)BB  * 256];
__device__ float g_attn2[(size_t)BB * 256];
__device__ float g_h2 [(size_t)BB  * 128];
__device__ unsigned char g_inv2[BB];
// pre-permuted fragment-ordered fp16 weights for KV (2 layers x 512 n x 384 k)
__device__ __half g_bph[2 * 512 * 384];
// folded tail weights: Wcat = [f1w_left@Wo || f1w_right]  (2 layers x 128 x 384)
__device__ float g_wcat[2 * 128 * 384];
__device__ float g_c0[2 * 128];          // f1w_left @ bo per layer

#define MODE_PLAIN      0
#define MODE_QGATHER    1
#define MODE_CONCAT     4

// ---------------------------------------------------------------------------
// tf32 / fp16 mma helpers
// ---------------------------------------------------------------------------
__device__ __forceinline__ uint32_t f2tf32(float f) {
    uint32_t r;
    asm("cvt.rna.tf32.f32 %0, %1;" : "=r"(r) : "f"(f));
    return r;
}
__device__ __forceinline__ uint4 f4tf32(float4 v) {
    uint4 r;
    r.x = f2tf32(v.x); r.y = f2tf32(v.y); r.z = f2tf32(v.z); r.w = f2tf32(v.w);
    return r;
}
__device__ __forceinline__ void mma_tf32(float* c, const uint32_t* a, uint32_t b0, uint32_t b1) {
    asm volatile(
        "mma.sync.aligned.m16n8k8.row.col.f32.tf32.tf32.f32 "
        "{%0,%1,%2,%3}, {%4,%5,%6,%7}, {%8,%9}, {%0,%1,%2,%3};"
        : "+f"(c[0]), "+f"(c[1]), "+f"(c[2]), "+f"(c[3])
        : "r"(a[0]), "r"(a[1]), "r"(a[2]), "r"(a[3]), "r"(b0), "r"(b1));
}
__device__ __forceinline__ void mma_f16(float* c, const uint32_t* a, uint32_t b0, uint32_t b1) {
    asm volatile(
        "mma.sync.aligned.m16n8k16.row.col.f32.f16.f16.f32 "
        "{%0,%1,%2,%3}, {%4,%5,%6,%7}, {%8,%9}, {%0,%1,%2,%3};"
        : "+f"(c[0]), "+f"(c[1]), "+f"(c[2]), "+f"(c[3])
        : "r"(a[0]), "r"(a[1]), "r"(a[2]), "r"(a[3]), "r"(b0), "r"(b1));
}

// ===========================================================================
// B pre-permutation: Wk||Wv [512 n][384 k] fp32 -> fragment-ordered fp16
// ===========================================================================
__global__ void prep_b_kernel(const float* __restrict__ Wk, const float* __restrict__ Wv,
                              __half* __restrict__ dst) {
    int idx = blockIdx.x * blockDim.x + threadIdx.x;   // 2 * 512 * 384
    if (idx >= 2 * 512 * 384) return;
    int l = idx / (512 * 384);
    int rem = idx - l * (512 * 384);
    int n = rem / 384;
    int k = rem - n * 384;
    const float* W = (n < 256) ? (Wk + (size_t)l * 256 * 384 + (size_t)n * 384)
                               : (Wv + (size_t)l * 256 * 384 + (size_t)(n - 256) * 384);
    float v = W[k];
    int nt = n >> 3, gid = n & 7;
    int ktp = k >> 5, k32 = k & 31;
    int kt_in = k32 >> 4, klo = k32 & 15;
    int tg = (klo & 7) >> 1, reg = klo >> 3, par = k & 1;
    int lane = gid * 4 + tg;
    size_t off = ((((size_t)l * 64 + nt) * 12 + ktp) * 32 + lane) * 8 + (kt_in * 2 + reg) * 2 + par;
    dst[off] = __float2half_rn(v);
}

// ===========================================================================
// Tail fold: Wcat[l][i][k] = (k<256) ? sum_j f1w[l][i][j]*Wo[l][j][k]
//                                    : f1w[l][i][k]
//            c0[l][i] = sum_j f1w[l][i][j]*bo[l][j]
// grid: 256 blocks (l*128+i), 384 threads (k)
// ===========================================================================
__global__ void prep_wc_kernel(const float* __restrict__ Wo, const float* __restrict__ bo,
                               const float* __restrict__ f1w,
                               float* __restrict__ wcat, float* __restrict__ c0) {
    int l = blockIdx.x >> 7;
    int i = blockIdx.x & 127;
    int k = threadIdx.x;
    const float* f1 = f1w + ((size_t)l * 128 + i) * 384;
    float v;
    if (k < 256) {
        const float* wo = Wo + (size_t)l * 256 * 256;
        float s = 0.f;
#pragma unroll 4
        for (int j = 0; j < 256; j++) s = fmaf(f1[j], wo[j * 256 + k], s);
        v = s;
    } else {
        v = f1[k];
    }
    wcat[((size_t)l * 128 + i) * 384 + k] = v;
    if (k == 0) {
        const float* bol = bo + l * 256;
        float s = 0.f;
#pragma unroll 4
        for (int j = 0; j < 256; j++) s = fmaf(f1[j], bol[j], s);
        c0[l * 128 + i] = s;
    }
}

// ===========================================================================
// KV projection kernel v6: fp16 mma m16n8k16, persistent CTAs, DOUBLE-BUFFERED
// fragment-permuted A; convert(i+1) issued after epilogue(i) with ONE barrier
// per iteration -> MUFU (cos) overlaps tensor (MMA) across desynced warps.
// CTA = 64 rows x 512 cols, 512 threads (16 warps, warp = 64 rows x 32 cols).
// ===========================================================================
struct KvParams {
    const __half* Bp;
    const float *bk, *bv;
    __half* C;                         // [M, 512] fp16
    int DIV, nblk;
    const float *ts, *etm, *tw, *tb;
    const float *Adense, *nf, *memv, *ef;
    const int *idx, *eidx;
};

#define KV_DSMEM (2 * 49152)

// stash one half2 (k even pair) for row m, col k into fragment-permuted A
__device__ __forceinline__ void kv_stash_h2(uint32_t* As, int m, int k, uint32_t h2) {
    int kt = k >> 4, mi = m >> 4;
    int r16 = m & 15, gid = r16 & 7, hi_r = r16 >> 3;
    int klo = k & 15, tg = (klo & 7) >> 1;
    int reg = hi_r + ((klo >> 3) << 1);
    As[(((kt * 4 + mi) * 32) + gid * 4 + tg) * 4 + reg] = h2;
}
__device__ __forceinline__ uint32_t f2h2(float a, float b) {
    __half2 h = __floats2half2_rn(a, b);
    return *(uint32_t*)&h;
}

template <int DENSE>
__device__ __forceinline__ void kv_convert(uint32_t* As, int bm, const KvParams& p, int tid) {
    const int grow = tid >> 3;     // 0..63
    const int gseg = tid & 7;      // 0..7
    const int m = bm + grow;
    if (DENSE) {
        const float4* s = (const float4*)(p.Adense + (size_t)m * 128);
#pragma unroll
        for (int i = 0; i < 4; i++) {
            int cf = gseg + 8 * i;
            float4 v = s[cf];
            int k = cf * 4;
            kv_stash_h2(As, grow, k, f2h2(v.x, v.y));
            kv_stash_h2(As, grow, k + 2, f2h2(v.z, v.w));
        }
    } else {
        int nd = __ldg(&p.idx[m]);
        const float4* s0 = (const float4*)(p.nf + (size_t)nd * 128);
        const float4* s1 = (const float4*)(p.memv + (size_t)nd * 128);
#pragma unroll
        for (int i = 0; i < 4; i++) {
            int cf = gseg + 8 * i;
            float4 x = s0[cf], y = s1[cf];
            int k = cf * 4;
            kv_stash_h2(As, grow, k, f2h2(x.x + y.x, x.y + y.y));
            kv_stash_h2(As, grow, k + 2, f2h2(x.z + y.z, x.w + y.w));
        }
    }
    {
        int e = __ldg(&p.eidx[m]);
        const float4* s = (const float4*)(p.ef + (size_t)e * 128);
#pragma unroll
        for (int i = 0; i < 4; i++) {
            int cf = gseg + 8 * i;
            float4 v = s[cf];
            int k = cf * 4;
            kv_stash_h2(As, grow, 128 + k, f2h2(v.x, v.y));
            kv_stash_h2(As, grow, 128 + k + 2, f2h2(v.z, v.w));
        }
    }
    float dt = __ldg(&p.ts[m / p.DIV]) - __ldg(&p.etm[m]);
#pragma unroll
    for (int i = 0; i < 4; i++) {
        int j0 = (gseg + 8 * i) * 4;
        float c0 = __cosf(fmaf(dt, __ldg(&p.tw[j0 + 0]), __ldg(&p.tb[j0 + 0])));
        float c1 = __cosf(fmaf(dt, __ldg(&p.tw[j0 + 1]), __ldg(&p.tb[j0 + 1])));
        float c2 = __cosf(fmaf(dt, __ldg(&p.tw[j0 + 2]), __ldg(&p.tb[j0 + 2])));
        float c3 = __cosf(fmaf(dt, __ldg(&p.tw[j0 + 3]), __ldg(&p.tb[j0 + 3])));
        kv_stash_h2(As, grow, 256 + j0, f2h2(c0, c1));
        kv_stash_h2(As, grow, 256 + j0 + 2, f2h2(c2, c3));
    }
}

template <int DENSE>
__global__ void __launch_bounds__(512, 1) kv_kernel(KvParams p) {
    extern __shared__ char smem[];
    uint32_t* perm = (uint32_t*)smem;        // 2 x 12288 uint32 (2 x 48KB)

    const int tid = threadIdx.x;
    const int lane = tid & 31;
    const int wid = tid >> 5;
    const int gID = lane >> 2;
    const int tg = lane & 3;
    const char* bpw = (const char*)p.Bp + (size_t)(wid * 4) * 6144;

    int blk = blockIdx.x;
    if (blk < p.nblk) kv_convert<DENSE>(perm, blk * 64, p, tid);
    __syncthreads();

    int parity = 0;
#pragma unroll 1
    for (; blk < p.nblk; blk += gridDim.x) {
        const int bm = blk * 64;
        const uint4* As4 = (const uint4*)(perm + parity * 12288);

        float acc[4][4][4];
#pragma unroll
        for (int mi = 0; mi < 4; mi++)
#pragma unroll
            for (int nj = 0; nj < 4; nj++)
#pragma unroll
                for (int q = 0; q < 4; q++) acc[mi][nj][q] = 0.f;

        uint4 bA[4], bB[4];

#define KV_LDB(buf, ktp_) { \
    _Pragma("unroll") \
    for (int nj = 0; nj < 4; nj++) \
        buf[nj] = *(const uint4*)(bpw + (size_t)nj * 6144 + (ktp_) * 512 + lane * 16); }

#define KV_STEP(buf, ktp_) { \
    _Pragma("unroll") \
    for (int kt_in = 0; kt_in < 2; kt_in++) { \
        const int kt = (ktp_) * 2 + kt_in; \
        _Pragma("unroll") \
        for (int mi = 0; mi < 4; mi++) { \
            uint4 av = As4[(kt * 4 + mi) * 32 + lane]; \
            uint32_t aa[4] = {av.x, av.y, av.z, av.w}; \
            _Pragma("unroll") \
            for (int nj = 0; nj < 4; nj++) { \
                uint32_t b0 = kt_in ? buf[nj].z : buf[nj].x; \
                uint32_t b1 = kt_in ? buf[nj].w : buf[nj].y; \
                mma_f16(acc[mi][nj], aa, b0, b1); \
            } \
        } \
    } }

        KV_LDB(bA, 0);
#pragma unroll 1
        for (int ktp = 0; ktp < 12; ktp += 2) {
            KV_LDB(bB, ktp + 1);
            KV_STEP(bA, ktp);
            if (ktp + 2 < 12) KV_LDB(bA, ktp + 2);
            KV_STEP(bB, ktp + 1);
        }
#undef KV_LDB
#undef KV_STEP

        // epilogue (fp16 out) — frees acc before convert
#pragma unroll
        for (int mi = 0; mi < 4; mi++) {
            const int r_lo = bm + mi * 16 + gID;
            __half* clo = p.C + (size_t)r_lo * 512;
            __half* chi = clo + (size_t)8 * 512;
#pragma unroll
            for (int nj = 0; nj < 4; nj++) {
                const int col = wid * 32 + nj * 8 + tg * 2;
                const float b0 = (col < 256) ? __ldg(&p.bk[col]) : __ldg(&p.bv[col - 256]);
                const float b1 = (col + 1 < 256) ? __ldg(&p.bk[col + 1]) : __ldg(&p.bv[col + 1 - 256]);
                *(__half2*)(clo + col) = __floats2half2_rn(acc[mi][nj][0] + b0, acc[mi][nj][1] + b1);
                *(__half2*)(chi + col) = __floats2half2_rn(acc[mi][nj][2] + b0, acc[mi][nj][3] + b1);
            }
        }

        // convert next block into the other buffer (overlaps: warps desynced)
        {
            int nxt = blk + gridDim.x;
            if (nxt < p.nblk)
                kv_convert<DENSE>(perm + (parity ^ 1) * 12288, nxt * 64, p, tid);
        }
        __syncthreads();
        parity ^= 1;
    }
}

// ===========================================================================
// tf32 mma.sync GEMM (Q / fused-fc1 / fc2): CTA = 128(m) x 128(n).
// cbias: per-col extra bias added ONLY for rows where invalid[m]==0 (pre-relu).
// ===========================================================================
struct TcParams {
    int Kdim, ldA, ldC;
    const float* W;
    const float* bias;
    const float* cbias;
    float* C;
    int relu;
    const unsigned char* invalid;
    const float *Adense, *nf, *memv, *st;
    const int *idx;
};

template <int MODE>
__global__ void __launch_bounds__(256) mma_gemm(TcParams p) {
    __shared__ uint32_t As[128][36];
    __shared__ uint32_t Bs[128][36];
    const int tid = threadIdx.x;
    const int lane = tid & 31;
    const int wid = tid >> 5;
    const int bm = blockIdx.x * 128;
    const int noff = blockIdx.y * 128;
    const float* W = p.W + (size_t)noff * p.Kdim;
    const float* bias = p.bias + noff;
    const int row = tid >> 1;
    const int seg = tid & 1;
    const int m = bm + row;
    const int wr = (wid >> 1) * 32;
    const int wc = (wid & 1) * 64;
    const int groupID = lane >> 2;
    const int tg = lane & 3;

    float acc[2][8][4];
#pragma unroll
    for (int mi = 0; mi < 2; mi++)
#pragma unroll
        for (int nj = 0; nj < 8; nj++)
#pragma unroll
            for (int q = 0; q < 4; q++) acc[mi][nj][q] = 0.f;

#pragma unroll 1
    for (int k0 = 0; k0 < p.Kdim; k0 += 32) {
        const int kb = k0 + seg * 16;
        {
            const float* s0 = nullptr;
            const float* s1 = nullptr;
            if constexpr (MODE == MODE_PLAIN) {
                s0 = p.Adense + (size_t)m * p.ldA + kb;
            } else if constexpr (MODE == MODE_QGATHER) {
                if (kb < 128) {
                    int nd = __ldg(&p.idx[m]);
                    s0 = p.nf + (size_t)nd * 128 + kb;
                    s1 = p.memv + (size_t)nd * 128 + kb;
                } else {
                    s0 = p.st + (kb - 128);
                }
            } else {  // MODE_CONCAT
                if (kb < 256) {
                    s0 = p.Adense + (size_t)m * 256 + kb;
                } else {
                    int nd = __ldg(&p.idx[m]);
                    s0 = p.nf + (size_t)nd * 128 + (kb - 256);
                    s1 = p.memv + (size_t)nd * 128 + (kb - 256);
                }
            }
#pragma unroll
            for (int i = 0; i < 4; i++) {
                float4 v = *(const float4*)(s0 + i * 4);
                if (s1) {
                    float4 w = *(const float4*)(s1 + i * 4);
                    v.x += w.x; v.y += w.y; v.z += w.z; v.w += w.w;
                }
                *(uint4*)&As[row][seg * 16 + i * 4] = f4tf32(v);
            }
        }
        {
            const float* wsrc = W + (size_t)row * p.Kdim + kb;
#pragma unroll
            for (int i = 0; i < 4; i++)
                *(uint4*)&Bs[row][seg * 16 + i * 4] = f4tf32(*(const float4*)(wsrc + i * 4));
        }
        __syncthreads();
#pragma unroll
        for (int kk = 0; kk < 4; kk++) {
            const int c0 = kk * 8 + tg;
            uint32_t a[2][4];
#pragma unroll
            for (int mi = 0; mi < 2; mi++) {
                int r0 = wr + mi * 16 + groupID;
                a[mi][0] = As[r0][c0];
                a[mi][1] = As[r0 + 8][c0];
                a[mi][2] = As[r0][c0 + 4];
                a[mi][3] = As[r0 + 8][c0 + 4];
            }
#pragma unroll
            for (int nj = 0; nj < 8; nj++) {
                int nb_ = wc + nj * 8 + groupID;
                uint32_t b0 = Bs[nb_][c0];
                uint32_t b1 = Bs[nb_][c0 + 4];
                mma_tf32(acc[0][nj], a[0], b0, b1);
                mma_tf32(acc[1][nj], a[1], b0, b1);
            }
        }
        __syncthreads();
    }

#pragma unroll
    for (int mi = 0; mi < 2; mi++) {
        const int r_lo = bm + wr + mi * 16 + groupID;
        const int r_hi = r_lo + 8;
        const bool z_lo = (p.invalid != nullptr) && p.invalid[r_lo];
        const bool z_hi = (p.invalid != nullptr) && p.invalid[r_hi];
        float* clo = p.C + (size_t)r_lo * p.ldC + noff;
        float* chi = p.C + (size_t)r_hi * p.ldC + noff;
#pragma unroll
        for (int nj = 0; nj < 8; nj++) {
            const int cl = wc + nj * 8 + tg * 2;
            const float b0 = __ldg(&bias[cl]);
            const float b1 = __ldg(&bias[cl + 1]);
            float cb0 = 0.f, cb1 = 0.f;
            if (p.cbias) {
                cb0 = __ldg(&p.cbias[noff + cl]);
                cb1 = __ldg(&p.cbias[noff + cl + 1]);
            }
            float v00 = acc[mi][nj][0] + b0 + (z_lo ? 0.f : cb0);
            float v01 = acc[mi][nj][1] + b1 + (z_lo ? 0.f : cb1);
            float v10 = acc[mi][nj][2] + b0 + (z_hi ? 0.f : cb0);
            float v11 = acc[mi][nj][3] + b1 + (z_hi ? 0.f : cb1);
            if (p.relu) {
                v00 = fmaxf(v00, 0.f); v01 = fmaxf(v01, 0.f);
                v10 = fmaxf(v10, 0.f); v11 = fmaxf(v11, 0.f);
            }
            *(float2*)(clo + cl) = make_float2(v00, v01);
            *(float2*)(chi + cl) = make_float2(v10, v11);
        }
    }
}

__global__ void st_kernel(const float* __restrict__ b) {
    g_st[threadIdx.x] = __cosf(b[threadIdx.x]);
}

// ---------------------------------------------------------------------------
// Temporal attention (kv fp16); zeroes output rows with no valid neighbor.
// ---------------------------------------------------------------------------
__global__ void attn_kernel(const float* __restrict__ q, const __half* __restrict__ kv,
                            const int* __restrict__ nbrs, float* __restrict__ outp,
                            unsigned char* __restrict__ invalid) {
    const int r = blockIdx.x;
    const int tid = threadIdx.x;
    const int warp = tid >> 5;
    const int lane = tid & 31;
    __shared__ float sq[256];
    __shared__ float sc[2][KNB];
    __shared__ float swt[2][KNB];
    __shared__ int smask[KNB];
    __shared__ int sinv;

    if (tid < 256) sq[tid] = q[(size_t)r * 256 + tid];
    if (tid < KNB) smask[tid] = (nbrs[r * KNB + tid] != 0) ? 1 : 0;
    __syncthreads();
    if (tid == 0) {
        int any = 0;
#pragma unroll
        for (int k = 0; k < KNB; k++) any |= smask[k];
        if (!any) smask[KNB - 1] = 1;
        sinv = !any;
        invalid[r] = (unsigned char)(!any);
    }
    __syncthreads();

    if (warp < KNB) {
        const __half* kp = kv + ((size_t)r * KNB + warp) * 512;
        float s0 = 0.f, s1 = 0.f;
#pragma unroll
        for (int i = 0; i < 4; i++) {
            int d = lane + 32 * i;
            s0 = fmaf(sq[d], __half2float(__ldg(&kp[d])), s0);
            s1 = fmaf(sq[128 + d], __half2float(__ldg(&kp[128 + d])), s1);
        }
#pragma unroll
        for (int o = 16; o > 0; o >>= 1) {
            s0 += __shfl_down_sync(0xffffffffu, s0, o);
            s1 += __shfl_down_sync(0xffffffffu, s1, o);
        }
        if (lane == 0) {
            const float scale = 0.08838834764831845f;
            sc[0][warp] = smask[warp] ? s0 * scale : -1e9f;
            sc[1][warp] = smask[warp] ? s1 * scale : -1e9f;
        }
    }
    __syncthreads();

    if (tid < 2) {
        float mx = -3.0e38f;
#pragma unroll
        for (int k = 0; k < KNB; k++) mx = fmaxf(mx, sc[tid][k]);
        float sum = 0.f;
#pragma unroll
        for (int k = 0; k < KNB; k++) {
            float e = __expf(sc[tid][k] - mx);
            swt[tid][k] = e;
            sum += e;
        }
        float inv = 1.0f / sum;
#pragma unroll
        for (int k = 0; k < KNB; k++) swt[tid][k] *= inv;
    }
    __syncthreads();

    if (tid < 256) {
        int h = tid >> 7;
        float o = 0.f;
#pragma unroll
        for (int k = 0; k < KNB; k++)
            o = fmaf(swt[h][k], __half2float(__ldg(&kv[((size_t)r * KNB + k) * 512 + 256 + tid])), o);
        outp[(size_t)r * 256 + tid] = sinv ? 0.f : o;
    }
}

// ---------------------------------------------------------------------------
// Host side
// ---------------------------------------------------------------------------
static void launch_mma(int mode, int M, int nchunks, const TcParams& p, cudaStream_t s) {
    dim3 grid(M / 128, nchunks);
    switch (mode) {
        case MODE_PLAIN:   mma_gemm<MODE_PLAIN><<<grid, 256, 0, s>>>(p); break;
        case MODE_QGATHER: mma_gemm<MODE_QGATHER><<<grid, 256, 0, s>>>(p); break;
        case MODE_CONCAT:  mma_gemm<MODE_CONCAT><<<grid, 256, 0, s>>>(p); break;
    }
}

extern "C" void kernel_launch(void* const* d_in, const int* in_sizes, int n_in,
                              void* d_out, int out_size) {
    const float* nf   = (const float*)d_in[0];
    const float* mem  = (const float*)d_in[1];
    const float* ef   = (const float*)d_in[2];
    const float* tw   = (const float*)d_in[3];
    const float* tb   = (const float*)d_in[4];
    const float* Wq   = (const float*)d_in[5];
    const float* bq   = (const float*)d_in[6];
    const float* Wk   = (const float*)d_in[7];
    const float* bk   = (const float*)d_in[8];
    const float* Wv   = (const float*)d_in[9];
    const float* bv   = (const float*)d_in[10];
    const float* Wo   = (const float*)d_in[11];
    const float* bo   = (const float*)d_in[12];
    const float* f1w  = (const float*)d_in[13];
    const float* f1b  = (const float*)d_in[14];
    const float* f2w  = (const float*)d_in[15];
    const float* f2b  = (const float*)d_in[16];
    const int*   src  = (const int*)d_in[17];
    const float* ts   = (const float*)d_in[18];
    const int*   nb2  = (const int*)d_in[19];
    const int*   ei2  = (const int*)d_in[20];
    const float* tm2  = (const float*)d_in[21];
    const int*   nb1  = (const int*)d_in[22];
    const int*   ei1  = (const int*)d_in[23];
    const float* tm1  = (const float*)d_in[24];
    float* out = (float*)d_out;

    float *pst, *pq1, *pattn1, *ph1, *pemb1;
    float *pq2, *pattn2, *ph2, *pwcat, *pc0;
    __half *pkv1, *pkv2, *pbph;
    unsigned char *pinv1, *pinv2;
    cudaGetSymbolAddress((void**)&pst, g_st);
    cudaGetSymbolAddress((void**)&pkv1, g_kv1);
    cudaGetSymbolAddress((void**)&pq1, g_q1);
    cudaGetSymbolAddress((void**)&pattn1, g_attn1);
    cudaGetSymbolAddress((void**)&ph1, g_h1);
    cudaGetSymbolAddress((void**)&pemb1, g_emb1);
    cudaGetSymbolAddress((void**)&pinv1, g_inv1);
    cudaGetSymbolAddress((void**)&pkv2, g_kv2);
    cudaGetSymbolAddress((void**)&pq2, g_q2);
    cudaGetSymbolAddress((void**)&pattn2, g_attn2);
    cudaGetSymbolAddress((void**)&ph2, g_h2);
    cudaGetSymbolAddress((void**)&pinv2, g_inv2);
    cudaGetSymbolAddress((void**)&pbph, g_bph);
    cudaGetSymbolAddress((void**)&pwcat, g_wcat);
    cudaGetSymbolAddress((void**)&pc0, g_c0);

    static cudaStream_t s_side = nullptr;
    static cudaEvent_t ev_fork = nullptr, ev_join = nullptr;
    if (s_side == nullptr) {
        cudaStreamCreateWithFlags(&s_side, cudaStreamNonBlocking);
        cudaEventCreateWithFlags(&ev_fork, cudaEventDisableTiming);
        cudaEventCreateWithFlags(&ev_join, cudaEventDisableTiming);
        cudaFuncSetAttribute(kv_kernel<0>, cudaFuncAttributeMaxDynamicSharedMemorySize, KV_DSMEM);
        cudaFuncSetAttribute(kv_kernel<1>, cudaFuncAttributeMaxDynamicSharedMemorySize, KV_DSMEM);
    }

    const cudaStream_t s0 = 0;

    st_kernel<<<1, 128, 0, s0>>>(tb);
    prep_b_kernel<<<(2 * 512 * 384 + 255) / 256, 256, 0, s0>>>(Wk, Wv, pbph);
    prep_wc_kernel<<<256, 384, 0, s0>>>(Wo, bo, f1w, pwcat, pc0);

    const float* Wq1 = Wq + 256 * 256;  const float* bq1 = bq + 256;
    const float* bk1 = bk + 256;
    const float* bv1 = bv + 256;
    const float* f2w1 = f2w + 128 * 128; const float* f2b1 = f2b + 128;

    // ---- fork: Q1 + Q2 on side stream, concurrent with KV1 (136 SMs) ----
    cudaEventRecord(ev_fork, s0);
    cudaStreamWaitEvent(s_side, ev_fork, 0);
    {   // Q1 (tf32): [20480,256], 2 col chunks
        TcParams p{};
        p.Kdim = 256; p.ldC = 256;
        p.W = Wq; p.bias = bq; p.C = pq1;
        p.nf = nf; p.memv = mem; p.st = pst; p.idx = nb2;
        launch_mma(MODE_QGATHER, N1, 2, p, s_side);
    }
    {   // Q2 (tf32)
        TcParams p{};
        p.Kdim = 256; p.ldC = 256;
        p.W = Wq1; p.bias = bq1; p.C = pq2;
        p.nf = nf; p.memv = mem; p.st = pst; p.idx = src;
        launch_mma(MODE_QGATHER, BB, 2, p, s_side);
    }
    cudaEventRecord(ev_join, s_side);

    {   // KV1 (fp16 v6, persistent, overlapped convert) on stream 0
        KvParams p{};
        p.Bp = pbph; p.bk = bk; p.bv = bv; p.C = pkv1;
        p.DIV = 100; p.nblk = NP1 / 64;
        p.ts = ts; p.etm = tm1; p.tw = tw; p.tb = tb;
        p.nf = nf; p.memv = mem; p.ef = ef; p.idx = nb1; p.eidx = ei1;
        kv_kernel<0><<<136, 512, KV_DSMEM, s0>>>(p);
    }
    cudaStreamWaitEvent(s0, ev_join, 0);

    attn_kernel<<<N1, 320, 0, s0>>>(pq1, pkv1, nb1, pattn1, pinv1);
    {   // fused O1+fc1 (tf32): K=384 [attn || base], conditional c0, relu
        TcParams p{};
        p.Kdim = 384; p.ldC = 128;
        p.W = pwcat; p.bias = f1b; p.cbias = pc0; p.C = ph1;
        p.Adense = pattn1; p.nf = nf; p.memv = mem; p.idx = nb2;
        p.invalid = pinv1; p.relu = 1;
        launch_mma(MODE_CONCAT, N1, 1, p, s0);
    }
    {   // fc2 L0 (tf32) -> emb1
        TcParams p{};
        p.Kdim = 128; p.ldA = 128; p.ldC = 128;
        p.W = f2w; p.bias = f2b; p.C = pemb1; p.Adense = ph1;
        launch_mma(MODE_PLAIN, N1, 1, p, s0);
    }
    {   // KV2 (fp16 v6, dense)
        KvParams p{};
        p.Bp = pbph + 512 * 384; p.bk = bk1; p.bv = bv1; p.C = pkv2;
        p.DIV = 10; p.nblk = NP2 / 64;
        p.ts = ts; p.etm = tm2; p.tw = tw; p.tb = tb;
        p.Adense = pemb1; p.ef = ef; p.eidx = ei2;
        kv_kernel<1><<<148, 512, KV_DSMEM, s0>>>(p);
    }
    attn_kernel<<<BB, 320, 0, s0>>>(pq2, pkv2, nb2, pattn2, pinv2);
    {   // fused O2+fc1 L1 (tf32)
        TcParams p{};
        p.Kdim = 384; p.ldC = 128;
        p.W = pwcat + 128 * 384; p.bias = f1b + 128; p.cbias = pc0 + 128; p.C = ph2;
        p.Adense = pattn2; p.nf = nf; p.memv = mem; p.idx = src;
        p.invalid = pinv2; p.relu = 1;
        launch_mma(MODE_CONCAT, BB, 1, p, s0);
    }
    {   // fc2 L1 (tf32) -> out
        TcParams p{};
        p.Kdim = 128; p.ldA = 128; p.ldC = 128;
        p.W = f2w1; p.bias = f2b1; p.C = out; p.Adense = ph2;
        launch_mma(MODE_PLAIN, BB, 1, p, s0);
    }
}

// round 10
// speedup vs baseline: 7.8002x; 1.0844x over previous
#include <cuda_runtime.h>
#include <cuda_fp16.h>
#include <cstdint>

// ---------------------------------------------------------------------------
// Problem constants
// ---------------------------------------------------------------------------
#define KNB 10
#define BB  2048
#define N1  20480
#define NP1 204800
#define NP2 20480
// D = T = 128, QD = 256, KD = 384, H = 2, hd = 128

// ---------------------------------------------------------------------------
// Scratch
// ---------------------------------------------------------------------------
__device__ float g_st[128];
__device__ __half g_kv1[(size_t)NP1 * 512];
__device__ float g_q1 [(size_t)N1  * 256];
__device__ float g_attn1[(size_t)N1 * 256];
__device__ float g_h1 [(size_t)N1  * 128];
__device__ float g_emb1[(size_t)N1 * 128];
__device__ unsigned char g_inv1[N1];
__device__ __half g_kv2[(size_t)NP2 * 512];
__device__ float g_q2 [(size_t)BB  * 256];
__device__ float g_attn2[(size_t)BB * 256];
__device__ float g_h2 [(size_t)BB  * 128];
__device__ unsigned char g_inv2[BB];
// pre-permuted fragment-ordered fp16 weights for KV (2 layers x 512 n x 384 k)
__device__ __half g_bph[2 * 512 * 384];
// folded tail weights: Wcat = [f1w_left@Wo || f1w_right]  (2 layers x 128 x 384)
__device__ float g_wcat[2 * 128 * 384];
__device__ float g_c0[2 * 128];          // f1w_left @ bo per layer

#define MODE_PLAIN      0
#define MODE_QGATHER    1
#define MODE_CONCAT     4

// ---------------------------------------------------------------------------
// fp16 mma helper
// ---------------------------------------------------------------------------
__device__ __forceinline__ void mma_f16(float* c, const uint32_t* a, uint32_t b0, uint32_t b1) {
    asm volatile(
        "mma.sync.aligned.m16n8k16.row.col.f32.f16.f16.f32 "
        "{%0,%1,%2,%3}, {%4,%5,%6,%7}, {%8,%9}, {%0,%1,%2,%3};"
        : "+f"(c[0]), "+f"(c[1]), "+f"(c[2]), "+f"(c[3])
        : "r"(a[0]), "r"(a[1]), "r"(a[2]), "r"(a[3]), "r"(b0), "r"(b1));
}
__device__ __forceinline__ uint32_t f2h2(float a, float b) {
    __half2 h = __floats2half2_rn(a, b);
    return *(uint32_t*)&h;
}

// ===========================================================================
// B pre-permutation: Wk||Wv [512 n][384 k] fp32 -> fragment-ordered fp16
// ===========================================================================
__global__ void prep_b_kernel(const float* __restrict__ Wk, const float* __restrict__ Wv,
                              __half* __restrict__ dst) {
    int idx = blockIdx.x * blockDim.x + threadIdx.x;   // 2 * 512 * 384
    if (idx >= 2 * 512 * 384) return;
    int l = idx / (512 * 384);
    int rem = idx - l * (512 * 384);
    int n = rem / 384;
    int k = rem - n * 384;
    const float* W = (n < 256) ? (Wk + (size_t)l * 256 * 384 + (size_t)n * 384)
                               : (Wv + (size_t)l * 256 * 384 + (size_t)(n - 256) * 384);
    float v = W[k];
    int nt = n >> 3, gid = n & 7;
    int ktp = k >> 5, k32 = k & 31;
    int kt_in = k32 >> 4, klo = k32 & 15;
    int tg = (klo & 7) >> 1, reg = klo >> 3, par = k & 1;
    int lane = gid * 4 + tg;
    size_t off = ((((size_t)l * 64 + nt) * 12 + ktp) * 32 + lane) * 8 + (kt_in * 2 + reg) * 2 + par;
    dst[off] = __float2half_rn(v);
}

// ===========================================================================
// Tail fold: Wcat[l][i][k] = (k<256) ? sum_j f1w[l][i][j]*Wo[l][j][k]
//                                    : f1w[l][i][k];  c0[l][i] = f1w_l@bo
// ===========================================================================
__global__ void prep_wc_kernel(const float* __restrict__ Wo, const float* __restrict__ bo,
                               const float* __restrict__ f1w,
                               float* __restrict__ wcat, float* __restrict__ c0) {
    int l = blockIdx.x >> 7;
    int i = blockIdx.x & 127;
    int k = threadIdx.x;
    const float* f1 = f1w + ((size_t)l * 128 + i) * 384;
    float v;
    if (k < 256) {
        const float* wo = Wo + (size_t)l * 256 * 256;
        float s = 0.f;
#pragma unroll 4
        for (int j = 0; j < 256; j++) s = fmaf(f1[j], wo[j * 256 + k], s);
        v = s;
    } else {
        v = f1[k];
    }
    wcat[((size_t)l * 128 + i) * 384 + k] = v;
    if (k == 0) {
        const float* bol = bo + l * 256;
        float s = 0.f;
#pragma unroll 4
        for (int j = 0; j < 256; j++) s = fmaf(f1[j], bol[j], s);
        c0[l * 128 + i] = s;
    }
}

// ===========================================================================
// KV projection kernel v6: fp16 mma m16n8k16, persistent CTAs, double-buffered
// fragment-permuted A; convert(i+1) after epilogue(i), one barrier/iteration.
// ===========================================================================
struct KvParams {
    const __half* Bp;
    const float *bk, *bv;
    __half* C;
    int DIV, nblk;
    const float *ts, *etm, *tw, *tb;
    const float *Adense, *nf, *memv, *ef;
    const int *idx, *eidx;
};

#define KV_DSMEM (2 * 49152)

__device__ __forceinline__ void kv_stash_h2(uint32_t* As, int m, int k, uint32_t h2) {
    int kt = k >> 4, mi = m >> 4;
    int r16 = m & 15, gid = r16 & 7, hi_r = r16 >> 3;
    int klo = k & 15, tg = (klo & 7) >> 1;
    int reg = hi_r + ((klo >> 3) << 1);
    As[(((kt * 4 + mi) * 32) + gid * 4 + tg) * 4 + reg] = h2;
}

template <int DENSE>
__device__ __forceinline__ void kv_convert(uint32_t* As, int bm, const KvParams& p, int tid) {
    const int grow = tid >> 3;
    const int gseg = tid & 7;
    const int m = bm + grow;
    if (DENSE) {
        const float4* s = (const float4*)(p.Adense + (size_t)m * 128);
#pragma unroll
        for (int i = 0; i < 4; i++) {
            int cf = gseg + 8 * i;
            float4 v = s[cf];
            int k = cf * 4;
            kv_stash_h2(As, grow, k, f2h2(v.x, v.y));
            kv_stash_h2(As, grow, k + 2, f2h2(v.z, v.w));
        }
    } else {
        int nd = __ldg(&p.idx[m]);
        const float4* s0 = (const float4*)(p.nf + (size_t)nd * 128);
        const float4* s1 = (const float4*)(p.memv + (size_t)nd * 128);
#pragma unroll
        for (int i = 0; i < 4; i++) {
            int cf = gseg + 8 * i;
            float4 x = s0[cf], y = s1[cf];
            int k = cf * 4;
            kv_stash_h2(As, grow, k, f2h2(x.x + y.x, x.y + y.y));
            kv_stash_h2(As, grow, k + 2, f2h2(x.z + y.z, x.w + y.w));
        }
    }
    {
        int e = __ldg(&p.eidx[m]);
        const float4* s = (const float4*)(p.ef + (size_t)e * 128);
#pragma unroll
        for (int i = 0; i < 4; i++) {
            int cf = gseg + 8 * i;
            float4 v = s[cf];
            int k = cf * 4;
            kv_stash_h2(As, grow, 128 + k, f2h2(v.x, v.y));
            kv_stash_h2(As, grow, 128 + k + 2, f2h2(v.z, v.w));
        }
    }
    float dt = __ldg(&p.ts[m / p.DIV]) - __ldg(&p.etm[m]);
#pragma unroll
    for (int i = 0; i < 4; i++) {
        int j0 = (gseg + 8 * i) * 4;
        float c0 = __cosf(fmaf(dt, __ldg(&p.tw[j0 + 0]), __ldg(&p.tb[j0 + 0])));
        float c1 = __cosf(fmaf(dt, __ldg(&p.tw[j0 + 1]), __ldg(&p.tb[j0 + 1])));
        float c2 = __cosf(fmaf(dt, __ldg(&p.tw[j0 + 2]), __ldg(&p.tb[j0 + 2])));
        float c3 = __cosf(fmaf(dt, __ldg(&p.tw[j0 + 3]), __ldg(&p.tb[j0 + 3])));
        kv_stash_h2(As, grow, 256 + j0, f2h2(c0, c1));
        kv_stash_h2(As, grow, 256 + j0 + 2, f2h2(c2, c3));
    }
}

template <int DENSE>
__global__ void __launch_bounds__(512, 1) kv_kernel(KvParams p) {
    extern __shared__ char smem[];
    uint32_t* perm = (uint32_t*)smem;

    const int tid = threadIdx.x;
    const int lane = tid & 31;
    const int wid = tid >> 5;
    const int gID = lane >> 2;
    const int tg = lane & 3;
    const char* bpw = (const char*)p.Bp + (size_t)(wid * 4) * 6144;

    int blk = blockIdx.x;
    if (blk < p.nblk) kv_convert<DENSE>(perm, blk * 64, p, tid);
    __syncthreads();

    int parity = 0;
#pragma unroll 1
    for (; blk < p.nblk; blk += gridDim.x) {
        const int bm = blk * 64;
        const uint4* As4 = (const uint4*)(perm + parity * 12288);

        float acc[4][4][4];
#pragma unroll
        for (int mi = 0; mi < 4; mi++)
#pragma unroll
            for (int nj = 0; nj < 4; nj++)
#pragma unroll
                for (int q = 0; q < 4; q++) acc[mi][nj][q] = 0.f;

        uint4 bA[4], bB[4];

#define KV_LDB(buf, ktp_) { \
    _Pragma("unroll") \
    for (int nj = 0; nj < 4; nj++) \
        buf[nj] = *(const uint4*)(bpw + (size_t)nj * 6144 + (ktp_) * 512 + lane * 16); }

#define KV_STEP(buf, ktp_) { \
    _Pragma("unroll") \
    for (int kt_in = 0; kt_in < 2; kt_in++) { \
        const int kt = (ktp_) * 2 + kt_in; \
        _Pragma("unroll") \
        for (int mi = 0; mi < 4; mi++) { \
            uint4 av = As4[(kt * 4 + mi) * 32 + lane]; \
            uint32_t aa[4] = {av.x, av.y, av.z, av.w}; \
            _Pragma("unroll") \
            for (int nj = 0; nj < 4; nj++) { \
                uint32_t b0 = kt_in ? buf[nj].z : buf[nj].x; \
                uint32_t b1 = kt_in ? buf[nj].w : buf[nj].y; \
                mma_f16(acc[mi][nj], aa, b0, b1); \
            } \
        } \
    } }

        KV_LDB(bA, 0);
#pragma unroll 1
        for (int ktp = 0; ktp < 12; ktp += 2) {
            KV_LDB(bB, ktp + 1);
            KV_STEP(bA, ktp);
            if (ktp + 2 < 12) KV_LDB(bA, ktp + 2);
            KV_STEP(bB, ktp + 1);
        }
#undef KV_LDB
#undef KV_STEP

#pragma unroll
        for (int mi = 0; mi < 4; mi++) {
            const int r_lo = bm + mi * 16 + gID;
            __half* clo = p.C + (size_t)r_lo * 512;
            __half* chi = clo + (size_t)8 * 512;
#pragma unroll
            for (int nj = 0; nj < 4; nj++) {
                const int col = wid * 32 + nj * 8 + tg * 2;
                const float b0 = (col < 256) ? __ldg(&p.bk[col]) : __ldg(&p.bv[col - 256]);
                const float b1 = (col + 1 < 256) ? __ldg(&p.bk[col + 1]) : __ldg(&p.bv[col + 1 - 256]);
                *(__half2*)(clo + col) = __floats2half2_rn(acc[mi][nj][0] + b0, acc[mi][nj][1] + b1);
                *(__half2*)(chi + col) = __floats2half2_rn(acc[mi][nj][2] + b0, acc[mi][nj][3] + b1);
            }
        }

        {
            int nxt = blk + gridDim.x;
            if (nxt < p.nblk)
                kv_convert<DENSE>(perm + (parity ^ 1) * 12288, nxt * 64, p, tid);
        }
        __syncthreads();
        parity ^= 1;
    }
}

// ===========================================================================
// fp16 mma.sync GEMM m16n8k16 (Q / fused-fc1 / fc2): CTA = 128(m) x 128(n).
// As/Bs: half2 lanes, 32-k chunk = 16 uint32/row, row stride 20 (bank-clean).
// cbias: extra per-col bias added ONLY for rows with invalid[m]==0 (pre-relu).
// ===========================================================================
struct TcParams {
    int Kdim, ldA, ldC;
    const float* W;
    const float* bias;
    const float* cbias;
    float* C;
    int relu;
    const unsigned char* invalid;
    const float *Adense, *nf, *memv, *st;
    const int *idx;
};

template <int MODE>
__global__ void __launch_bounds__(256) mma_gemm(TcParams p) {
    __shared__ uint32_t As[128][20];
    __shared__ uint32_t Bs[128][20];
    const int tid = threadIdx.x;
    const int lane = tid & 31;
    const int wid = tid >> 5;
    const int bm = blockIdx.x * 128;
    const int noff = blockIdx.y * 128;
    const float* W = p.W + (size_t)noff * p.Kdim;
    const float* bias = p.bias + noff;
    const int row = tid >> 1;
    const int seg = tid & 1;
    const int m = bm + row;
    const int wr = (wid >> 1) * 32;
    const int wc = (wid & 1) * 64;
    const int groupID = lane >> 2;
    const int tg = lane & 3;

    float acc[2][8][4];
#pragma unroll
    for (int mi = 0; mi < 2; mi++)
#pragma unroll
        for (int nj = 0; nj < 8; nj++)
#pragma unroll
            for (int q = 0; q < 4; q++) acc[mi][nj][q] = 0.f;

#pragma unroll 1
    for (int k0 = 0; k0 < p.Kdim; k0 += 32) {
        const int kb = k0 + seg * 16;
        // ---- stage A (128 x 32 fp16): each thread does a 16-float half-row ----
        {
            const float* s0 = nullptr;
            const float* s1 = nullptr;
            if constexpr (MODE == MODE_PLAIN) {
                s0 = p.Adense + (size_t)m * p.ldA + kb;
            } else if constexpr (MODE == MODE_QGATHER) {
                if (kb < 128) {
                    int nd = __ldg(&p.idx[m]);
                    s0 = p.nf + (size_t)nd * 128 + kb;
                    s1 = p.memv + (size_t)nd * 128 + kb;
                } else {
                    s0 = p.st + (kb - 128);
                }
            } else {  // MODE_CONCAT
                if (kb < 256) {
                    s0 = p.Adense + (size_t)m * 256 + kb;
                } else {
                    int nd = __ldg(&p.idx[m]);
                    s0 = p.nf + (size_t)nd * 128 + (kb - 256);
                    s1 = p.memv + (size_t)nd * 128 + (kb - 256);
                }
            }
            uint32_t h[8];
#pragma unroll
            for (int i = 0; i < 4; i++) {
                float4 v = *(const float4*)(s0 + i * 4);
                if (s1) {
                    float4 w = *(const float4*)(s1 + i * 4);
                    v.x += w.x; v.y += w.y; v.z += w.z; v.w += w.w;
                }
                h[i * 2 + 0] = f2h2(v.x, v.y);
                h[i * 2 + 1] = f2h2(v.z, v.w);
            }
            *(uint4*)&As[row][seg * 8] = make_uint4(h[0], h[1], h[2], h[3]);
            *(uint4*)&As[row][seg * 8 + 4] = make_uint4(h[4], h[5], h[6], h[7]);
        }
        // ---- stage B (128 x 32 fp16) ----
        {
            const float* wsrc = W + (size_t)row * p.Kdim + kb;
            uint32_t h[8];
#pragma unroll
            for (int i = 0; i < 4; i++) {
                float4 v = *(const float4*)(wsrc + i * 4);
                h[i * 2 + 0] = f2h2(v.x, v.y);
                h[i * 2 + 1] = f2h2(v.z, v.w);
            }
            *(uint4*)&Bs[row][seg * 8] = make_uint4(h[0], h[1], h[2], h[3]);
            *(uint4*)&Bs[row][seg * 8 + 4] = make_uint4(h[4], h[5], h[6], h[7]);
        }
        __syncthreads();
        // ---- 2 x k16 mma steps ----
#pragma unroll
        for (int kt = 0; kt < 2; kt++) {
            const int cb = kt * 8;
            uint32_t a[2][4];
#pragma unroll
            for (int mi = 0; mi < 2; mi++) {
                int r0 = wr + mi * 16 + groupID;
                a[mi][0] = As[r0][cb + tg];
                a[mi][1] = As[r0 + 8][cb + tg];
                a[mi][2] = As[r0][cb + 4 + tg];
                a[mi][3] = As[r0 + 8][cb + 4 + tg];
            }
#pragma unroll
            for (int nj = 0; nj < 8; nj++) {
                int nb_ = wc + nj * 8 + groupID;
                uint32_t b0 = Bs[nb_][cb + tg];
                uint32_t b1 = Bs[nb_][cb + 4 + tg];
                mma_f16(acc[0][nj], a[0], b0, b1);
                mma_f16(acc[1][nj], a[1], b0, b1);
            }
        }
        __syncthreads();
    }

#pragma unroll
    for (int mi = 0; mi < 2; mi++) {
        const int r_lo = bm + wr + mi * 16 + groupID;
        const int r_hi = r_lo + 8;
        const bool z_lo = (p.invalid != nullptr) && p.invalid[r_lo];
        const bool z_hi = (p.invalid != nullptr) && p.invalid[r_hi];
        float* clo = p.C + (size_t)r_lo * p.ldC + noff;
        float* chi = p.C + (size_t)r_hi * p.ldC + noff;
#pragma unroll
        for (int nj = 0; nj < 8; nj++) {
            const int cl = wc + nj * 8 + tg * 2;
            const float b0 = __ldg(&bias[cl]);
            const float b1 = __ldg(&bias[cl + 1]);
            float cb0 = 0.f, cb1 = 0.f;
            if (p.cbias) {
                cb0 = __ldg(&p.cbias[noff + cl]);
                cb1 = __ldg(&p.cbias[noff + cl + 1]);
            }
            float v00 = acc[mi][nj][0] + b0 + (z_lo ? 0.f : cb0);
            float v01 = acc[mi][nj][1] + b1 + (z_lo ? 0.f : cb1);
            float v10 = acc[mi][nj][2] + b0 + (z_hi ? 0.f : cb0);
            float v11 = acc[mi][nj][3] + b1 + (z_hi ? 0.f : cb1);
            if (p.relu) {
                v00 = fmaxf(v00, 0.f); v01 = fmaxf(v01, 0.f);
                v10 = fmaxf(v10, 0.f); v11 = fmaxf(v11, 0.f);
            }
            *(float2*)(clo + cl) = make_float2(v00, v01);
            *(float2*)(chi + cl) = make_float2(v10, v11);
        }
    }
}

__global__ void st_kernel(const float* __restrict__ b) {
    g_st[threadIdx.x] = __cosf(b[threadIdx.x]);
}

// ---------------------------------------------------------------------------
// Temporal attention (kv fp16); zeroes output rows with no valid neighbor.
// ---------------------------------------------------------------------------
__global__ void attn_kernel(const float* __restrict__ q, const __half* __restrict__ kv,
                            const int* __restrict__ nbrs, float* __restrict__ outp,
                            unsigned char* __restrict__ invalid) {
    const int r = blockIdx.x;
    const int tid = threadIdx.x;
    const int warp = tid >> 5;
    const int lane = tid & 31;
    __shared__ float sq[256];
    __shared__ float sc[2][KNB];
    __shared__ float swt[2][KNB];
    __shared__ int smask[KNB];
    __shared__ int sinv;

    if (tid < 256) sq[tid] = q[(size_t)r * 256 + tid];
    if (tid < KNB) smask[tid] = (nbrs[r * KNB + tid] != 0) ? 1 : 0;
    __syncthreads();
    if (tid == 0) {
        int any = 0;
#pragma unroll
        for (int k = 0; k < KNB; k++) any |= smask[k];
        if (!any) smask[KNB - 1] = 1;
        sinv = !any;
        invalid[r] = (unsigned char)(!any);
    }
    __syncthreads();

    if (warp < KNB) {
        const __half* kp = kv + ((size_t)r * KNB + warp) * 512;
        float s0 = 0.f, s1 = 0.f;
#pragma unroll
        for (int i = 0; i < 4; i++) {
            int d = lane + 32 * i;
            s0 = fmaf(sq[d], __half2float(__ldg(&kp[d])), s0);
            s1 = fmaf(sq[128 + d], __half2float(__ldg(&kp[128 + d])), s1);
        }
#pragma unroll
        for (int o = 16; o > 0; o >>= 1) {
            s0 += __shfl_down_sync(0xffffffffu, s0, o);
            s1 += __shfl_down_sync(0xffffffffu, s1, o);
        }
        if (lane == 0) {
            const float scale = 0.08838834764831845f;
            sc[0][warp] = smask[warp] ? s0 * scale : -1e9f;
            sc[1][warp] = smask[warp] ? s1 * scale : -1e9f;
        }
    }
    __syncthreads();

    if (tid < 2) {
        float mx = -3.0e38f;
#pragma unroll
        for (int k = 0; k < KNB; k++) mx = fmaxf(mx, sc[tid][k]);
        float sum = 0.f;
#pragma unroll
        for (int k = 0; k < KNB; k++) {
            float e = __expf(sc[tid][k] - mx);
            swt[tid][k] = e;
            sum += e;
        }
        float inv = 1.0f / sum;
#pragma unroll
        for (int k = 0; k < KNB; k++) swt[tid][k] *= inv;
    }
    __syncthreads();

    if (tid < 256) {
        int h = tid >> 7;
        float o = 0.f;
#pragma unroll
        for (int k = 0; k < KNB; k++)
            o = fmaf(swt[h][k], __half2float(__ldg(&kv[((size_t)r * KNB + k) * 512 + 256 + tid])), o);
        outp[(size_t)r * 256 + tid] = sinv ? 0.f : o;
    }
}

// ---------------------------------------------------------------------------
// Host side
// ---------------------------------------------------------------------------
static void launch_mma(int mode, int M, int nchunks, const TcParams& p, cudaStream_t s) {
    dim3 grid(M / 128, nchunks);
    switch (mode) {
        case MODE_PLAIN:   mma_gemm<MODE_PLAIN><<<grid, 256, 0, s>>>(p); break;
        case MODE_QGATHER: mma_gemm<MODE_QGATHER><<<grid, 256, 0, s>>>(p); break;
        case MODE_CONCAT:  mma_gemm<MODE_CONCAT><<<grid, 256, 0, s>>>(p); break;
    }
}

extern "C" void kernel_launch(void* const* d_in, const int* in_sizes, int n_in,
                              void* d_out, int out_size) {
    const float* nf   = (const float*)d_in[0];
    const float* mem  = (const float*)d_in[1];
    const float* ef   = (const float*)d_in[2];
    const float* tw   = (const float*)d_in[3];
    const float* tb   = (const float*)d_in[4];
    const float* Wq   = (const float*)d_in[5];
    const float* bq   = (const float*)d_in[6];
    const float* Wk   = (const float*)d_in[7];
    const float* bk   = (const float*)d_in[8];
    const float* Wv   = (const float*)d_in[9];
    const float* bv   = (const float*)d_in[10];
    const float* Wo   = (const float*)d_in[11];
    const float* bo   = (const float*)d_in[12];
    const float* f1w  = (const float*)d_in[13];
    const float* f1b  = (const float*)d_in[14];
    const float* f2w  = (const float*)d_in[15];
    const float* f2b  = (const float*)d_in[16];
    const int*   src  = (const int*)d_in[17];
    const float* ts   = (const float*)d_in[18];
    const int*   nb2  = (const int*)d_in[19];
    const int*   ei2  = (const int*)d_in[20];
    const float* tm2  = (const float*)d_in[21];
    const int*   nb1  = (const int*)d_in[22];
    const int*   ei1  = (const int*)d_in[23];
    const float* tm1  = (const float*)d_in[24];
    float* out = (float*)d_out;

    float *pst, *pq1, *pattn1, *ph1, *pemb1;
    float *pq2, *pattn2, *ph2, *pwcat, *pc0;
    __half *pkv1, *pkv2, *pbph;
    unsigned char *pinv1, *pinv2;
    cudaGetSymbolAddress((void**)&pst, g_st);
    cudaGetSymbolAddress((void**)&pkv1, g_kv1);
    cudaGetSymbolAddress((void**)&pq1, g_q1);
    cudaGetSymbolAddress((void**)&pattn1, g_attn1);
    cudaGetSymbolAddress((void**)&ph1, g_h1);
    cudaGetSymbolAddress((void**)&pemb1, g_emb1);
    cudaGetSymbolAddress((void**)&pinv1, g_inv1);
    cudaGetSymbolAddress((void**)&pkv2, g_kv2);
    cudaGetSymbolAddress((void**)&pq2, g_q2);
    cudaGetSymbolAddress((void**)&pattn2, g_attn2);
    cudaGetSymbolAddress((void**)&ph2, g_h2);
    cudaGetSymbolAddress((void**)&pinv2, g_inv2);
    cudaGetSymbolAddress((void**)&pbph, g_bph);
    cudaGetSymbolAddress((void**)&pwcat, g_wcat);
    cudaGetSymbolAddress((void**)&pc0, g_c0);

    static cudaStream_t s_side = nullptr;
    static cudaEvent_t ev_fork = nullptr, ev_join = nullptr;
    if (s_side == nullptr) {
        cudaStreamCreateWithFlags(&s_side, cudaStreamNonBlocking);
        cudaEventCreateWithFlags(&ev_fork, cudaEventDisableTiming);
        cudaEventCreateWithFlags(&ev_join, cudaEventDisableTiming);
        cudaFuncSetAttribute(kv_kernel<0>, cudaFuncAttributeMaxDynamicSharedMemorySize, KV_DSMEM);
        cudaFuncSetAttribute(kv_kernel<1>, cudaFuncAttributeMaxDynamicSharedMemorySize, KV_DSMEM);
    }

    const cudaStream_t s0 = 0;

    const float* Wq1 = Wq + 256 * 256;  const float* bq1 = bq + 256;
    const float* bk1 = bk + 256;
    const float* bv1 = bv + 256;
    const float* f2w1 = f2w + 128 * 128; const float* f2b1 = f2b + 128;

    // ---- fork immediately: side stream does st + prep_wc + Q1 + Q2 ----
    cudaEventRecord(ev_fork, s0);
    cudaStreamWaitEvent(s_side, ev_fork, 0);

    st_kernel<<<1, 128, 0, s_side>>>(tb);
    prep_wc_kernel<<<256, 384, 0, s_side>>>(Wo, bo, f1w, pwcat, pc0);
    {   // Q1 (fp16): [20480,256], 2 col chunks
        TcParams p{};
        p.Kdim = 256; p.ldC = 256;
        p.W = Wq; p.bias = bq; p.C = pq1;
        p.nf = nf; p.memv = mem; p.st = pst; p.idx = nb2;
        launch_mma(MODE_QGATHER, N1, 2, p, s_side);
    }
    {   // Q2 (fp16)
        TcParams p{};
        p.Kdim = 256; p.ldC = 256;
        p.W = Wq1; p.bias = bq1; p.C = pq2;
        p.nf = nf; p.memv = mem; p.st = pst; p.idx = src;
        launch_mma(MODE_QGATHER, BB, 2, p, s_side);
    }
    cudaEventRecord(ev_join, s_side);

    // ---- main stream: prep_b then KV1 (persistent, 136 SMs) ----
    prep_b_kernel<<<(2 * 512 * 384 + 255) / 256, 256, 0, s0>>>(Wk, Wv, pbph);
    {
        KvParams p{};
        p.Bp = pbph; p.bk = bk; p.bv = bv; p.C = pkv1;
        p.DIV = 100; p.nblk = NP1 / 64;
        p.ts = ts; p.etm = tm1; p.tw = tw; p.tb = tb;
        p.nf = nf; p.memv = mem; p.ef = ef; p.idx = nb1; p.eidx = ei1;
        kv_kernel<0><<<136, 512, KV_DSMEM, s0>>>(p);
    }
    cudaStreamWaitEvent(s0, ev_join, 0);

    attn_kernel<<<N1, 320, 0, s0>>>(pq1, pkv1, nb1, pattn1, pinv1);
    {   // fused O1+fc1 (fp16): K=384 [attn || base], conditional c0, relu
        TcParams p{};
        p.Kdim = 384; p.ldC = 128;
        p.W = pwcat; p.bias = f1b; p.cbias = pc0; p.C = ph1;
        p.Adense = pattn1; p.nf = nf; p.memv = mem; p.idx = nb2;
        p.invalid = pinv1; p.relu = 1;
        launch_mma(MODE_CONCAT, N1, 1, p, s0);
    }
    {   // fc2 L0 (fp16) -> emb1
        TcParams p{};
        p.Kdim = 128; p.ldA = 128; p.ldC = 128;
        p.W = f2w; p.bias = f2b; p.C = pemb1; p.Adense = ph1;
        launch_mma(MODE_PLAIN, N1, 1, p, s0);
    }
    {   // KV2 (fp16, dense, persistent)
        KvParams p{};
        p.Bp = pbph + 512 * 384; p.bk = bk1; p.bv = bv1; p.C = pkv2;
        p.DIV = 10; p.nblk = NP2 / 64;
        p.ts = ts; p.etm = tm2; p.tw = tw; p.tb = tb;
        p.Adense = pemb1; p.ef = ef; p.eidx = ei2;
        kv_kernel<1><<<148, 512, KV_DSMEM, s0>>>(p);
    }
    attn_kernel<<<BB, 320, 0, s0>>>(pq2, pkv2, nb2, pattn2, pinv2);
    {   // fused O2+fc1 L1 (fp16)
        TcParams p{};
        p.Kdim = 384; p.ldC = 128;
        p.W = pwcat + 128 * 384; p.bias = f1b + 128; p.cbias = pc0 + 128; p.C = ph2;
        p.Adense = pattn2; p.nf = nf; p.memv = mem; p.idx = src;
        p.invalid = pinv2; p.relu = 1;
        launch_mma(MODE_CONCAT, BB, 1, p, s0);
    }
    {   // fc2 L1 (fp16) -> out
        TcParams p{};
        p.Kdim = 128; p.ldA = 128; p.ldC = 128;
        p.W = f2w1; p.bias = f2b1; p.C = out; p.Adense = ph2;
        launch_mma(MODE_PLAIN, BB, 1, p, s0);
    }
}

// round 11
// speedup vs baseline: 7.9618x; 1.0207x over previous
#include <cuda_runtime.h>
#include <cuda_fp16.h>
#include <cstdint>

// ---------------------------------------------------------------------------
// Problem constants
// ---------------------------------------------------------------------------
#define KNB 10
#define BB  2048
#define N1  20480
#define NP1 204800
#define NP2 20480
// D = T = 128, QD = 256, KD = 384, H = 2, hd = 128

// ---------------------------------------------------------------------------
// Scratch
// ---------------------------------------------------------------------------
__device__ __half g_kv1[(size_t)NP1 * 512];
__device__ float g_q1 [(size_t)N1  * 256];
__device__ float g_attn1[(size_t)N1 * 256];
__device__ float g_h1 [(size_t)N1  * 128];
__device__ float g_emb1[(size_t)N1 * 128];
__device__ unsigned char g_inv1[N1];
__device__ __half g_kv2[(size_t)NP2 * 512];
__device__ float g_q2 [(size_t)BB  * 256];
__device__ float g_attn2[(size_t)BB * 256];
__device__ float g_h2 [(size_t)BB  * 128];
__device__ unsigned char g_inv2[BB];
// pre-permuted fragment-ordered fp16 weights for KV (2 layers x 512 n x 384 k)
__device__ __half g_bph[2 * 512 * 384];
// folded tail weights: Wcat = [f1w_left@Wo || f1w_right]  (2 layers x 128 x 384)
__device__ float g_wcat[2 * 128 * 384];
__device__ float g_c0[2 * 128];          // f1w_left @ bo per layer
__device__ float g_bq2[2 * 256];         // bq + st @ Wq_right^T per layer

#define MODE_PLAIN      0
#define MODE_QGATHER    1
#define MODE_CONCAT     4

// ---------------------------------------------------------------------------
// fp16 mma helper + fast cosine (FMA-pipe, no MUFU)
// ---------------------------------------------------------------------------
__device__ __forceinline__ void mma_f16(float* c, const uint32_t* a, uint32_t b0, uint32_t b1) {
    asm volatile(
        "mma.sync.aligned.m16n8k16.row.col.f32.f16.f16.f32 "
        "{%0,%1,%2,%3}, {%4,%5,%6,%7}, {%8,%9}, {%0,%1,%2,%3};"
        : "+f"(c[0]), "+f"(c[1]), "+f"(c[2]), "+f"(c[3])
        : "r"(a[0]), "r"(a[1]), "r"(a[2]), "r"(a[3]), "r"(b0), "r"(b1));
}
__device__ __forceinline__ uint32_t f2h2(float a, float b) {
    __half2 h = __floats2half2_rn(a, b);
    return *(uint32_t*)&h;
}

// cos(t) via quadrant reduction + minimax polys; |err| ~ 1e-6, valid |t| < ~1e4.
__device__ __forceinline__ float fast_cos(float t) {
    float qf = rintf(t * 0.6366197723675814f);     // t * 2/pi
    int q = (int)qf;
    float r = fmaf(qf, -1.5707962513f, t);          // pi/2 hi
    r = fmaf(qf, -7.54978942e-8f, r);               // pi/2 lo
    float z = r * r;
    float cp = fmaf(z, fmaf(z, fmaf(z, -1.3888397e-3f, 4.16666418e-2f), -0.5f), 1.0f);
    float sp = r * fmaf(z, fmaf(z, 8.3321608e-3f, -1.66666547e-1f), 1.0f);
    float v = (q & 1) ? sp : cp;
    uint32_t sgn = (uint32_t)((q + 1) & 2) << 30;   // quadrants 1,2 -> negate
    return __uint_as_float(__float_as_uint(v) ^ sgn);
}

// ===========================================================================
// B pre-permutation: Wk||Wv [512 n][384 k] fp32 -> fragment-ordered fp16
// ===========================================================================
__global__ void prep_b_kernel(const float* __restrict__ Wk, const float* __restrict__ Wv,
                              __half* __restrict__ dst) {
    int idx = blockIdx.x * blockDim.x + threadIdx.x;   // 2 * 512 * 384
    if (idx >= 2 * 512 * 384) return;
    int l = idx / (512 * 384);
    int rem = idx - l * (512 * 384);
    int n = rem / 384;
    int k = rem - n * 384;
    const float* W = (n < 256) ? (Wk + (size_t)l * 256 * 384 + (size_t)n * 384)
                               : (Wv + (size_t)l * 256 * 384 + (size_t)(n - 256) * 384);
    float v = W[k];
    int nt = n >> 3, gid = n & 7;
    int ktp = k >> 5, k32 = k & 31;
    int kt_in = k32 >> 4, klo = k32 & 15;
    int tg = (klo & 7) >> 1, reg = klo >> 3, par = k & 1;
    int lane = gid * 4 + tg;
    size_t off = ((((size_t)l * 64 + nt) * 12 + ktp) * 32 + lane) * 8 + (kt_in * 2 + reg) * 2 + par;
    dst[off] = __float2half_rn(v);
}

// ===========================================================================
// Tail fold: Wcat / c0 (see R9) — runs on side stream
// ===========================================================================
__global__ void prep_wc_kernel(const float* __restrict__ Wo, const float* __restrict__ bo,
                               const float* __restrict__ f1w,
                               float* __restrict__ wcat, float* __restrict__ c0) {
    int l = blockIdx.x >> 7;
    int i = blockIdx.x & 127;
    int k = threadIdx.x;
    const float* f1 = f1w + ((size_t)l * 128 + i) * 384;
    float v;
    if (k < 256) {
        const float* wo = Wo + (size_t)l * 256 * 256;
        float s = 0.f;
#pragma unroll 4
        for (int j = 0; j < 256; j++) s = fmaf(f1[j], wo[j * 256 + k], s);
        v = s;
    } else {
        v = f1[k];
    }
    wcat[((size_t)l * 128 + i) * 384 + k] = v;
    if (k == 0) {
        const float* bol = bo + l * 256;
        float s = 0.f;
#pragma unroll 4
        for (int j = 0; j < 256; j++) s = fmaf(f1[j], bol[j], s);
        c0[l * 128 + i] = s;
    }
}

// ===========================================================================
// Q-bias fold: bq2[l][n] = bq[l][n] + sum_j cos(tb[j]) * Wq[l][n][128+j]
// grid 2 (layer), 256 threads (n)
// ===========================================================================
__global__ void prep_bq_kernel(const float* __restrict__ Wq, const float* __restrict__ bq,
                               const float* __restrict__ tb, float* __restrict__ bq2) {
    int l = blockIdx.x;
    int n = threadIdx.x;
    __shared__ float st[128];
    if (n < 128) st[n] = __cosf(tb[n]);
    __syncthreads();
    const float* w = Wq + (((size_t)l * 256 + n) * 256) + 128;
    float s = bq[l * 256 + n];
#pragma unroll 4
    for (int j = 0; j < 128; j++) s = fmaf(st[j], w[j], s);
    bq2[l * 256 + n] = s;
}

// ===========================================================================
// KV projection kernel v7: fp16 mma m16n8k16, persistent CTAs, double-buffered
// fragment-permuted A; convert uses fast_cos (FMA pipe, overlaps tensor MMA).
// ===========================================================================
struct KvParams {
    const __half* Bp;
    const float *bk, *bv;
    __half* C;
    int DIV, nblk;
    const float *ts, *etm, *tw, *tb;
    const float *Adense, *nf, *memv, *ef;
    const int *idx, *eidx;
};

#define KV_DSMEM (2 * 49152)

__device__ __forceinline__ void kv_stash_h2(uint32_t* As, int m, int k, uint32_t h2) {
    int kt = k >> 4, mi = m >> 4;
    int r16 = m & 15, gid = r16 & 7, hi_r = r16 >> 3;
    int klo = k & 15, tg = (klo & 7) >> 1;
    int reg = hi_r + ((klo >> 3) << 1);
    As[(((kt * 4 + mi) * 32) + gid * 4 + tg) * 4 + reg] = h2;
}

template <int DENSE>
__device__ __forceinline__ void kv_convert(uint32_t* As, int bm, const KvParams& p, int tid) {
    const int grow = tid >> 3;
    const int gseg = tid & 7;
    const int m = bm + grow;
    if (DENSE) {
        const float4* s = (const float4*)(p.Adense + (size_t)m * 128);
#pragma unroll
        for (int i = 0; i < 4; i++) {
            int cf = gseg + 8 * i;
            float4 v = s[cf];
            int k = cf * 4;
            kv_stash_h2(As, grow, k, f2h2(v.x, v.y));
            kv_stash_h2(As, grow, k + 2, f2h2(v.z, v.w));
        }
    } else {
        int nd = __ldg(&p.idx[m]);
        const float4* s0 = (const float4*)(p.nf + (size_t)nd * 128);
        const float4* s1 = (const float4*)(p.memv + (size_t)nd * 128);
#pragma unroll
        for (int i = 0; i < 4; i++) {
            int cf = gseg + 8 * i;
            float4 x = s0[cf], y = s1[cf];
            int k = cf * 4;
            kv_stash_h2(As, grow, k, f2h2(x.x + y.x, x.y + y.y));
            kv_stash_h2(As, grow, k + 2, f2h2(x.z + y.z, x.w + y.w));
        }
    }
    {
        int e = __ldg(&p.eidx[m]);
        const float4* s = (const float4*)(p.ef + (size_t)e * 128);
#pragma unroll
        for (int i = 0; i < 4; i++) {
            int cf = gseg + 8 * i;
            float4 v = s[cf];
            int k = cf * 4;
            kv_stash_h2(As, grow, 128 + k, f2h2(v.x, v.y));
            kv_stash_h2(As, grow, 128 + k + 2, f2h2(v.z, v.w));
        }
    }
    float dt = __ldg(&p.ts[m / p.DIV]) - __ldg(&p.etm[m]);
#pragma unroll
    for (int i = 0; i < 4; i++) {
        int j0 = (gseg + 8 * i) * 4;
        float c0 = fast_cos(fmaf(dt, __ldg(&p.tw[j0 + 0]), __ldg(&p.tb[j0 + 0])));
        float c1 = fast_cos(fmaf(dt, __ldg(&p.tw[j0 + 1]), __ldg(&p.tb[j0 + 1])));
        float c2 = fast_cos(fmaf(dt, __ldg(&p.tw[j0 + 2]), __ldg(&p.tb[j0 + 2])));
        float c3 = fast_cos(fmaf(dt, __ldg(&p.tw[j0 + 3]), __ldg(&p.tb[j0 + 3])));
        kv_stash_h2(As, grow, 256 + j0, f2h2(c0, c1));
        kv_stash_h2(As, grow, 256 + j0 + 2, f2h2(c2, c3));
    }
}

template <int DENSE>
__global__ void __launch_bounds__(512, 1) kv_kernel(KvParams p) {
    extern __shared__ char smem[];
    uint32_t* perm = (uint32_t*)smem;

    const int tid = threadIdx.x;
    const int lane = tid & 31;
    const int wid = tid >> 5;
    const int gID = lane >> 2;
    const int tg = lane & 3;
    const char* bpw = (const char*)p.Bp + (size_t)(wid * 4) * 6144;

    int blk = blockIdx.x;
    if (blk < p.nblk) kv_convert<DENSE>(perm, blk * 64, p, tid);
    __syncthreads();

    int parity = 0;
#pragma unroll 1
    for (; blk < p.nblk; blk += gridDim.x) {
        const int bm = blk * 64;
        const uint4* As4 = (const uint4*)(perm + parity * 12288);

        float acc[4][4][4];
#pragma unroll
        for (int mi = 0; mi < 4; mi++)
#pragma unroll
            for (int nj = 0; nj < 4; nj++)
#pragma unroll
                for (int q = 0; q < 4; q++) acc[mi][nj][q] = 0.f;

        uint4 bA[4], bB[4];

#define KV_LDB(buf, ktp_) { \
    _Pragma("unroll") \
    for (int nj = 0; nj < 4; nj++) \
        buf[nj] = *(const uint4*)(bpw + (size_t)nj * 6144 + (ktp_) * 512 + lane * 16); }

#define KV_STEP(buf, ktp_) { \
    _Pragma("unroll") \
    for (int kt_in = 0; kt_in < 2; kt_in++) { \
        const int kt = (ktp_) * 2 + kt_in; \
        _Pragma("unroll") \
        for (int mi = 0; mi < 4; mi++) { \
            uint4 av = As4[(kt * 4 + mi) * 32 + lane]; \
            uint32_t aa[4] = {av.x, av.y, av.z, av.w}; \
            _Pragma("unroll") \
            for (int nj = 0; nj < 4; nj++) { \
                uint32_t b0 = kt_in ? buf[nj].z : buf[nj].x; \
                uint32_t b1 = kt_in ? buf[nj].w : buf[nj].y; \
                mma_f16(acc[mi][nj], aa, b0, b1); \
            } \
        } \
    } }

        KV_LDB(bA, 0);
#pragma unroll 1
        for (int ktp = 0; ktp < 12; ktp += 2) {
            KV_LDB(bB, ktp + 1);
            KV_STEP(bA, ktp);
            if (ktp + 2 < 12) KV_LDB(bA, ktp + 2);
            KV_STEP(bB, ktp + 1);
        }
#undef KV_LDB
#undef KV_STEP

#pragma unroll
        for (int mi = 0; mi < 4; mi++) {
            const int r_lo = bm + mi * 16 + gID;
            __half* clo = p.C + (size_t)r_lo * 512;
            __half* chi = clo + (size_t)8 * 512;
#pragma unroll
            for (int nj = 0; nj < 4; nj++) {
                const int col = wid * 32 + nj * 8 + tg * 2;
                const float b0 = (col < 256) ? __ldg(&p.bk[col]) : __ldg(&p.bv[col - 256]);
                const float b1 = (col + 1 < 256) ? __ldg(&p.bk[col + 1]) : __ldg(&p.bv[col + 1 - 256]);
                *(__half2*)(clo + col) = __floats2half2_rn(acc[mi][nj][0] + b0, acc[mi][nj][1] + b1);
                *(__half2*)(chi + col) = __floats2half2_rn(acc[mi][nj][2] + b0, acc[mi][nj][3] + b1);
            }
        }

        {
            int nxt = blk + gridDim.x;
            if (nxt < p.nblk)
                kv_convert<DENSE>(perm + (parity ^ 1) * 12288, nxt * 64, p, tid);
        }
        __syncthreads();
        parity ^= 1;
    }
}

// ===========================================================================
// fp16 mma.sync GEMM m16n8k16 (Q / fused-fc1 / fc2): CTA = 128(m) x 128(n).
// ldW: weight row stride (= Kdim except Q, where rows keep stride 256).
// ===========================================================================
struct TcParams {
    int Kdim, ldA, ldC, ldW;
    const float* W;
    const float* bias;
    const float* cbias;
    float* C;
    int relu;
    const unsigned char* invalid;
    const float *Adense, *nf, *memv;
    const int *idx;
};

template <int MODE>
__global__ void __launch_bounds__(256) mma_gemm(TcParams p) {
    __shared__ uint32_t As[128][20];
    __shared__ uint32_t Bs[128][20];
    const int tid = threadIdx.x;
    const int lane = tid & 31;
    const int wid = tid >> 5;
    const int bm = blockIdx.x * 128;
    const int noff = blockIdx.y * 128;
    const float* W = p.W + (size_t)noff * p.ldW;
    const float* bias = p.bias + noff;
    const int row = tid >> 1;
    const int seg = tid & 1;
    const int m = bm + row;
    const int wr = (wid >> 1) * 32;
    const int wc = (wid & 1) * 64;
    const int groupID = lane >> 2;
    const int tg = lane & 3;

    float acc[2][8][4];
#pragma unroll
    for (int mi = 0; mi < 2; mi++)
#pragma unroll
        for (int nj = 0; nj < 8; nj++)
#pragma unroll
            for (int q = 0; q < 4; q++) acc[mi][nj][q] = 0.f;

#pragma unroll 1
    for (int k0 = 0; k0 < p.Kdim; k0 += 32) {
        const int kb = k0 + seg * 16;
        {
            const float* s0 = nullptr;
            const float* s1 = nullptr;
            if constexpr (MODE == MODE_PLAIN) {
                s0 = p.Adense + (size_t)m * p.ldA + kb;
            } else if constexpr (MODE == MODE_QGATHER) {
                // Kdim = 128: pure base gather
                int nd = __ldg(&p.idx[m]);
                s0 = p.nf + (size_t)nd * 128 + kb;
                s1 = p.memv + (size_t)nd * 128 + kb;
            } else {  // MODE_CONCAT
                if (kb < 256) {
                    s0 = p.Adense + (size_t)m * 256 + kb;
                } else {
                    int nd = __ldg(&p.idx[m]);
                    s0 = p.nf + (size_t)nd * 128 + (kb - 256);
                    s1 = p.memv + (size_t)nd * 128 + (kb - 256);
                }
            }
            uint32_t h[8];
#pragma unroll
            for (int i = 0; i < 4; i++) {
                float4 v = *(const float4*)(s0 + i * 4);
                if (s1) {
                    float4 w = *(const float4*)(s1 + i * 4);
                    v.x += w.x; v.y += w.y; v.z += w.z; v.w += w.w;
                }
                h[i * 2 + 0] = f2h2(v.x, v.y);
                h[i * 2 + 1] = f2h2(v.z, v.w);
            }
            *(uint4*)&As[row][seg * 8] = make_uint4(h[0], h[1], h[2], h[3]);
            *(uint4*)&As[row][seg * 8 + 4] = make_uint4(h[4], h[5], h[6], h[7]);
        }
        {
            const float* wsrc = W + (size_t)row * p.ldW + kb;
            uint32_t h[8];
#pragma unroll
            for (int i = 0; i < 4; i++) {
                float4 v = *(const float4*)(wsrc + i * 4);
                h[i * 2 + 0] = f2h2(v.x, v.y);
                h[i * 2 + 1] = f2h2(v.z, v.w);
            }
            *(uint4*)&Bs[row][seg * 8] = make_uint4(h[0], h[1], h[2], h[3]);
            *(uint4*)&Bs[row][seg * 8 + 4] = make_uint4(h[4], h[5], h[6], h[7]);
        }
        __syncthreads();
#pragma unroll
        for (int kt = 0; kt < 2; kt++) {
            const int cb = kt * 8;
            uint32_t a[2][4];
#pragma unroll
            for (int mi = 0; mi < 2; mi++) {
                int r0 = wr + mi * 16 + groupID;
                a[mi][0] = As[r0][cb + tg];
                a[mi][1] = As[r0 + 8][cb + tg];
                a[mi][2] = As[r0][cb + 4 + tg];
                a[mi][3] = As[r0 + 8][cb + 4 + tg];
            }
#pragma unroll
            for (int nj = 0; nj < 8; nj++) {
                int nb_ = wc + nj * 8 + groupID;
                uint32_t b0 = Bs[nb_][cb + tg];
                uint32_t b1 = Bs[nb_][cb + 4 + tg];
                mma_f16(acc[0][nj], a[0], b0, b1);
                mma_f16(acc[1][nj], a[1], b0, b1);
            }
        }
        __syncthreads();
    }

#pragma unroll
    for (int mi = 0; mi < 2; mi++) {
        const int r_lo = bm + wr + mi * 16 + groupID;
        const int r_hi = r_lo + 8;
        const bool z_lo = (p.invalid != nullptr) && p.invalid[r_lo];
        const bool z_hi = (p.invalid != nullptr) && p.invalid[r_hi];
        float* clo = p.C + (size_t)r_lo * p.ldC + noff;
        float* chi = p.C + (size_t)r_hi * p.ldC + noff;
#pragma unroll
        for (int nj = 0; nj < 8; nj++) {
            const int cl = wc + nj * 8 + tg * 2;
            const float b0 = __ldg(&bias[cl]);
            const float b1 = __ldg(&bias[cl + 1]);
            float cb0 = 0.f, cb1 = 0.f;
            if (p.cbias) {
                cb0 = __ldg(&p.cbias[noff + cl]);
                cb1 = __ldg(&p.cbias[noff + cl + 1]);
            }
            float v00 = acc[mi][nj][0] + b0 + (z_lo ? 0.f : cb0);
            float v01 = acc[mi][nj][1] + b1 + (z_lo ? 0.f : cb1);
            float v10 = acc[mi][nj][2] + b0 + (z_hi ? 0.f : cb0);
            float v11 = acc[mi][nj][3] + b1 + (z_hi ? 0.f : cb1);
            if (p.relu) {
                v00 = fmaxf(v00, 0.f); v01 = fmaxf(v01, 0.f);
                v10 = fmaxf(v10, 0.f); v11 = fmaxf(v11, 0.f);
            }
            *(float2*)(clo + cl) = make_float2(v00, v01);
            *(float2*)(chi + cl) = make_float2(v10, v11);
        }
    }
}

// ---------------------------------------------------------------------------
// Temporal attention (kv fp16); zeroes output rows with no valid neighbor.
// ---------------------------------------------------------------------------
__global__ void attn_kernel(const float* __restrict__ q, const __half* __restrict__ kv,
                            const int* __restrict__ nbrs, float* __restrict__ outp,
                            unsigned char* __restrict__ invalid) {
    const int r = blockIdx.x;
    const int tid = threadIdx.x;
    const int warp = tid >> 5;
    const int lane = tid & 31;
    __shared__ float sq[256];
    __shared__ float sc[2][KNB];
    __shared__ float swt[2][KNB];
    __shared__ int smask[KNB];
    __shared__ int sinv;

    if (tid < 256) sq[tid] = q[(size_t)r * 256 + tid];
    if (tid < KNB) smask[tid] = (nbrs[r * KNB + tid] != 0) ? 1 : 0;
    __syncthreads();
    if (tid == 0) {
        int any = 0;
#pragma unroll
        for (int k = 0; k < KNB; k++) any |= smask[k];
        if (!any) smask[KNB - 1] = 1;
        sinv = !any;
        invalid[r] = (unsigned char)(!any);
    }
    __syncthreads();

    if (warp < KNB) {
        const __half* kp = kv + ((size_t)r * KNB + warp) * 512;
        float s0 = 0.f, s1 = 0.f;
#pragma unroll
        for (int i = 0; i < 4; i++) {
            int d = lane + 32 * i;
            s0 = fmaf(sq[d], __half2float(__ldg(&kp[d])), s0);
            s1 = fmaf(sq[128 + d], __half2float(__ldg(&kp[128 + d])), s1);
        }
#pragma unroll
        for (int o = 16; o > 0; o >>= 1) {
            s0 += __shfl_down_sync(0xffffffffu, s0, o);
            s1 += __shfl_down_sync(0xffffffffu, s1, o);
        }
        if (lane == 0) {
            const float scale = 0.08838834764831845f;
            sc[0][warp] = smask[warp] ? s0 * scale : -1e9f;
            sc[1][warp] = smask[warp] ? s1 * scale : -1e9f;
        }
    }
    __syncthreads();

    if (tid < 2) {
        float mx = -3.0e38f;
#pragma unroll
        for (int k = 0; k < KNB; k++) mx = fmaxf(mx, sc[tid][k]);
        float sum = 0.f;
#pragma unroll
        for (int k = 0; k < KNB; k++) {
            float e = __expf(sc[tid][k] - mx);
            swt[tid][k] = e;
            sum += e;
        }
        float inv = 1.0f / sum;
#pragma unroll
        for (int k = 0; k < KNB; k++) swt[tid][k] *= inv;
    }
    __syncthreads();

    if (tid < 256) {
        int h = tid >> 7;
        float o = 0.f;
#pragma unroll
        for (int k = 0; k < KNB; k++)
            o = fmaf(swt[h][k], __half2float(__ldg(&kv[((size_t)r * KNB + k) * 512 + 256 + tid])), o);
        outp[(size_t)r * 256 + tid] = sinv ? 0.f : o;
    }
}

// ---------------------------------------------------------------------------
// Host side
// ---------------------------------------------------------------------------
static void launch_mma(int mode, int M, int nchunks, const TcParams& p, cudaStream_t s) {
    dim3 grid(M / 128, nchunks);
    switch (mode) {
        case MODE_PLAIN:   mma_gemm<MODE_PLAIN><<<grid, 256, 0, s>>>(p); break;
        case MODE_QGATHER: mma_gemm<MODE_QGATHER><<<grid, 256, 0, s>>>(p); break;
        case MODE_CONCAT:  mma_gemm<MODE_CONCAT><<<grid, 256, 0, s>>>(p); break;
    }
}

extern "C" void kernel_launch(void* const* d_in, const int* in_sizes, int n_in,
                              void* d_out, int out_size) {
    const float* nf   = (const float*)d_in[0];
    const float* mem  = (const float*)d_in[1];
    const float* ef   = (const float*)d_in[2];
    const float* tw   = (const float*)d_in[3];
    const float* tb   = (const float*)d_in[4];
    const float* Wq   = (const float*)d_in[5];
    const float* bq   = (const float*)d_in[6];
    const float* Wk   = (const float*)d_in[7];
    const float* bk   = (const float*)d_in[8];
    const float* Wv   = (const float*)d_in[9];
    const float* bv   = (const float*)d_in[10];
    const float* Wo   = (const float*)d_in[11];
    const float* bo   = (const float*)d_in[12];
    const float* f1w  = (const float*)d_in[13];
    const float* f1b  = (const float*)d_in[14];
    const float* f2w  = (const float*)d_in[15];
    const float* f2b  = (const float*)d_in[16];
    const int*   src  = (const int*)d_in[17];
    const float* ts   = (const float*)d_in[18];
    const int*   nb2  = (const int*)d_in[19];
    const int*   ei2  = (const int*)d_in[20];
    const float* tm2  = (const float*)d_in[21];
    const int*   nb1  = (const int*)d_in[22];
    const int*   ei1  = (const int*)d_in[23];
    const float* tm1  = (const float*)d_in[24];
    float* out = (float*)d_out;

    float *pq1, *pattn1, *ph1, *pemb1;
    float *pq2, *pattn2, *ph2, *pwcat, *pc0, *pbq2;
    __half *pkv1, *pkv2, *pbph;
    unsigned char *pinv1, *pinv2;
    cudaGetSymbolAddress((void**)&pkv1, g_kv1);
    cudaGetSymbolAddress((void**)&pq1, g_q1);
    cudaGetSymbolAddress((void**)&pattn1, g_attn1);
    cudaGetSymbolAddress((void**)&ph1, g_h1);
    cudaGetSymbolAddress((void**)&pemb1, g_emb1);
    cudaGetSymbolAddress((void**)&pinv1, g_inv1);
    cudaGetSymbolAddress((void**)&pkv2, g_kv2);
    cudaGetSymbolAddress((void**)&pq2, g_q2);
    cudaGetSymbolAddress((void**)&pattn2, g_attn2);
    cudaGetSymbolAddress((void**)&ph2, g_h2);
    cudaGetSymbolAddress((void**)&pinv2, g_inv2);
    cudaGetSymbolAddress((void**)&pbph, g_bph);
    cudaGetSymbolAddress((void**)&pwcat, g_wcat);
    cudaGetSymbolAddress((void**)&pc0, g_c0);
    cudaGetSymbolAddress((void**)&pbq2, g_bq2);

    static cudaStream_t s_side = nullptr;
    static cudaEvent_t ev_fork = nullptr, ev_join = nullptr;
    if (s_side == nullptr) {
        cudaStreamCreateWithFlags(&s_side, cudaStreamNonBlocking);
        cudaEventCreateWithFlags(&ev_fork, cudaEventDisableTiming);
        cudaEventCreateWithFlags(&ev_join, cudaEventDisableTiming);
        cudaFuncSetAttribute(kv_kernel<0>, cudaFuncAttributeMaxDynamicSharedMemorySize, KV_DSMEM);
        cudaFuncSetAttribute(kv_kernel<1>, cudaFuncAttributeMaxDynamicSharedMemorySize, KV_DSMEM);
    }

    const cudaStream_t s0 = 0;

    const float* bk1 = bk + 256;
    const float* bv1 = bv + 256;
    const float* f2w1 = f2w + 128 * 128; const float* f2b1 = f2b + 128;

    // ---- fork immediately: side stream does preps + Q1 + Q2 ----
    cudaEventRecord(ev_fork, s0);
    cudaStreamWaitEvent(s_side, ev_fork, 0);

    prep_bq_kernel<<<2, 256, 0, s_side>>>(Wq, bq, tb, pbq2);
    prep_wc_kernel<<<256, 384, 0, s_side>>>(Wo, bo, f1w, pwcat, pc0);
    {   // Q1 (fp16, K=128 after st-fold): [20480,256], 2 col chunks
        TcParams p{};
        p.Kdim = 128; p.ldC = 256; p.ldW = 256;
        p.W = Wq; p.bias = pbq2; p.C = pq1;
        p.nf = nf; p.memv = mem; p.idx = nb2;
        launch_mma(MODE_QGATHER, N1, 2, p, s_side);
    }
    {   // Q2 (fp16, K=128)
        TcParams p{};
        p.Kdim = 128; p.ldC = 256; p.ldW = 256;
        p.W = Wq + 256 * 256; p.bias = pbq2 + 256; p.C = pq2;
        p.nf = nf; p.memv = mem; p.idx = src;
        launch_mma(MODE_QGATHER, BB, 2, p, s_side);
    }
    cudaEventRecord(ev_join, s_side);

    // ---- main stream: prep_b then KV1 (persistent, 136 SMs) ----
    prep_b_kernel<<<(2 * 512 * 384 + 255) / 256, 256, 0, s0>>>(Wk, Wv, pbph);
    {
        KvParams p{};
        p.Bp = pbph; p.bk = bk; p.bv = bv; p.C = pkv1;
        p.DIV = 100; p.nblk = NP1 / 64;
        p.ts = ts; p.etm = tm1; p.tw = tw; p.tb = tb;
        p.nf = nf; p.memv = mem; p.ef = ef; p.idx = nb1; p.eidx = ei1;
        kv_kernel<0><<<136, 512, KV_DSMEM, s0>>>(p);
    }
    cudaStreamWaitEvent(s0, ev_join, 0);

    attn_kernel<<<N1, 320, 0, s0>>>(pq1, pkv1, nb1, pattn1, pinv1);
    {   // fused O1+fc1 (fp16): K=384 [attn || base], conditional c0, relu
        TcParams p{};
        p.Kdim = 384; p.ldC = 128; p.ldW = 384;
        p.W = pwcat; p.bias = f1b; p.cbias = pc0; p.C = ph1;
        p.Adense = pattn1; p.nf = nf; p.memv = mem; p.idx = nb2;
        p.invalid = pinv1; p.relu = 1;
        launch_mma(MODE_CONCAT, N1, 1, p, s0);
    }
    {   // fc2 L0 (fp16) -> emb1
        TcParams p{};
        p.Kdim = 128; p.ldA = 128; p.ldC = 128; p.ldW = 128;
        p.W = f2w; p.bias = f2b; p.C = pemb1; p.Adense = ph1;
        launch_mma(MODE_PLAIN, N1, 1, p, s0);
    }
    {   // KV2 (fp16, dense, persistent)
        KvParams p{};
        p.Bp = pbph + 512 * 384; p.bk = bk1; p.bv = bv1; p.C = pkv2;
        p.DIV = 10; p.nblk = NP2 / 64;
        p.ts = ts; p.etm = tm2; p.tw = tw; p.tb = tb;
        p.Adense = pemb1; p.ef = ef; p.eidx = ei2;
        kv_kernel<1><<<148, 512, KV_DSMEM, s0>>>(p);
    }
    attn_kernel<<<BB, 320, 0, s0>>>(pq2, pkv2, nb2, pattn2, pinv2);
    {   // fused O2+fc1 L1 (fp16)
        TcParams p{};
        p.Kdim = 384; p.ldC = 128; p.ldW = 384;
        p.W = pwcat + 128 * 384; p.bias = f1b + 128; p.cbias = pc0 + 128; p.C = ph2;
        p.Adense = pattn2; p.nf = nf; p.memv = mem; p.idx = src;
        p.invalid = pinv2; p.relu = 1;
        launch_mma(MODE_CONCAT, BB, 1, p, s0);
    }
    {   // fc2 L1 (fp16) -> out
        TcParams p{};
        p.Kdim = 128; p.ldA = 128; p.ldC = 128; p.ldW = 128;
        p.W = f2w1; p.bias = f2b1; p.C = out; p.Adense = ph2;
        launch_mma(MODE_PLAIN, BB, 1, p, s0);
    }
}